// round 4
// baseline (speedup 1.0000x reference)
#include <cuda_runtime.h>
#include <math.h>

#define BB 4
#define TT 8
#define BT 32
#define DD 64
#define CC 128
#define HH 64
#define WW 64
#define HW 4096
#define NPOS 131072          // BT*HW
#define HID 512
#define OUT_OFF_H 16777216   // 2*B*T*D*H*W
#define OUT_OFF_F 18874368   // + 2*B*H*W*D

typedef unsigned long long ull;

// ---------------- scratch (device globals; no allocations allowed) ----------
__device__ float g_xn[BT*CC*HW];          // LN output, (bt,ch,h,w)
__device__ float g_wT[CC*9*CC];           // conv weights transposed: (ic,tap,oc)
__device__ float g_xsp_re[NPOS*DD];       // (bt,d,hw)  d-major
__device__ float g_xsp_im[NPOS*DD];
__device__ float g_xeig_re[NPOS*DD];      // (pos,e) pos-major; reused as y in-place
__device__ float g_xeig_im[NPOS*DD];
__device__ float g_z_re[NPOS*DD];         // (pos,e)
__device__ float g_z_im[NPOS*DD];
__device__ float g_hdn[HID*NPOS];         // (hid,pos)
__device__ float g_xmean_re[BT*DD], g_xmean_im[BT*DD];
__device__ float g_ff_re[BT*DD],    g_ff_im[BT*DD];      // flux forcing
__device__ float g_src_re[BT*DD],   g_src_im[BT*DD];
__device__ float g_gate[BT*DD];
__device__ float g_ah_re[DD], g_ah_im[DD], g_ch_re[DD], g_ch_im[DD];
__device__ float g_af_re[DD], g_af_im[DD], g_cf_re[DD], g_cf_im[DD];

// ---------------- packed f32x2 helpers --------------------------------------
#define FMA2(acc, a, b) asm("fma.rn.f32x2 %0, %1, %2, %0;" : "+l"(acc) : "l"(a), "l"(b))

__device__ __forceinline__ ull dup2(float v) {
    unsigned u = __float_as_uint(v);
    return ((ull)u << 32) | (ull)u;
}
__device__ __forceinline__ float lo32(ull v) { return __uint_as_float((unsigned)v); }
__device__ __forceinline__ float hi32(ull v) { return __uint_as_float((unsigned)(v >> 32)); }

// ---------------------------------------------------------------- LayerNorm
__global__ void k_ln(const float* __restrict__ xre, const float* __restrict__ xim,
                     const float* __restrict__ gamma, const float* __restrict__ beta) {
    __shared__ float s[32*129];
    __shared__ float smu[32], srs[32];
    int bid = blockIdx.x;
    int bt  = bid >> 7;
    int rem = bid & 127;
    int h   = rem >> 1;
    int w0  = (rem & 1) << 5;
    int tid = threadIdx.x;
    for (int i = tid; i < 4096; i += 128) {
        int ch = i >> 5, p = i & 31;
        int d  = ch & 63;
        const float* src = (ch < 64) ? xre : xim;
        s[p*129 + ch] = src[((bt*64 + d)*64 + h)*64 + w0 + p];
    }
    __syncthreads();
    if (tid < 32) {
        float sum = 0.f, ss = 0.f;
        #pragma unroll 8
        for (int ch = 0; ch < 128; ++ch) { float v = s[tid*129 + ch]; sum += v; ss += v*v; }
        float mu  = sum * (1.0f/128.0f);
        float var = ss * (1.0f/128.0f) - mu*mu;
        smu[tid] = mu;
        srs[tid] = rsqrtf(var + 1e-5f);
    }
    __syncthreads();
    for (int i = tid; i < 4096; i += 128) {
        int ch = i >> 5, p = i & 31;
        float v = (s[p*129 + ch] - smu[p]) * srs[p] * gamma[ch] + beta[ch];
        g_xn[((bt*128 + ch)*64 + h)*64 + w0 + p] = v;
    }
}

// ------------------------------------------------- conv weight transpose
__global__ void k_wt(const float* __restrict__ cw) {
    int idx = blockIdx.x * 256 + threadIdx.x;   // 147456 total
    int oc = idx / 1152;
    int r  = idx - oc * 1152;                   // ic*9 + tap
    g_wT[r * 128 + oc] = cw[idx];
}

// -------------------------------------- conv 3x3 SAME + bias + metric + residual
__global__ void k_conv(const float* __restrict__ xre, const float* __restrict__ xim,
                       const float* __restrict__ cb, const float* __restrict__ metric) {
    __shared__ __align__(16) ull   s_ind[800];  // 8 ic x 10 x 10, duplicated (v,v)
    __shared__ __align__(16) float s_w[9216];   // 8 ic x 9 tap x 128 oc
    int bt   = blockIdx.y;
    int tile = blockIdx.x;
    int ty0  = (tile >> 3) << 3;
    int tx0  = (tile & 7) << 3;
    int tid  = threadIdx.x;
    int og   = tid >> 4;            // 16 groups of 8 oc
    int pt   = tid & 15;            // 16 pos-threads -> 64 positions
    int ty   = pt >> 1;
    int txb  = (pt & 1) << 2;
    int ocb  = og << 3;
    ull acc[4][4];
    #pragma unroll
    for (int o = 0; o < 4; ++o)
        #pragma unroll
        for (int j = 0; j < 4; ++j) acc[o][j] = 0ull;

    for (int ccik = 0; ccik < 16; ++ccik) {
        int ic0 = ccik << 3;
        __syncthreads();
        for (int i = tid; i < 800; i += 256) {
            int ic = i / 100; int r = i - ic*100;
            int yy = r / 10;  int xx = r - yy*10;
            int gy = ty0 + yy - 1, gx = tx0 + xx - 1;
            float v = 0.f;
            if (gy >= 0 && gy < 64 && gx >= 0 && gx < 64)
                v = g_xn[((bt*128 + ic0 + ic)*64 + gy)*64 + gx];
            s_ind[i] = dup2(v);
        }
        for (int i = tid; i < 9216; i += 256)
            s_w[i] = g_wT[ic0*1152 + i];
        __syncthreads();
        #pragma unroll 1
        for (int ic = 0; ic < 8; ++ic) {
            #pragma unroll
            for (int ky = 0; ky < 3; ++ky) {
                #pragma unroll
                for (int kx = 0; kx < 3; ++kx) {
                    int ib = ic*100 + (ty+ky)*10 + txb + kx;
                    ull vd0 = s_ind[ib+0], vd1 = s_ind[ib+1];
                    ull vd2 = s_ind[ib+2], vd3 = s_ind[ib+3];
                    const float* wrow = &s_w[(ic*9 + ky*3 + kx)*128 + ocb];
                    #pragma unroll
                    for (int oh = 0; oh < 4; ++oh) {
                        ull w2 = *(const ull*)(wrow + 2*oh);
                        FMA2(acc[oh][0], w2, vd0);
                        FMA2(acc[oh][1], w2, vd1);
                        FMA2(acc[oh][2], w2, vd2);
                        FMA2(acc[oh][3], w2, vd3);
                    }
                }
            }
        }
    }
    int h = ty0 + ty;
    #pragma unroll
    for (int oh = 0; oh < 4; ++oh) {
        int ocE = ocb + 2*oh;
        int dE  = ocE & 63;
        float bE = cb[ocE], bO = cb[ocE+1];
        bool isim = (ocE >= 64);
        #pragma unroll
        for (int j = 0; j < 4; ++j) {
            int w   = tx0 + txb + j;
            float m = metric[h*64 + w];
            float vE = (lo32(acc[oh][j]) + bE) * m;
            float vO = (hi32(acc[oh][j]) + bO) * m;
            int idxE = ((bt*64 + dE)*64 + h)*64 + w;
            int idxO = idxE + 4096;
            if (!isim) { g_xsp_re[idxE] = xre[idxE] + vE; g_xsp_re[idxO] = xre[idxO] + vO; }
            else       { g_xsp_im[idxE] = xim[idxE] + vE; g_xsp_im[idxO] = xim[idxO] + vO; }
        }
    }
}

// --------------------------- complex 64x64 GEMM over positions (E / Edec)
// acc: P = vr*er - vi*ei (real), Q = vr*ei + vi*er (imag); nei array holds -ei.
__device__ __forceinline__ void egemm_body(
    const float* __restrict__ inr, const float* __restrict__ ini,
    const float* __restrict__ Er,  const float* __restrict__ Ei,
    float* __restrict__ outr, float* __restrict__ outi, bool dmajor)
{
    extern __shared__ ull dynsm[];
    ull*   vr_d = dynsm;                 // [d][p] stride 65 (conflict-free 64b)
    ull*   vi_d = dynsm + 4160;
    float* ser  = (float*)(dynsm + 8320);  // [d][e]
    float* sei  = ser + 4096;
    float* snei = sei + 4096;
    int tid  = threadIdx.x;
    int pos0 = blockIdx.x << 6;
    int bt   = pos0 >> 12;
    int hw0  = pos0 & 4095;
    for (int i = tid; i < 4096; i += 256) {
        int a = i >> 6, b = i & 63;
        float xr, xi;
        if (dmajor) {                      // a = d, b = p
            int g = (bt*64 + a)*4096 + hw0 + b;
            xr = inr[g]; xi = ini[g];
            vr_d[a*65 + b] = dup2(xr);
            vi_d[a*65 + b] = dup2(xi);
        } else {                           // a = p, b = d (coalesced read, strided STS ok)
            int g = (pos0 + a)*64 + b;
            xr = inr[g]; xi = ini[g];
            vr_d[b*65 + a] = dup2(xr);
            vi_d[b*65 + a] = dup2(xi);
        }
        float er_ = Er[i], ei_ = Ei[i];
        ser[i] = er_; sei[i] = ei_; snei[i] = -ei_;
    }
    __syncthreads();
    int eg = tid >> 4, pt = tid & 15;
    int e0 = eg << 2;
    ull ar2[4][2], ai2[4][2];
    #pragma unroll
    for (int j = 0; j < 4; ++j) { ar2[j][0]=0; ar2[j][1]=0; ai2[j][0]=0; ai2[j][1]=0; }
    #pragma unroll 2
    for (int d = 0; d < 64; ++d) {
        ull vrd[4], vid[4];
        #pragma unroll
        for (int j = 0; j < 4; ++j) {
            vrd[j] = vr_d[d*65 + pt + 16*j];
            vid[j] = vi_d[d*65 + pt + 16*j];
        }
        ull er2[2], ei2[2], nei2[2];
        #pragma unroll
        for (int eh = 0; eh < 2; ++eh) {
            er2[eh]  = *(const ull*)(ser  + d*64 + e0 + 2*eh);
            ei2[eh]  = *(const ull*)(sei  + d*64 + e0 + 2*eh);
            nei2[eh] = *(const ull*)(snei + d*64 + e0 + 2*eh);
        }
        #pragma unroll
        for (int j = 0; j < 4; ++j)
            #pragma unroll
            for (int eh = 0; eh < 2; ++eh) {
                FMA2(ar2[j][eh], vrd[j], er2[eh]);
                FMA2(ar2[j][eh], vid[j], nei2[eh]);
                FMA2(ai2[j][eh], vrd[j], ei2[eh]);
                FMA2(ai2[j][eh], vid[j], er2[eh]);
            }
    }
    #pragma unroll
    for (int j = 0; j < 4; ++j) {
        int pos = pos0 + pt + 16*j;
        *(float4*)(outr + pos*64 + e0) =
            make_float4(lo32(ar2[j][0]), hi32(ar2[j][0]), lo32(ar2[j][1]), hi32(ar2[j][1]));
        *(float4*)(outi + pos*64 + e0) =
            make_float4(lo32(ai2[j][0]), hi32(ai2[j][0]), lo32(ai2[j][1]), hi32(ai2[j][1]));
    }
}

__global__ void k_egemm1(const float* __restrict__ Er, const float* __restrict__ Ei) {
    egemm_body(g_xsp_re, g_xsp_im, Er, Ei, g_xeig_re, g_xeig_im, true);
}
__global__ void k_egemm2(const float* __restrict__ Er, const float* __restrict__ Ei) {
    egemm_body(g_xeig_re, g_xeig_im, Er, Ei, g_z_re, g_z_im, false);
}

// ----------------------------------------------- spatial mean of x_eig
__global__ void k_mean() {
    __shared__ float rr[256], ri[256];
    int bt = blockIdx.x, tid = threadIdx.x;
    int c = tid >> 6, e = tid & 63;
    float sr = 0.f, si = 0.f;
    int base = ((bt*4096 + c*1024)*64) + e;
    for (int i = 0; i < 1024; ++i) {
        sr += g_xeig_re[base + i*64];
        si += g_xeig_im[base + i*64];
    }
    rr[tid] = sr; ri[tid] = si;
    __syncthreads();
    if (c == 0) {
        sr = rr[e] + rr[64+e] + rr[128+e] + rr[192+e];
        si = ri[e] + ri[64+e] + ri[128+e] + ri[192+e];
        g_xmean_re[bt*64 + e] = sr * (1.0f/4096.0f);
        g_xmean_im[bt*64 + e] = si * (1.0f/4096.0f);
    }
}

// ----------------------------------------------- per-d recurrence constants
__global__ void k_consts(const float* __restrict__ dt,
                         const float* __restrict__ lhr, const float* __restrict__ lhi,
                         const float* __restrict__ lfr, const float* __restrict__ lfi) {
    int d = threadIdx.x;
    float t = dt[0];
    {
        float lr = -fabsf(lhr[d]), li = lhi[d];
        float m = expf(lr*t);
        float ar = m*cosf(li*t), ai = m*sinf(li*t);
        float nr = ar - 1.f, ni = ai;
        float den = lr*lr + li*li;
        g_ah_re[d] = ar; g_ah_im[d] = ai;
        g_ch_re[d] = (nr*lr + ni*li)/den;
        g_ch_im[d] = (ni*lr - nr*li)/den;
    }
    {
        float lr = -fabsf(lfr[d]), li = lfi[d];
        float m = expf(lr*t);
        float ar = m*cosf(li*t), ai = m*sinf(li*t);
        float nr = ar - 1.f, ni = ai;
        float den = lr*lr + li*li;
        g_af_re[d] = ar; g_af_im[d] = ai;
        g_cf_re[d] = (nr*lr + ni*li)/den;
        g_cf_im[d] = (ni*lr - nr*li)/den;
    }
}

// ----------------------------------------------- flux scan over T
__global__ void k_flux(const float* __restrict__ fpr, const float* __restrict__ fpi,
                       float* __restrict__ dout) {
    int tid = threadIdx.x;
    int b = tid >> 6, d = tid & 63;
    float ar = g_af_re[d], ai = g_af_im[d];
    float cr = g_cf_re[d], ci = g_cf_im[d];
    float sr = fpr[b*64 + d], si = fpi[b*64 + d];
    #pragma unroll
    for (int t = 0; t < 8; ++t) {
        int idx = (b*8 + t)*64 + d;
        g_ff_re[idx] = sr; g_ff_im[idx] = si;        // forcing = state BEFORE update
        float xr = g_xmean_re[idx], xi = g_xmean_im[idx];
        float ur = xr*cr - xi*ci, ui = xr*ci + xi*cr;
        float nsr = ar*sr - ai*si + ur;
        float nsi = ar*si + ai*sr + ui;
        sr = nsr; si = nsi;
    }
    dout[OUT_OFF_F + b*64 + d]       = sr;
    dout[OUT_OFF_F + 256 + b*64 + d] = si;
}

// ----------------------------------------------- source / gate
__global__ void k_srcgate(const float* __restrict__ Wsr, const float* __restrict__ Wsi,
                          const float* __restrict__ Wg,  const float* __restrict__ bg) {
    int bt = blockIdx.x;
    int e  = threadIdx.x;
    float sr = 0.f, si = 0.f, ga = 0.f;
    #pragma unroll 8
    for (int d = 0; d < 64; ++d) {
        float fr = g_ff_re[bt*64 + d], fi = g_ff_im[bt*64 + d];
        float wr = Wsr[d*64 + e], wi = Wsi[d*64 + e];
        sr += fr*wr - fi*wi;
        si += fr*wi + fi*wr;
        ga += fr*Wg[d*64 + e];
    }
    g_src_re[bt*64 + e] = sr;
    g_src_im[bt*64 + e] = si;
    g_gate[bt*64 + e]   = 1.f/(1.f + expf(-(ga + bg[e])));
}

// ----------------------------------------------- main recurrence (in-place), h_out
__global__ void k_rec(const float* __restrict__ hpr, const float* __restrict__ hpi,
                      float* __restrict__ dout) {
    int bid = blockIdx.x;            // b*4096 + hw
    int b = bid >> 12;
    int d = threadIdx.x;
    float ar = g_ah_re[d], ai = g_ah_im[d];
    float cr = g_ch_re[d], ci = g_ch_im[d];
    float yr = hpr[bid*64 + d], yi = hpi[bid*64 + d];
    int hw = bid & 4095;
    #pragma unroll
    for (int t = 0; t < 8; ++t) {
        int bt  = b*8 + t;
        int idx = (bt*4096 + hw)*64 + d;
        float xr = g_xeig_re[idx], xi = g_xeig_im[idx];
        float g  = g_gate[bt*64 + d];
        float sr = g_src_re[bt*64 + d], si = g_src_im[bt*64 + d];
        float fr = xr*g + sr*(1.f - g);
        float fi = xi*g + si*(1.f - g);
        float ur = fr*cr - fi*ci, ui = fr*ci + fi*cr;
        float nyr = ar*yr - ai*yi + ur;
        float nyi = ar*yi + ai*yr + ui;
        yr = nyr; yi = nyi;
        g_xeig_re[idx] = yr;
        g_xeig_im[idx] = yi;
    }
    dout[OUT_OFF_H + bid*64 + d]           = yr;
    dout[OUT_OFF_H + 1048576 + bid*64 + d] = yi;
}

// ----------------------------------------------- FFN
__device__ __forceinline__ float gelu_f(float x) {
    float x3 = x*x*x;
    return 0.5f*x*(1.f + tanhf(0.7978845608028654f*(x + 0.044715f*x3)));
}

// ffn1: hdn[hid, pos] = gelu( [z_re|z_im](pos,:) @ w1 + b1 ), K=128 in two chunks
__global__ void k_ffn1(const float* __restrict__ w1, const float* __restrict__ b1) {
    extern __shared__ ull dynsm[];
    ull*   s_zd = dynsm;                 // [64][64] dup (k-local, p)
    float* s_w  = (float*)(dynsm + 4096);  // [128][128]
    int tid  = threadIdx.x;
    int pos0 = blockIdx.x << 6;
    int hid0 = blockIdx.y << 7;
    for (int i = tid; i < 16384; i += 256) {
        int k = i >> 7, h = i & 127;
        s_w[i] = w1[k*512 + hid0 + h];
    }
    int hg = tid >> 4, pt = tid & 15;
    int h0 = hg << 3;
    ull acc[4][4];
    #pragma unroll
    for (int o = 0; o < 4; ++o)
        #pragma unroll
        for (int j = 0; j < 4; ++j) acc[o][j] = 0ull;

    for (int kc = 0; kc < 2; ++kc) {
        const float* src = kc ? g_z_im : g_z_re;
        __syncthreads();
        for (int i = tid; i < 4096; i += 256) {
            int k = i >> 6, p = i & 63;
            s_zd[k*64 + p] = dup2(src[(pos0 + p)*64 + k]);
        }
        __syncthreads();
        #pragma unroll 2
        for (int k = 0; k < 64; ++k) {
            ull w2[4], vd[4];
            #pragma unroll
            for (int oh = 0; oh < 4; ++oh)
                w2[oh] = *(const ull*)(s_w + (kc*64 + k)*128 + h0 + 2*oh);
            #pragma unroll
            for (int j = 0; j < 4; ++j)
                vd[j] = s_zd[k*64 + pt + 16*j];
            #pragma unroll
            for (int oh = 0; oh < 4; ++oh)
                #pragma unroll
                for (int j = 0; j < 4; ++j)
                    FMA2(acc[oh][j], w2[oh], vd[j]);
        }
    }
    #pragma unroll
    for (int oh = 0; oh < 4; ++oh) {
        int hE = hid0 + h0 + 2*oh;
        float bE = b1[hE], bO = b1[hE+1];
        #pragma unroll
        for (int j = 0; j < 4; ++j) {
            int p = pt + 16*j;
            g_hdn[hE*NPOS     + pos0 + p] = gelu_f(lo32(acc[oh][j]) + bE);
            g_hdn[(hE+1)*NPOS + pos0 + p] = gelu_f(hi32(acc[oh][j]) + bO);
        }
    }
}

__global__ void k_ffn2(const float* __restrict__ w2g, const float* __restrict__ b2,
                       float* __restrict__ dout) {
    extern __shared__ ull dynsm[];
    ull*   s_hd = dynsm;                   // [64][64] dup (k-local, p)
    float* s_w  = (float*)(dynsm + 4096);  // [64][128] per chunk
    float* s_zr = s_w + 8192;              // [64 p][64 d]
    float* s_zi = s_zr + 4096;
    int tid  = threadIdx.x;
    int pos0 = blockIdx.x << 6;
    for (int i = tid; i < 4096; i += 256) {
        int p = i >> 6, d = i & 63;
        s_zr[i] = g_z_re[(pos0 + p)*64 + d];
        s_zi[i] = g_z_im[(pos0 + p)*64 + d];
    }
    int ocg = tid >> 4, pt = tid & 15;
    int oc0 = ocg << 3;
    ull acc[4][4];
    #pragma unroll
    for (int o = 0; o < 4; ++o)
        #pragma unroll
        for (int j = 0; j < 4; ++j) acc[o][j] = 0ull;

    for (int kc = 0; kc < 8; ++kc) {
        int k0 = kc << 6;
        __syncthreads();
        for (int i = tid; i < 4096; i += 256) {
            int k = i >> 6, p = i & 63;
            s_hd[k*64 + p] = dup2(g_hdn[(k0 + k)*NPOS + pos0 + p]);
        }
        for (int i = tid; i < 8192; i += 256) {
            int k = i >> 7, oc = i & 127;
            s_w[i] = w2g[(k0 + k)*128 + oc];
        }
        __syncthreads();
        #pragma unroll 2
        for (int k = 0; k < 64; ++k) {
            ull w2[4], vd[4];
            #pragma unroll
            for (int oh = 0; oh < 4; ++oh)
                w2[oh] = *(const ull*)(s_w + k*128 + oc0 + 2*oh);
            #pragma unroll
            for (int j = 0; j < 4; ++j)
                vd[j] = s_hd[k*64 + pt + 16*j];
            #pragma unroll
            for (int oh = 0; oh < 4; ++oh)
                #pragma unroll
                for (int j = 0; j < 4; ++j)
                    FMA2(acc[oh][j], w2[oh], vd[j]);
        }
    }
    int bt  = pos0 >> 12;
    int hw0 = pos0 & 4095;
    #pragma unroll
    for (int oh = 0; oh < 4; ++oh) {
        int ocE = oc0 + 2*oh;
        int dE  = ocE & 63;
        float bE = b2[ocE], bO = b2[ocE+1];
        bool isim = (ocE >= 64);
        #pragma unroll
        for (int j = 0; j < 4; ++j) {
            int p = pt + 16*j;
            float aE = lo32(acc[oh][j]) + bE;
            float aO = hi32(acc[oh][j]) + bO;
            int baseE = (bt*64 + dE)*4096 + hw0 + p;
            int baseO = baseE + 4096;
            if (!isim) {
                dout[baseE] = aE + s_zr[p*64 + dE]     + g_xsp_re[baseE];
                dout[baseO] = aO + s_zr[p*64 + dE + 1] + g_xsp_re[baseO];
            } else {
                dout[8388608 + baseE] = aE + s_zi[p*64 + dE]     + g_xsp_im[baseE];
                dout[8388608 + baseO] = aO + s_zi[p*64 + dE + 1] + g_xsp_im[baseO];
            }
        }
    }
}

// ---------------------------------------------------------------- launch
extern "C" void kernel_launch(void* const* d_in, const int* in_sizes, int n_in,
                              void* d_out, int out_size) {
    const float* x_re    = (const float*)d_in[0];
    const float* x_im    = (const float*)d_in[1];
    const float* hp_re   = (const float*)d_in[2];
    const float* hp_im   = (const float*)d_in[3];
    const float* fp_re   = (const float*)d_in[4];
    const float* fp_im   = (const float*)d_in[5];
    const float* dt      = (const float*)d_in[6];
    const float* ln_g    = (const float*)d_in[7];
    const float* ln_b    = (const float*)d_in[8];
    const float* conv_w  = (const float*)d_in[9];
    const float* conv_b  = (const float*)d_in[10];
    const float* metric  = (const float*)d_in[11];
    const float* E_re    = (const float*)d_in[12];
    const float* E_im    = (const float*)d_in[13];
    const float* Ed_re   = (const float*)d_in[14];
    const float* Ed_im   = (const float*)d_in[15];
    const float* lh_re   = (const float*)d_in[16];
    const float* lh_im   = (const float*)d_in[17];
    const float* lf_re   = (const float*)d_in[18];
    const float* lf_im   = (const float*)d_in[19];
    const float* Ws_re   = (const float*)d_in[20];
    const float* Ws_im   = (const float*)d_in[21];
    const float* W_gate  = (const float*)d_in[22];
    const float* b_gate  = (const float*)d_in[23];
    const float* ffn_w1  = (const float*)d_in[24];
    const float* ffn_b1  = (const float*)d_in[25];
    const float* ffn_w2  = (const float*)d_in[26];
    const float* ffn_b2  = (const float*)d_in[27];
    float* out = (float*)d_out;

    // egemm: 2*4160*8 + 3*4096*4 = 66560 + 49152 = 115712 bytes
    // ffn1/ffn2: 4096*8 + 16384*4 = 98304 bytes
    cudaFuncSetAttribute(k_egemm1, cudaFuncAttributeMaxDynamicSharedMemorySize, 115712);
    cudaFuncSetAttribute(k_egemm2, cudaFuncAttributeMaxDynamicSharedMemorySize, 115712);
    cudaFuncSetAttribute(k_ffn1,   cudaFuncAttributeMaxDynamicSharedMemorySize, 98304);
    cudaFuncSetAttribute(k_ffn2,   cudaFuncAttributeMaxDynamicSharedMemorySize, 98304);

    k_ln<<<4096, 128>>>(x_re, x_im, ln_g, ln_b);
    k_wt<<<576, 256>>>(conv_w);
    k_conv<<<dim3(64, 32), 256>>>(x_re, x_im, conv_b, metric);
    k_egemm1<<<2048, 256, 115712>>>(E_re, E_im);
    k_mean<<<32, 256>>>();
    k_consts<<<1, 64>>>(dt, lh_re, lh_im, lf_re, lf_im);
    k_flux<<<1, 256>>>(fp_re, fp_im, out);
    k_srcgate<<<32, 64>>>(Ws_re, Ws_im, W_gate, b_gate);
    k_rec<<<16384, 64>>>(hp_re, hp_im, out);
    k_egemm2<<<2048, 256, 115712>>>(Ed_re, Ed_im);
    k_ffn1<<<dim3(2048, 4), 256, 98304>>>(ffn_w1, ffn_b1);
    k_ffn2<<<2048, 256, 98304>>>(ffn_w2, ffn_b2, out);
}

// round 7
// speedup vs baseline: 1.1689x; 1.1689x over previous
#include <cuda_runtime.h>
#include <math.h>

#define BB 4
#define TT 8
#define BT 32
#define DD 64
#define CC 128
#define HH 64
#define WW 64
#define HW 4096
#define NPOS 131072          // BT*HW
#define HID 512
#define OUT_OFF_H 16777216   // 2*B*T*D*H*W
#define OUT_OFF_F 18874368   // + 2*B*H*W*D

// ---------------- scratch (device globals; no allocations allowed) ----------
__device__ float g_xn[BT*CC*HW];          // LN output, (bt,ch,h,w)
__device__ float g_wT[CC*9*CC];           // conv weights transposed: (ic,tap,oc)
__device__ float g_xsp_re[NPOS*DD];       // (bt,d,hw)  d-major
__device__ float g_xsp_im[NPOS*DD];
__device__ float g_xeig_re[NPOS*DD];      // (pos,e) pos-major; reused as y in-place
__device__ float g_xeig_im[NPOS*DD];
__device__ float g_z_re[NPOS*DD];         // (e,pos) e-major
__device__ float g_z_im[NPOS*DD];
__device__ float g_hdn[HID*NPOS];         // (hid,pos)
__device__ float g_xmean_re[BT*DD], g_xmean_im[BT*DD];
__device__ float g_ff_re[BT*DD],    g_ff_im[BT*DD];      // flux forcing
__device__ float g_src_re[BT*DD],   g_src_im[BT*DD];
__device__ float g_gate[BT*DD];
__device__ float g_ah_re[DD], g_ah_im[DD], g_ch_re[DD], g_ch_im[DD];
__device__ float g_af_re[DD], g_af_im[DD], g_cf_re[DD], g_cf_im[DD];

// ---------------------------------------------------------------- LayerNorm
__global__ void k_ln(const float* __restrict__ xre, const float* __restrict__ xim,
                     const float* __restrict__ gamma, const float* __restrict__ beta) {
    __shared__ float s[32*129];
    __shared__ float smu[32], srs[32];
    int bid = blockIdx.x;
    int bt  = bid >> 7;
    int rem = bid & 127;
    int h   = rem >> 1;
    int w0  = (rem & 1) << 5;
    int tid = threadIdx.x;
    for (int i = tid; i < 4096; i += 128) {
        int ch = i >> 5, p = i & 31;
        int d  = ch & 63;
        const float* src = (ch < 64) ? xre : xim;
        s[p*129 + ch] = src[((bt*64 + d)*64 + h)*64 + w0 + p];
    }
    __syncthreads();
    if (tid < 32) {
        float sum = 0.f, ss = 0.f;
        #pragma unroll 8
        for (int ch = 0; ch < 128; ++ch) { float v = s[tid*129 + ch]; sum += v; ss += v*v; }
        float mu  = sum * (1.0f/128.0f);
        float var = ss * (1.0f/128.0f) - mu*mu;
        smu[tid] = mu;
        srs[tid] = rsqrtf(var + 1e-5f);
    }
    __syncthreads();
    for (int i = tid; i < 4096; i += 128) {
        int ch = i >> 5, p = i & 31;
        float v = (s[p*129 + ch] - smu[p]) * srs[p] * gamma[ch] + beta[ch];
        g_xn[((bt*128 + ch)*64 + h)*64 + w0 + p] = v;
    }
}

// ------------------------------------------------- conv weight transpose
__global__ void k_wt(const float* __restrict__ cw) {
    int idx = blockIdx.x * 256 + threadIdx.x;   // 147456 total
    int oc = idx / 1152;
    int r  = idx - oc * 1152;                   // ic*9 + tap
    g_wT[r * 128 + oc] = cw[idx];
}

// -------------------------------------- conv 3x3 SAME + bias + metric + residual
__global__ void k_conv(const float* __restrict__ xre, const float* __restrict__ xim,
                       const float* __restrict__ cb, const float* __restrict__ metric) {
    __shared__ __align__(16) float s_in[8*10*12];   // 8 ic x 10 rows x 12-wide rows
    __shared__ __align__(16) float s_w[9216];       // 8 ic x 9 tap x 128 oc
    int bt   = blockIdx.y;
    int tile = blockIdx.x;
    int ty0  = (tile >> 3) << 3;
    int tx0  = (tile & 7) << 3;
    int tid  = threadIdx.x;
    int og   = tid >> 4;            // 16 groups of 8 oc
    int pt   = tid & 15;            // 16 pos-threads -> 64 positions
    int ty   = pt >> 1;
    int txb  = (pt & 1) << 2;
    int ocb  = og << 3;
    float acc[8][4];
    #pragma unroll
    for (int o = 0; o < 8; ++o)
        #pragma unroll
        for (int j = 0; j < 4; ++j) acc[o][j] = 0.f;

    for (int ccik = 0; ccik < 16; ++ccik) {
        int ic0 = ccik << 3;
        __syncthreads();
        for (int i = tid; i < 800; i += 256) {
            int ic = i / 100; int r = i - ic*100;
            int yy = r / 10;  int xx = r - yy*10;
            int gy = ty0 + yy - 1, gx = tx0 + xx - 1;
            float v = 0.f;
            if (gy >= 0 && gy < 64 && gx >= 0 && gx < 64)
                v = g_xn[((bt*128 + ic0 + ic)*64 + gy)*64 + gx];
            s_in[(ic*10 + yy)*12 + xx] = v;
        }
        for (int i = tid; i < 9216; i += 256)
            s_w[i] = g_wT[ic0*1152 + i];
        __syncthreads();
        #pragma unroll 1
        for (int ic = 0; ic < 8; ++ic) {
            #pragma unroll
            for (int ky = 0; ky < 3; ++ky) {
                int ib0 = (ic*10 + ty + ky)*12 + txb;
                float4 va = *(const float4*)&s_in[ib0];
                float2 vb = *(const float2*)&s_in[ib0 + 4];
                float v[6] = {va.x, va.y, va.z, va.w, vb.x, vb.y};
                #pragma unroll
                for (int kx = 0; kx < 3; ++kx) {
                    const float* wrow = &s_w[(ic*9 + ky*3 + kx)*128 + ocb];
                    float4 w0 = *(const float4*)wrow;
                    float4 w1 = *(const float4*)(wrow + 4);
                    float w[8] = {w0.x, w0.y, w0.z, w0.w, w1.x, w1.y, w1.z, w1.w};
                    #pragma unroll
                    for (int o = 0; o < 8; ++o)
                        #pragma unroll
                        for (int j = 0; j < 4; ++j)
                            acc[o][j] += w[o]*v[kx + j];
                }
            }
        }
    }
    int h = ty0 + ty;
    int wq = tx0 + txb;
    float4 mv = *(const float4*)&metric[h*64 + wq];
    float mm[4] = {mv.x, mv.y, mv.z, mv.w};
    #pragma unroll
    for (int o = 0; o < 8; ++o) {
        int oc = ocb + o;
        int d  = oc & 63;
        float bias = cb[oc];
        int base = ((bt*64 + d)*64 + h)*64 + wq;
        float4 r;
        const float* xin = (oc < 64) ? xre : xim;
        float4 xv = *(const float4*)&xin[base];
        r.x = xv.x + (acc[o][0] + bias)*mm[0];
        r.y = xv.y + (acc[o][1] + bias)*mm[1];
        r.z = xv.z + (acc[o][2] + bias)*mm[2];
        r.w = xv.w + (acc[o][3] + bias)*mm[3];
        if (oc < 64) *(float4*)&g_xsp_re[base] = r;
        else         *(float4*)&g_xsp_im[base] = r;
    }
}

// --------------------------- complex 64x64 GEMM over positions (E / Edec)
// dmajor=true : input (bt,d,hw) d-major, output (pos,e) pos-major  (egemm1)
// dmajor=false: input (pos,e)  pos-major, output (e,pos) e-major   (egemm2)
#define EST 68   // smem row stride (floats), multiple of 4 for float4
__device__ __forceinline__ void egemm_body(
    const float* __restrict__ inr, const float* __restrict__ ini,
    const float* __restrict__ Er,  const float* __restrict__ Ei,
    float* __restrict__ outr, float* __restrict__ outi, bool dmajor)
{
    extern __shared__ float sm[];
    float* sxr = sm;                 // [d][p] stride EST
    float* sxi = sm + 64*EST;
    float* ser = sm + 2*64*EST;      // [d][e] stride EST
    float* sei = sm + 3*64*EST;
    int tid  = threadIdx.x;
    int pos0 = blockIdx.x << 6;
    int bt   = pos0 >> 12;
    int hw0  = pos0 & 4095;
    for (int i = tid; i < 4096; i += 256) {
        int a = i >> 6, b = i & 63;
        if (dmajor) {                      // a = d, b = p
            int g = (bt*64 + a)*4096 + hw0 + b;
            sxr[a*EST + b] = inr[g];
            sxi[a*EST + b] = ini[g];
        } else {                           // a = p, b = d (coalesced read)
            int g = (pos0 + a)*64 + b;
            sxr[b*EST + a] = inr[g];
            sxi[b*EST + a] = ini[g];
        }
        ser[a*EST + b] = Er[i];
        sei[a*EST + b] = Ei[i];
    }
    __syncthreads();
    int eg = tid >> 4, pt = tid & 15;
    int e0 = eg << 2,  p0 = pt << 2;
    float ar[4][4] = {}, ai[4][4] = {};
    #pragma unroll 4
    for (int d = 0; d < 64; ++d) {
        float4 vr4 = *(const float4*)&sxr[d*EST + p0];
        float4 vi4 = *(const float4*)&sxi[d*EST + p0];
        float4 er4 = *(const float4*)&ser[d*EST + e0];
        float4 ei4 = *(const float4*)&sei[d*EST + e0];
        float vr[4] = {vr4.x, vr4.y, vr4.z, vr4.w};
        float vi[4] = {vi4.x, vi4.y, vi4.z, vi4.w};
        float er[4] = {er4.x, er4.y, er4.z, er4.w};
        float ei[4] = {ei4.x, ei4.y, ei4.z, ei4.w};
        #pragma unroll
        for (int pj = 0; pj < 4; ++pj)
            #pragma unroll
            for (int ej = 0; ej < 4; ++ej) {
                ar[pj][ej] += vr[pj]*er[ej] - vi[pj]*ei[ej];
                ai[pj][ej] += vr[pj]*ei[ej] + vi[pj]*er[ej];
            }
    }
    if (dmajor) {
        #pragma unroll
        for (int pj = 0; pj < 4; ++pj) {
            int pos = pos0 + p0 + pj;
            *(float4*)(outr + pos*64 + e0) = make_float4(ar[pj][0], ar[pj][1], ar[pj][2], ar[pj][3]);
            *(float4*)(outi + pos*64 + e0) = make_float4(ai[pj][0], ai[pj][1], ai[pj][2], ai[pj][3]);
        }
    } else {
        #pragma unroll
        for (int ej = 0; ej < 4; ++ej) {
            int e = e0 + ej;
            *(float4*)(outr + e*NPOS + pos0 + p0) = make_float4(ar[0][ej], ar[1][ej], ar[2][ej], ar[3][ej]);
            *(float4*)(outi + e*NPOS + pos0 + p0) = make_float4(ai[0][ej], ai[1][ej], ai[2][ej], ai[3][ej]);
        }
    }
}

__global__ void k_egemm1(const float* __restrict__ Er, const float* __restrict__ Ei) {
    egemm_body(g_xsp_re, g_xsp_im, Er, Ei, g_xeig_re, g_xeig_im, true);
}
__global__ void k_egemm2(const float* __restrict__ Er, const float* __restrict__ Ei) {
    egemm_body(g_xeig_re, g_xeig_im, Er, Ei, g_z_re, g_z_im, false);
}

// ----------------------------------------------- spatial mean of x_eig
__global__ void k_mean() {
    __shared__ float rr[256], ri[256];
    int bt = blockIdx.x, tid = threadIdx.x;
    int c = tid >> 6, e = tid & 63;
    float sr = 0.f, si = 0.f;
    int base = ((bt*4096 + c*1024)*64) + e;
    for (int i = 0; i < 1024; ++i) {
        sr += g_xeig_re[base + i*64];
        si += g_xeig_im[base + i*64];
    }
    rr[tid] = sr; ri[tid] = si;
    __syncthreads();
    if (c == 0) {
        sr = rr[e] + rr[64+e] + rr[128+e] + rr[192+e];
        si = ri[e] + ri[64+e] + ri[128+e] + ri[192+e];
        g_xmean_re[bt*64 + e] = sr * (1.0f/4096.0f);
        g_xmean_im[bt*64 + e] = si * (1.0f/4096.0f);
    }
}

// ----------------------------------------------- per-d recurrence constants
__global__ void k_consts(const float* __restrict__ dt,
                         const float* __restrict__ lhr, const float* __restrict__ lhi,
                         const float* __restrict__ lfr, const float* __restrict__ lfi) {
    int d = threadIdx.x;
    float t = dt[0];
    {
        float lr = -fabsf(lhr[d]), li = lhi[d];
        float m = expf(lr*t);
        float ar = m*cosf(li*t), ai = m*sinf(li*t);
        float nr = ar - 1.f, ni = ai;
        float den = lr*lr + li*li;
        g_ah_re[d] = ar; g_ah_im[d] = ai;
        g_ch_re[d] = (nr*lr + ni*li)/den;
        g_ch_im[d] = (ni*lr - nr*li)/den;
    }
    {
        float lr = -fabsf(lfr[d]), li = lfi[d];
        float m = expf(lr*t);
        float ar = m*cosf(li*t), ai = m*sinf(li*t);
        float nr = ar - 1.f, ni = ai;
        float den = lr*lr + li*li;
        g_af_re[d] = ar; g_af_im[d] = ai;
        g_cf_re[d] = (nr*lr + ni*li)/den;
        g_cf_im[d] = (ni*lr - nr*li)/den;
    }
}

// ----------------------------------------------- flux scan over T
__global__ void k_flux(const float* __restrict__ fpr, const float* __restrict__ fpi,
                       float* __restrict__ dout) {
    int tid = threadIdx.x;
    int b = tid >> 6, d = tid & 63;
    float ar = g_af_re[d], ai = g_af_im[d];
    float cr = g_cf_re[d], ci = g_cf_im[d];
    float sr = fpr[b*64 + d], si = fpi[b*64 + d];
    #pragma unroll
    for (int t = 0; t < 8; ++t) {
        int idx = (b*8 + t)*64 + d;
        g_ff_re[idx] = sr; g_ff_im[idx] = si;        // forcing = state BEFORE update
        float xr = g_xmean_re[idx], xi = g_xmean_im[idx];
        float ur = xr*cr - xi*ci, ui = xr*ci + xi*cr;
        float nsr = ar*sr - ai*si + ur;
        float nsi = ar*si + ai*sr + ui;
        sr = nsr; si = nsi;
    }
    dout[OUT_OFF_F + b*64 + d]       = sr;
    dout[OUT_OFF_F + 256 + b*64 + d] = si;
}

// ----------------------------------------------- source / gate
__global__ void k_srcgate(const float* __restrict__ Wsr, const float* __restrict__ Wsi,
                          const float* __restrict__ Wg,  const float* __restrict__ bg) {
    int bt = blockIdx.x;
    int e  = threadIdx.x;
    float sr = 0.f, si = 0.f, ga = 0.f;
    #pragma unroll 8
    for (int d = 0; d < 64; ++d) {
        float fr = g_ff_re[bt*64 + d], fi = g_ff_im[bt*64 + d];
        float wr = Wsr[d*64 + e], wi = Wsi[d*64 + e];
        sr += fr*wr - fi*wi;
        si += fr*wi + fi*wr;
        ga += fr*Wg[d*64 + e];
    }
    g_src_re[bt*64 + e] = sr;
    g_src_im[bt*64 + e] = si;
    g_gate[bt*64 + e]   = 1.f/(1.f + expf(-(ga + bg[e])));
}

// ----------------------------------------------- main recurrence (in-place), h_out
__global__ void k_rec(const float* __restrict__ hpr, const float* __restrict__ hpi,
                      float* __restrict__ dout) {
    int bid = blockIdx.x;            // b*4096 + hw
    int b = bid >> 12;
    int d = threadIdx.x;
    float ar = g_ah_re[d], ai = g_ah_im[d];
    float cr = g_ch_re[d], ci = g_ch_im[d];
    float yr = hpr[bid*64 + d], yi = hpi[bid*64 + d];
    int hw = bid & 4095;
    #pragma unroll
    for (int t = 0; t < 8; ++t) {
        int bt  = b*8 + t;
        int idx = (bt*4096 + hw)*64 + d;
        float xr = g_xeig_re[idx], xi = g_xeig_im[idx];
        float g  = g_gate[bt*64 + d];
        float sr = g_src_re[bt*64 + d], si = g_src_im[bt*64 + d];
        float fr = xr*g + sr*(1.f - g);
        float fi = xi*g + si*(1.f - g);
        float ur = fr*cr - fi*ci, ui = fr*ci + fi*cr;
        float nyr = ar*yr - ai*yi + ur;
        float nyi = ar*yi + ai*yr + ui;
        yr = nyr; yi = nyi;
        g_xeig_re[idx] = yr;
        g_xeig_im[idx] = yi;
    }
    dout[OUT_OFF_H + bid*64 + d]           = yr;
    dout[OUT_OFF_H + 1048576 + bid*64 + d] = yi;
}

// ----------------------------------------------- FFN
__device__ __forceinline__ float gelu_f(float x) {
    float x3 = x*x*x;
    return 0.5f*x*(1.f + tanhf(0.7978845608028654f*(x + 0.044715f*x3)));
}

// ffn1: hdn[hid, pos] = gelu( [z_re|z_im](:,pos) @ w1 + b1 );  z is e-major
// dynamic smem: 8192 + 16384 floats = 98304 bytes
__global__ void k_ffn1(const float* __restrict__ w1, const float* __restrict__ b1) {
    extern __shared__ float sm[];
    float* s_z = sm;            // [128 k][64 p], stride 64
    float* s_w = sm + 8192;     // [128 k][128 h]
    int tid  = threadIdx.x;
    int pos0 = blockIdx.x << 6;
    int hid0 = blockIdx.y << 7;
    for (int i = tid; i < 8192; i += 256) {
        int k = i >> 6, p = i & 63;
        const float* src = (k < 64) ? (g_z_re + k*NPOS) : (g_z_im + (k - 64)*NPOS);
        s_z[i] = src[pos0 + p];                    // coalesced (e-major z)
    }
    for (int i = tid; i < 16384; i += 256) {
        int k = i >> 7, h = i & 127;
        s_w[i] = w1[k*512 + hid0 + h];
    }
    __syncthreads();
    int hg = tid >> 4, pt = tid & 15;
    int h0 = hg << 3, p0 = pt << 2;
    float acc[8][4] = {};
    #pragma unroll 4
    for (int k = 0; k < 128; ++k) {
        float4 v4 = *(const float4*)&s_z[k*64 + p0];
        float4 w0 = *(const float4*)&s_w[k*128 + h0];
        float4 w1v = *(const float4*)&s_w[k*128 + h0 + 4];
        float v[4] = {v4.x, v4.y, v4.z, v4.w};
        float w[8] = {w0.x, w0.y, w0.z, w0.w, w1v.x, w1v.y, w1v.z, w1v.w};
        #pragma unroll
        for (int o = 0; o < 8; ++o)
            #pragma unroll
            for (int j = 0; j < 4; ++j)
                acc[o][j] += w[o]*v[j];
    }
    #pragma unroll
    for (int o = 0; o < 8; ++o) {
        int hid = hid0 + h0 + o;
        float bb = b1[hid];
        float4 r;
        r.x = gelu_f(acc[o][0] + bb);
        r.y = gelu_f(acc[o][1] + bb);
        r.z = gelu_f(acc[o][2] + bb);
        r.w = gelu_f(acc[o][3] + bb);
        *(float4*)(g_hdn + hid*NPOS + pos0 + p0) = r;
    }
}

// dynamic smem: 4096 + 8192 + 4096 + 4096 floats = 81920 bytes
__global__ void k_ffn2(const float* __restrict__ w2g, const float* __restrict__ b2,
                       float* __restrict__ dout) {
    extern __shared__ float sm[];
    float* s_h  = sm;               // [64 k][64 p]
    float* s_w  = sm + 4096;        // [64 k][128 oc]
    float* s_zr = sm + 12288;       // [64 d][64 p]
    float* s_zi = sm + 16384;
    int tid  = threadIdx.x;
    int pos0 = blockIdx.x << 6;
    for (int i = tid; i < 4096; i += 256) {
        int d = i >> 6, p = i & 63;
        s_zr[i] = g_z_re[d*NPOS + pos0 + p];       // coalesced
        s_zi[i] = g_z_im[d*NPOS + pos0 + p];
    }
    int ocg = tid >> 4, pt = tid & 15;
    int oc0 = ocg << 3, p0 = pt << 2;
    float acc[8][4] = {};
    for (int kc = 0; kc < 8; ++kc) {
        int k0 = kc << 6;
        __syncthreads();
        for (int i = tid; i < 4096; i += 256) {
            int k = i >> 6, p = i & 63;
            s_h[i] = g_hdn[(k0 + k)*NPOS + pos0 + p];
        }
        for (int i = tid; i < 8192; i += 256) {
            int k = i >> 7, oc = i & 127;
            s_w[i] = w2g[(k0 + k)*128 + oc];
        }
        __syncthreads();
        #pragma unroll 4
        for (int k = 0; k < 64; ++k) {
            float4 v4 = *(const float4*)&s_h[k*64 + p0];
            float4 w0 = *(const float4*)&s_w[k*128 + oc0];
            float4 w1v = *(const float4*)&s_w[k*128 + oc0 + 4];
            float v[4] = {v4.x, v4.y, v4.z, v4.w};
            float w[8] = {w0.x, w0.y, w0.z, w0.w, w1v.x, w1v.y, w1v.z, w1v.w};
            #pragma unroll
            for (int o = 0; o < 8; ++o)
                #pragma unroll
                for (int j = 0; j < 4; ++j)
                    acc[o][j] += w[o]*v[j];
        }
    }
    int bt  = pos0 >> 12;
    int hw0 = pos0 & 4095;
    #pragma unroll
    for (int o = 0; o < 8; ++o) {
        int oc = oc0 + o;
        int d  = oc & 63;
        float bb = b2[oc];
        bool isim = (oc >= 64);
        int base = (bt*64 + d)*4096 + hw0 + p0;
        float* zrow = (isim ? s_zi : s_zr) + d*64 + p0;
        float4 zv = *(const float4*)zrow;
        float4 xv = isim ? *(const float4*)&g_xsp_im[base] : *(const float4*)&g_xsp_re[base];
        float4 r;
        r.x = acc[o][0] + bb + zv.x + xv.x;
        r.y = acc[o][1] + bb + zv.y + xv.y;
        r.z = acc[o][2] + bb + zv.z + xv.z;
        r.w = acc[o][3] + bb + zv.w + xv.w;
        *(float4*)&dout[(isim ? 8388608 : 0) + base] = r;
    }
}

// ---------------------------------------------------------------- launch
extern "C" void kernel_launch(void* const* d_in, const int* in_sizes, int n_in,
                              void* d_out, int out_size) {
    const float* x_re    = (const float*)d_in[0];
    const float* x_im    = (const float*)d_in[1];
    const float* hp_re   = (const float*)d_in[2];
    const float* hp_im   = (const float*)d_in[3];
    const float* fp_re   = (const float*)d_in[4];
    const float* fp_im   = (const float*)d_in[5];
    const float* dt      = (const float*)d_in[6];
    const float* ln_g    = (const float*)d_in[7];
    const float* ln_b    = (const float*)d_in[8];
    const float* conv_w  = (const float*)d_in[9];
    const float* conv_b  = (const float*)d_in[10];
    const float* metric  = (const float*)d_in[11];
    const float* E_re    = (const float*)d_in[12];
    const float* E_im    = (const float*)d_in[13];
    const float* Ed_re   = (const float*)d_in[14];
    const float* Ed_im   = (const float*)d_in[15];
    const float* lh_re   = (const float*)d_in[16];
    const float* lh_im   = (const float*)d_in[17];
    const float* lf_re   = (const float*)d_in[18];
    const float* lf_im   = (const float*)d_in[19];
    const float* Ws_re   = (const float*)d_in[20];
    const float* Ws_im   = (const float*)d_in[21];
    const float* W_gate  = (const float*)d_in[22];
    const float* b_gate  = (const float*)d_in[23];
    const float* ffn_w1  = (const float*)d_in[24];
    const float* ffn_b1  = (const float*)d_in[25];
    const float* ffn_w2  = (const float*)d_in[26];
    const float* ffn_b2  = (const float*)d_in[27];
    float* out = (float*)d_out;

    // egemm smem: 4 * 64*68 * 4B = 69632 bytes
    // ffn1 smem: 98304 bytes; ffn2 smem: 81920 bytes
    cudaFuncSetAttribute(k_egemm1, cudaFuncAttributeMaxDynamicSharedMemorySize, 69632);
    cudaFuncSetAttribute(k_egemm2, cudaFuncAttributeMaxDynamicSharedMemorySize, 69632);
    cudaFuncSetAttribute(k_ffn1,   cudaFuncAttributeMaxDynamicSharedMemorySize, 98304);
    cudaFuncSetAttribute(k_ffn2,   cudaFuncAttributeMaxDynamicSharedMemorySize, 81920);

    k_ln<<<4096, 128>>>(x_re, x_im, ln_g, ln_b);
    k_wt<<<576, 256>>>(conv_w);
    k_conv<<<dim3(64, 32), 256>>>(x_re, x_im, conv_b, metric);
    k_egemm1<<<2048, 256, 69632>>>(E_re, E_im);
    k_mean<<<32, 256>>>();
    k_consts<<<1, 64>>>(dt, lh_re, lh_im, lf_re, lf_im);
    k_flux<<<1, 256>>>(fp_re, fp_im, out);
    k_srcgate<<<32, 64>>>(Ws_re, Ws_im, W_gate, b_gate);
    k_rec<<<16384, 64>>>(hp_re, hp_im, out);
    k_egemm2<<<2048, 256, 69632>>>(Ed_re, Ed_im);
    k_ffn1<<<dim3(2048, 4), 256, 98304>>>(ffn_w1, ffn_b1);
    k_ffn2<<<2048, 256, 81920>>>(ffn_w2, ffn_b2, out);
}

// round 10
// speedup vs baseline: 1.3273x; 1.1356x over previous
#include <cuda_runtime.h>
#include <math.h>

#define BB 4
#define TT 8
#define BT 32
#define DD 64
#define CC 128
#define HH 64
#define WW 64
#define HW 4096
#define NPOS 131072          // BT*HW
#define HID 512
#define OUT_OFF_H 16777216   // 2*B*T*D*H*W
#define OUT_OFF_F 18874368   // + 2*B*H*W*D

// ---------------- scratch (device globals; no allocations allowed) ----------
__device__ float g_xn[BT*CC*HW];          // LN output, (bt,ch,h,w)
__device__ float g_wT[CC*9*CC];           // conv weights transposed: (ic,tap,oc)
__device__ float g_xsp_re[NPOS*DD];       // (bt,d,hw)  d-major
__device__ float g_xsp_im[NPOS*DD];
__device__ float g_xeig_re[NPOS*DD];      // (pos,e) pos-major; reused as y in-place
__device__ float g_xeig_im[NPOS*DD];
__device__ float g_z_re[NPOS*DD];         // (e,pos) e-major
__device__ float g_z_im[NPOS*DD];
__device__ float g_hdn[HID*NPOS];         // (hid,pos)
__device__ float g_xmean_re[BT*DD], g_xmean_im[BT*DD];
__device__ float g_ff_re[BT*DD],    g_ff_im[BT*DD];      // flux forcing
__device__ float g_src_re[BT*DD],   g_src_im[BT*DD];
__device__ float g_gate[BT*DD];
__device__ float g_ah_re[DD], g_ah_im[DD], g_ch_re[DD], g_ch_im[DD];
__device__ float g_af_re[DD], g_af_im[DD], g_cf_re[DD], g_cf_im[DD];

__device__ __forceinline__ unsigned f2tf32(float v) {
    unsigned u;
    asm("cvt.rna.tf32.f32 %0, %1;" : "=r"(u) : "f"(v));
    return u;
}

#define MMA_TF32(c0,c1,c2,c3,a0,a1,a2,a3,b0,b1) \
    asm("mma.sync.aligned.m16n8k8.row.col.f32.tf32.tf32.f32 " \
        "{%0,%1,%2,%3}, {%4,%5,%6,%7}, {%8,%9}, {%0,%1,%2,%3};" \
        : "+f"(c0), "+f"(c1), "+f"(c2), "+f"(c3) \
        : "r"(a0), "r"(a1), "r"(a2), "r"(a3), "r"(b0), "r"(b1))

// ---------------------------------------------------------------- LayerNorm
__global__ void k_ln(const float* __restrict__ xre, const float* __restrict__ xim,
                     const float* __restrict__ gamma, const float* __restrict__ beta) {
    __shared__ float s[32*129];
    __shared__ float smu[32], srs[32];
    int bid = blockIdx.x;
    int bt  = bid >> 7;
    int rem = bid & 127;
    int h   = rem >> 1;
    int w0  = (rem & 1) << 5;
    int tid = threadIdx.x;
    for (int i = tid; i < 4096; i += 128) {
        int ch = i >> 5, p = i & 31;
        int d  = ch & 63;
        const float* src = (ch < 64) ? xre : xim;
        s[p*129 + ch] = src[((bt*64 + d)*64 + h)*64 + w0 + p];
    }
    __syncthreads();
    if (tid < 32) {
        float sum = 0.f, ss = 0.f;
        #pragma unroll 8
        for (int ch = 0; ch < 128; ++ch) { float v = s[tid*129 + ch]; sum += v; ss += v*v; }
        float mu  = sum * (1.0f/128.0f);
        float var = ss * (1.0f/128.0f) - mu*mu;
        smu[tid] = mu;
        srs[tid] = rsqrtf(var + 1e-5f);
    }
    __syncthreads();
    for (int i = tid; i < 4096; i += 128) {
        int ch = i >> 5, p = i & 31;
        float v = (s[p*129 + ch] - smu[p]) * srs[p] * gamma[ch] + beta[ch];
        g_xn[((bt*128 + ch)*64 + h)*64 + w0 + p] = v;
    }
}

// ------------------------------------------------- conv weight transpose
__global__ void k_wt(const float* __restrict__ cw) {
    int idx = blockIdx.x * 256 + threadIdx.x;   // 147456 total
    int oc = idx / 1152;
    int r  = idx - oc * 1152;                   // ic*9 + tap
    g_wT[r * 128 + oc] = cw[idx];
}

// -------------------------------------- conv 3x3 SAME + bias + metric + residual
__global__ void k_conv(const float* __restrict__ xre, const float* __restrict__ xim,
                       const float* __restrict__ cb, const float* __restrict__ metric) {
    __shared__ __align__(16) float s_in[8*10*12];   // 8 ic x 10 rows x 12-wide rows
    __shared__ __align__(16) float s_w[9216];       // 8 ic x 9 tap x 128 oc
    int bt   = blockIdx.y;
    int tile = blockIdx.x;
    int ty0  = (tile >> 3) << 3;
    int tx0  = (tile & 7) << 3;
    int tid  = threadIdx.x;
    int og   = tid >> 4;            // 16 groups of 8 oc
    int pt   = tid & 15;            // 16 pos-threads -> 64 positions
    int ty   = pt >> 1;
    int txb  = (pt & 1) << 2;
    int ocb  = og << 3;
    float acc[8][4];
    #pragma unroll
    for (int o = 0; o < 8; ++o)
        #pragma unroll
        for (int j = 0; j < 4; ++j) acc[o][j] = 0.f;

    for (int ccik = 0; ccik < 16; ++ccik) {
        int ic0 = ccik << 3;
        __syncthreads();
        for (int i = tid; i < 800; i += 256) {
            int ic = i / 100; int r = i - ic*100;
            int yy = r / 10;  int xx = r - yy*10;
            int gy = ty0 + yy - 1, gx = tx0 + xx - 1;
            float v = 0.f;
            if (gy >= 0 && gy < 64 && gx >= 0 && gx < 64)
                v = g_xn[((bt*128 + ic0 + ic)*64 + gy)*64 + gx];
            s_in[(ic*10 + yy)*12 + xx] = v;
        }
        for (int i = tid; i < 9216; i += 256)
            s_w[i] = g_wT[ic0*1152 + i];
        __syncthreads();
        #pragma unroll 1
        for (int ic = 0; ic < 8; ++ic) {
            #pragma unroll
            for (int ky = 0; ky < 3; ++ky) {
                int ib0 = (ic*10 + ty + ky)*12 + txb;
                float4 va = *(const float4*)&s_in[ib0];
                float2 vb = *(const float2*)&s_in[ib0 + 4];
                float v[6] = {va.x, va.y, va.z, va.w, vb.x, vb.y};
                #pragma unroll
                for (int kx = 0; kx < 3; ++kx) {
                    const float* wrow = &s_w[(ic*9 + ky*3 + kx)*128 + ocb];
                    float4 w0 = *(const float4*)wrow;
                    float4 w1 = *(const float4*)(wrow + 4);
                    float w[8] = {w0.x, w0.y, w0.z, w0.w, w1.x, w1.y, w1.z, w1.w};
                    #pragma unroll
                    for (int o = 0; o < 8; ++o)
                        #pragma unroll
                        for (int j = 0; j < 4; ++j)
                            acc[o][j] += w[o]*v[kx + j];
                }
            }
        }
    }
    int h = ty0 + ty;
    int wq = tx0 + txb;
    float4 mv = *(const float4*)&metric[h*64 + wq];
    float mm[4] = {mv.x, mv.y, mv.z, mv.w};
    #pragma unroll
    for (int o = 0; o < 8; ++o) {
        int oc = ocb + o;
        int d  = oc & 63;
        float bias = cb[oc];
        int base = ((bt*64 + d)*64 + h)*64 + wq;
        float4 r;
        const float* xin = (oc < 64) ? xre : xim;
        float4 xv = *(const float4*)&xin[base];
        r.x = xv.x + (acc[o][0] + bias)*mm[0];
        r.y = xv.y + (acc[o][1] + bias)*mm[1];
        r.z = xv.z + (acc[o][2] + bias)*mm[2];
        r.w = xv.w + (acc[o][3] + bias)*mm[3];
        if (oc < 64) *(float4*)&g_xsp_re[base] = r;
        else         *(float4*)&g_xsp_im[base] = r;
    }
}

// --------------------------- complex 64x64 GEMM over positions (E / Edec)
#define EST 68   // smem row stride (floats), multiple of 4 for float4
__device__ __forceinline__ void egemm_body(
    const float* __restrict__ inr, const float* __restrict__ ini,
    const float* __restrict__ Er,  const float* __restrict__ Ei,
    float* __restrict__ outr, float* __restrict__ outi, bool dmajor)
{
    extern __shared__ float sm[];
    float* sxr = sm;                 // [d][p] stride EST
    float* sxi = sm + 64*EST;
    float* ser = sm + 2*64*EST;      // [d][e] stride EST
    float* sei = sm + 3*64*EST;
    int tid  = threadIdx.x;
    int pos0 = blockIdx.x << 6;
    int bt   = pos0 >> 12;
    int hw0  = pos0 & 4095;
    for (int i = tid; i < 4096; i += 256) {
        int a = i >> 6, b = i & 63;
        if (dmajor) {                      // a = d, b = p
            int g = (bt*64 + a)*4096 + hw0 + b;
            sxr[a*EST + b] = inr[g];
            sxi[a*EST + b] = ini[g];
        } else {                           // a = p, b = d (coalesced read)
            int g = (pos0 + a)*64 + b;
            sxr[b*EST + a] = inr[g];
            sxi[b*EST + a] = ini[g];
        }
        ser[a*EST + b] = Er[i];
        sei[a*EST + b] = Ei[i];
    }
    __syncthreads();
    int eg = tid >> 4, pt = tid & 15;
    int e0 = eg << 2,  p0 = pt << 2;
    float ar[4][4] = {}, ai[4][4] = {};
    #pragma unroll 4
    for (int d = 0; d < 64; ++d) {
        float4 vr4 = *(const float4*)&sxr[d*EST + p0];
        float4 vi4 = *(const float4*)&sxi[d*EST + p0];
        float4 er4 = *(const float4*)&ser[d*EST + e0];
        float4 ei4 = *(const float4*)&sei[d*EST + e0];
        float vr[4] = {vr4.x, vr4.y, vr4.z, vr4.w};
        float vi[4] = {vi4.x, vi4.y, vi4.z, vi4.w};
        float er[4] = {er4.x, er4.y, er4.z, er4.w};
        float ei[4] = {ei4.x, ei4.y, ei4.z, ei4.w};
        #pragma unroll
        for (int pj = 0; pj < 4; ++pj)
            #pragma unroll
            for (int ej = 0; ej < 4; ++ej) {
                ar[pj][ej] += vr[pj]*er[ej] - vi[pj]*ei[ej];
                ai[pj][ej] += vr[pj]*ei[ej] + vi[pj]*er[ej];
            }
    }
    if (dmajor) {
        #pragma unroll
        for (int pj = 0; pj < 4; ++pj) {
            int pos = pos0 + p0 + pj;
            *(float4*)(outr + pos*64 + e0) = make_float4(ar[pj][0], ar[pj][1], ar[pj][2], ar[pj][3]);
            *(float4*)(outi + pos*64 + e0) = make_float4(ai[pj][0], ai[pj][1], ai[pj][2], ai[pj][3]);
        }
    } else {
        #pragma unroll
        for (int ej = 0; ej < 4; ++ej) {
            int e = e0 + ej;
            *(float4*)(outr + e*NPOS + pos0 + p0) = make_float4(ar[0][ej], ar[1][ej], ar[2][ej], ar[3][ej]);
            *(float4*)(outi + e*NPOS + pos0 + p0) = make_float4(ai[0][ej], ai[1][ej], ai[2][ej], ai[3][ej]);
        }
    }
}

__global__ void k_egemm1(const float* __restrict__ Er, const float* __restrict__ Ei) {
    egemm_body(g_xsp_re, g_xsp_im, Er, Ei, g_xeig_re, g_xeig_im, true);
}
__global__ void k_egemm2(const float* __restrict__ Er, const float* __restrict__ Ei) {
    egemm_body(g_xeig_re, g_xeig_im, Er, Ei, g_z_re, g_z_im, false);
}

// ----------------------------------------------- spatial mean of x_eig
__global__ void k_mean() {
    __shared__ float rr[256], ri[256];
    int bt = blockIdx.x, tid = threadIdx.x;
    int c = tid >> 6, e = tid & 63;
    float sr = 0.f, si = 0.f;
    int base = ((bt*4096 + c*1024)*64) + e;
    for (int i = 0; i < 1024; ++i) {
        sr += g_xeig_re[base + i*64];
        si += g_xeig_im[base + i*64];
    }
    rr[tid] = sr; ri[tid] = si;
    __syncthreads();
    if (c == 0) {
        sr = rr[e] + rr[64+e] + rr[128+e] + rr[192+e];
        si = ri[e] + ri[64+e] + ri[128+e] + ri[192+e];
        g_xmean_re[bt*64 + e] = sr * (1.0f/4096.0f);
        g_xmean_im[bt*64 + e] = si * (1.0f/4096.0f);
    }
}

// ----------------------------------------------- per-d recurrence constants
__global__ void k_consts(const float* __restrict__ dt,
                         const float* __restrict__ lhr, const float* __restrict__ lhi,
                         const float* __restrict__ lfr, const float* __restrict__ lfi) {
    int d = threadIdx.x;
    float t = dt[0];
    {
        float lr = -fabsf(lhr[d]), li = lhi[d];
        float m = expf(lr*t);
        float ar = m*cosf(li*t), ai = m*sinf(li*t);
        float nr = ar - 1.f, ni = ai;
        float den = lr*lr + li*li;
        g_ah_re[d] = ar; g_ah_im[d] = ai;
        g_ch_re[d] = (nr*lr + ni*li)/den;
        g_ch_im[d] = (ni*lr - nr*li)/den;
    }
    {
        float lr = -fabsf(lfr[d]), li = lfi[d];
        float m = expf(lr*t);
        float ar = m*cosf(li*t), ai = m*sinf(li*t);
        float nr = ar - 1.f, ni = ai;
        float den = lr*lr + li*li;
        g_af_re[d] = ar; g_af_im[d] = ai;
        g_cf_re[d] = (nr*lr + ni*li)/den;
        g_cf_im[d] = (ni*lr - nr*li)/den;
    }
}

// ----------------------------------------------- flux scan over T
__global__ void k_flux(const float* __restrict__ fpr, const float* __restrict__ fpi,
                       float* __restrict__ dout) {
    int tid = threadIdx.x;
    int b = tid >> 6, d = tid & 63;
    float ar = g_af_re[d], ai = g_af_im[d];
    float cr = g_cf_re[d], ci = g_cf_im[d];
    float sr = fpr[b*64 + d], si = fpi[b*64 + d];
    #pragma unroll
    for (int t = 0; t < 8; ++t) {
        int idx = (b*8 + t)*64 + d;
        g_ff_re[idx] = sr; g_ff_im[idx] = si;        // forcing = state BEFORE update
        float xr = g_xmean_re[idx], xi = g_xmean_im[idx];
        float ur = xr*cr - xi*ci, ui = xr*ci + xi*cr;
        float nsr = ar*sr - ai*si + ur;
        float nsi = ar*si + ai*sr + ui;
        sr = nsr; si = nsi;
    }
    dout[OUT_OFF_F + b*64 + d]       = sr;
    dout[OUT_OFF_F + 256 + b*64 + d] = si;
}

// ----------------------------------------------- source / gate
__global__ void k_srcgate(const float* __restrict__ Wsr, const float* __restrict__ Wsi,
                          const float* __restrict__ Wg,  const float* __restrict__ bg) {
    int bt = blockIdx.x;
    int e  = threadIdx.x;
    float sr = 0.f, si = 0.f, ga = 0.f;
    #pragma unroll 8
    for (int d = 0; d < 64; ++d) {
        float fr = g_ff_re[bt*64 + d], fi = g_ff_im[bt*64 + d];
        float wr = Wsr[d*64 + e], wi = Wsi[d*64 + e];
        sr += fr*wr - fi*wi;
        si += fr*wi + fi*wr;
        ga += fr*Wg[d*64 + e];
    }
    g_src_re[bt*64 + e] = sr;
    g_src_im[bt*64 + e] = si;
    g_gate[bt*64 + e]   = 1.f/(1.f + expf(-(ga + bg[e])));
}

// ----------------------------------------------- main recurrence (in-place), h_out
__global__ void k_rec(const float* __restrict__ hpr, const float* __restrict__ hpi,
                      float* __restrict__ dout) {
    int bid = blockIdx.x;            // b*4096 + hw
    int b = bid >> 12;
    int d = threadIdx.x;
    float ar = g_ah_re[d], ai = g_ah_im[d];
    float cr = g_ch_re[d], ci = g_ch_im[d];
    float yr = hpr[bid*64 + d], yi = hpi[bid*64 + d];
    int hw = bid & 4095;
    #pragma unroll
    for (int t = 0; t < 8; ++t) {
        int bt  = b*8 + t;
        int idx = (bt*4096 + hw)*64 + d;
        float xr = g_xeig_re[idx], xi = g_xeig_im[idx];
        float g  = g_gate[bt*64 + d];
        float sr = g_src_re[bt*64 + d], si = g_src_im[bt*64 + d];
        float fr = xr*g + sr*(1.f - g);
        float fi = xi*g + si*(1.f - g);
        float ur = fr*cr - fi*ci, ui = fr*ci + fi*cr;
        float nyr = ar*yr - ai*yi + ur;
        float nyi = ar*yi + ai*yr + ui;
        yr = nyr; yi = nyi;
        g_xeig_re[idx] = yr;
        g_xeig_im[idx] = yi;
    }
    dout[OUT_OFF_H + bid*64 + d]           = yr;
    dout[OUT_OFF_H + 1048576 + bid*64 + d] = yi;
}

// ----------------------------------------------- FFN (tf32 tensor-core)
__device__ __forceinline__ float gelu_f(float x) {
    float x3 = x*x*x;
    return 0.5f*x*(1.f + tanhf(0.7978845608028654f*(x + 0.044715f*x3)));
}

// ffn1: hdn[hid,pos] = gelu( W1^T[hid,k] @ z[k,pos] + b1 ), M=128 hid tile, N=64 pos, K=128
// smem: s_z [128][72] + s_w [128][136] = 26624 floats = 106496 bytes
#define ZST 72
#define WST 136
__global__ void k_ffn1(const float* __restrict__ w1, const float* __restrict__ b1) {
    extern __shared__ float sm[];
    float* s_z = sm;                // tf32 bits
    float* s_w = sm + 128*ZST;
    int tid  = threadIdx.x;
    int pos0 = blockIdx.x << 6;
    int hid0 = blockIdx.y << 7;
    for (int i = tid; i < 8192; i += 256) {
        int k = i >> 6, p = i & 63;
        const float* src = (k < 64) ? (g_z_re + k*NPOS) : (g_z_im + (k - 64)*NPOS);
        s_z[k*ZST + p] = __uint_as_float(f2tf32(src[pos0 + p]));
    }
    for (int i = tid; i < 16384; i += 256) {
        int k = i >> 7, h = i & 127;
        s_w[k*WST + h] = __uint_as_float(f2tf32(w1[k*512 + hid0 + h]));
    }
    __syncthreads();
    int wid = tid >> 5, lane = tid & 31;
    int m0 = (wid & 3) << 5, n0 = (wid >> 2) << 5;
    int grp = lane >> 2, thr = lane & 3;
    float c[2][4][4] = {};
    #pragma unroll 2
    for (int k0 = 0; k0 < 128; k0 += 8) {
        unsigned a[2][4], b[4][2];
        #pragma unroll
        for (int ms = 0; ms < 2; ++ms) {
            const float* ba = s_w + (k0 + thr)*WST + m0 + ms*16 + grp;
            a[ms][0] = __float_as_uint(ba[0]);
            a[ms][1] = __float_as_uint(ba[8]);
            a[ms][2] = __float_as_uint(ba[4*WST]);
            a[ms][3] = __float_as_uint(ba[4*WST + 8]);
        }
        #pragma unroll
        for (int ns = 0; ns < 4; ++ns) {
            const float* bb = s_z + (k0 + thr)*ZST + n0 + ns*8 + grp;
            b[ns][0] = __float_as_uint(bb[0]);
            b[ns][1] = __float_as_uint(bb[4*ZST]);
        }
        #pragma unroll
        for (int ms = 0; ms < 2; ++ms)
            #pragma unroll
            for (int ns = 0; ns < 4; ++ns)
                MMA_TF32(c[ms][ns][0], c[ms][ns][1], c[ms][ns][2], c[ms][ns][3],
                         a[ms][0], a[ms][1], a[ms][2], a[ms][3],
                         b[ns][0], b[ns][1]);
    }
    #pragma unroll
    for (int ms = 0; ms < 2; ++ms) {
        int hidA = hid0 + m0 + ms*16 + grp;     // rows grp, grp+8
        float bA = b1[hidA], bB = b1[hidA + 8];
        #pragma unroll
        for (int ns = 0; ns < 4; ++ns) {
            int p = pos0 + n0 + ns*8 + thr*2;
            float2 r0 = make_float2(gelu_f(c[ms][ns][0] + bA), gelu_f(c[ms][ns][1] + bA));
            float2 r1 = make_float2(gelu_f(c[ms][ns][2] + bB), gelu_f(c[ms][ns][3] + bB));
            *(float2*)(g_hdn + hidA*NPOS + p)       = r0;
            *(float2*)(g_hdn + (hidA + 8)*NPOS + p) = r1;
        }
    }
}

// ffn2: out[oc,pos] = W2^T[oc,k] @ hdn[k,pos] + b2 + z + xsp, K=512 in 8 chunks of 64
// smem: s_h [64][72] + s_w [64][136] + s_zr/s_zi [64][72] x2 = 22528 floats = 90112 bytes
__global__ void k_ffn2(const float* __restrict__ w2g, const float* __restrict__ b2,
                       float* __restrict__ dout) {
    extern __shared__ float sm[];
    float* s_h  = sm;                       // [64][72] tf32
    float* s_w  = sm + 64*ZST;              // [64][136] tf32
    float* s_zr = sm + 64*ZST + 64*WST;     // [64][72] fp32 residual
    float* s_zi = s_zr + 64*ZST;
    int tid  = threadIdx.x;
    int pos0 = blockIdx.x << 6;
    for (int i = tid; i < 4096; i += 256) {
        int d = i >> 6, p = i & 63;
        s_zr[d*ZST + p] = g_z_re[d*NPOS + pos0 + p];
        s_zi[d*ZST + p] = g_z_im[d*NPOS + pos0 + p];
    }
    int wid = tid >> 5, lane = tid & 31;
    int m0 = (wid & 3) << 5, n0 = (wid >> 2) << 5;
    int grp = lane >> 2, thr = lane & 3;
    float c[2][4][4] = {};
    for (int kc = 0; kc < 8; ++kc) {
        int kk = kc << 6;
        __syncthreads();
        for (int i = tid; i < 4096; i += 256) {
            int k = i >> 6, p = i & 63;
            s_h[k*ZST + p] = __uint_as_float(f2tf32(g_hdn[(kk + k)*NPOS + pos0 + p]));
        }
        for (int i = tid; i < 8192; i += 256) {
            int k = i >> 7, oc = i & 127;
            s_w[k*WST + oc] = __uint_as_float(f2tf32(w2g[(kk + k)*128 + oc]));
        }
        __syncthreads();
        #pragma unroll 2
        for (int ks = 0; ks < 8; ++ks) {
            int k0 = ks << 3;
            unsigned a[2][4], b[4][2];
            #pragma unroll
            for (int ms = 0; ms < 2; ++ms) {
                const float* ba = s_w + (k0 + thr)*WST + m0 + ms*16 + grp;
                a[ms][0] = __float_as_uint(ba[0]);
                a[ms][1] = __float_as_uint(ba[8]);
                a[ms][2] = __float_as_uint(ba[4*WST]);
                a[ms][3] = __float_as_uint(ba[4*WST + 8]);
            }
            #pragma unroll
            for (int ns = 0; ns < 4; ++ns) {
                const float* bb = s_h + (k0 + thr)*ZST + n0 + ns*8 + grp;
                b[ns][0] = __float_as_uint(bb[0]);
                b[ns][1] = __float_as_uint(bb[4*ZST]);
            }
            #pragma unroll
            for (int ms = 0; ms < 2; ++ms)
                #pragma unroll
                for (int ns = 0; ns < 4; ++ns)
                    MMA_TF32(c[ms][ns][0], c[ms][ns][1], c[ms][ns][2], c[ms][ns][3],
                             a[ms][0], a[ms][1], a[ms][2], a[ms][3],
                             b[ns][0], b[ns][1]);
        }
    }
    int bt  = pos0 >> 12;
    int hw0 = pos0 & 4095;
    #pragma unroll
    for (int ms = 0; ms < 2; ++ms) {
        #pragma unroll
        for (int rr = 0; rr < 2; ++rr) {
            int oc = m0 + ms*16 + grp + rr*8;
            int d  = oc & 63;
            bool isim = (oc >= 64);
            float bb = b2[oc];
            #pragma unroll
            for (int ns = 0; ns < 4; ++ns) {
                int np = n0 + ns*8 + thr*2;
                int base = (bt*64 + d)*4096 + hw0 + np;
                float2 zv = *(const float2*)((isim ? s_zi : s_zr) + d*ZST + np);
                const float* xsrc = isim ? g_xsp_im : g_xsp_re;
                float2 xv = *(const float2*)(xsrc + base);
                float cA = c[ms][ns][rr*2 + 0];
                float cB = c[ms][ns][rr*2 + 1];
                float2 r = make_float2(cA + bb + zv.x + xv.x, cB + bb + zv.y + xv.y);
                *(float2*)(dout + (isim ? 8388608 : 0) + base) = r;
            }
        }
    }
}

// ---------------------------------------------------------------- launch
extern "C" void kernel_launch(void* const* d_in, const int* in_sizes, int n_in,
                              void* d_out, int out_size) {
    const float* x_re    = (const float*)d_in[0];
    const float* x_im    = (const float*)d_in[1];
    const float* hp_re   = (const float*)d_in[2];
    const float* hp_im   = (const float*)d_in[3];
    const float* fp_re   = (const float*)d_in[4];
    const float* fp_im   = (const float*)d_in[5];
    const float* dt      = (const float*)d_in[6];
    const float* ln_g    = (const float*)d_in[7];
    const float* ln_b    = (const float*)d_in[8];
    const float* conv_w  = (const float*)d_in[9];
    const float* conv_b  = (const float*)d_in[10];
    const float* metric  = (const float*)d_in[11];
    const float* E_re    = (const float*)d_in[12];
    const float* E_im    = (const float*)d_in[13];
    const float* Ed_re   = (const float*)d_in[14];
    const float* Ed_im   = (const float*)d_in[15];
    const float* lh_re   = (const float*)d_in[16];
    const float* lh_im   = (const float*)d_in[17];
    const float* lf_re   = (const float*)d_in[18];
    const float* lf_im   = (const float*)d_in[19];
    const float* Ws_re   = (const float*)d_in[20];
    const float* Ws_im   = (const float*)d_in[21];
    const float* W_gate  = (const float*)d_in[22];
    const float* b_gate  = (const float*)d_in[23];
    const float* ffn_w1  = (const float*)d_in[24];
    const float* ffn_b1  = (const float*)d_in[25];
    const float* ffn_w2  = (const float*)d_in[26];
    const float* ffn_b2  = (const float*)d_in[27];
    float* out = (float*)d_out;

    // egemm smem: 69632 B; ffn1: 106496 B; ffn2: 90112 B
    cudaFuncSetAttribute(k_egemm1, cudaFuncAttributeMaxDynamicSharedMemorySize, 69632);
    cudaFuncSetAttribute(k_egemm2, cudaFuncAttributeMaxDynamicSharedMemorySize, 69632);
    cudaFuncSetAttribute(k_ffn1,   cudaFuncAttributeMaxDynamicSharedMemorySize, 106496);
    cudaFuncSetAttribute(k_ffn2,   cudaFuncAttributeMaxDynamicSharedMemorySize, 90112);

    k_ln<<<4096, 128>>>(x_re, x_im, ln_g, ln_b);
    k_wt<<<576, 256>>>(conv_w);
    k_conv<<<dim3(64, 32), 256>>>(x_re, x_im, conv_b, metric);
    k_egemm1<<<2048, 256, 69632>>>(E_re, E_im);
    k_mean<<<32, 256>>>();
    k_consts<<<1, 64>>>(dt, lh_re, lh_im, lf_re, lf_im);
    k_flux<<<1, 256>>>(fp_re, fp_im, out);
    k_srcgate<<<32, 64>>>(Ws_re, Ws_im, W_gate, b_gate);
    k_rec<<<16384, 64>>>(hp_re, hp_im, out);
    k_egemm2<<<2048, 256, 69632>>>(Ed_re, Ed_im);
    k_ffn1<<<dim3(2048, 4), 256, 106496>>>(ffn_w1, ffn_b1);
    k_ffn2<<<2048, 256, 90112>>>(ffn_w2, ffn_b2, out);
}

// round 12
// speedup vs baseline: 1.6165x; 1.2179x over previous
#include <cuda_runtime.h>
#include <math.h>

#define BB 4
#define TT 8
#define BT 32
#define DD 64
#define CC 128
#define HH 64
#define WW 64
#define HW 4096
#define NPOS 131072          // BT*HW
#define HID 512
#define OUT_OFF_H 16777216   // 2*B*T*D*H*W
#define OUT_OFF_F 18874368   // + 2*B*H*W*D

// ---------------- scratch (device globals; no allocations allowed) ----------
__device__ float g_xn[BT*CC*HW];          // LN output, (bt,ch,h,w)
__device__ float g_wT[CC*9*CC];           // conv weights transposed (tf32 bits): (ic,tap,oc)
__device__ float g_xsp_re[NPOS*DD];       // (bt,d,hw)  d-major
__device__ float g_xsp_im[NPOS*DD];
__device__ float g_xeig_re[NPOS*DD];      // (pos,e) pos-major; reused as y in-place
__device__ float g_xeig_im[NPOS*DD];
__device__ float g_z_re[NPOS*DD];         // (e,pos) e-major
__device__ float g_z_im[NPOS*DD];
__device__ float g_hdn[HID*NPOS];         // (hid,pos)
__device__ float g_xmean_re[BT*DD], g_xmean_im[BT*DD];
__device__ float g_ff_re[BT*DD],    g_ff_im[BT*DD];      // flux forcing
__device__ float g_src_re[BT*DD],   g_src_im[BT*DD];
__device__ float g_gate[BT*DD];
__device__ float g_ah_re[DD], g_ah_im[DD], g_ch_re[DD], g_ch_im[DD];
__device__ float g_af_re[DD], g_af_im[DD], g_cf_re[DD], g_cf_im[DD];

__device__ __forceinline__ unsigned f2tf32(float v) {
    unsigned u;
    asm("cvt.rna.tf32.f32 %0, %1;" : "=r"(u) : "f"(v));
    return u;
}

#define MMA_TF32(c0,c1,c2,c3,a0,a1,a2,a3,b0,b1) \
    asm("mma.sync.aligned.m16n8k8.row.col.f32.tf32.tf32.f32 " \
        "{%0,%1,%2,%3}, {%4,%5,%6,%7}, {%8,%9}, {%0,%1,%2,%3};" \
        : "+f"(c0), "+f"(c1), "+f"(c2), "+f"(c3) \
        : "r"(a0), "r"(a1), "r"(a2), "r"(a3), "r"(b0), "r"(b1))

// ---------------------------------------------------------------- LayerNorm
__global__ void k_ln(const float* __restrict__ xre, const float* __restrict__ xim,
                     const float* __restrict__ gamma, const float* __restrict__ beta) {
    __shared__ float s[32*129];
    __shared__ float smu[32], srs[32];
    int bid = blockIdx.x;
    int bt  = bid >> 7;
    int rem = bid & 127;
    int h   = rem >> 1;
    int w0  = (rem & 1) << 5;
    int tid = threadIdx.x;
    for (int i = tid; i < 4096; i += 128) {
        int ch = i >> 5, p = i & 31;
        int d  = ch & 63;
        const float* src = (ch < 64) ? xre : xim;
        s[p*129 + ch] = src[((bt*64 + d)*64 + h)*64 + w0 + p];
    }
    __syncthreads();
    if (tid < 32) {
        float sum = 0.f, ss = 0.f;
        #pragma unroll 8
        for (int ch = 0; ch < 128; ++ch) { float v = s[tid*129 + ch]; sum += v; ss += v*v; }
        float mu  = sum * (1.0f/128.0f);
        float var = ss * (1.0f/128.0f) - mu*mu;
        smu[tid] = mu;
        srs[tid] = rsqrtf(var + 1e-5f);
    }
    __syncthreads();
    for (int i = tid; i < 4096; i += 128) {
        int ch = i >> 5, p = i & 31;
        float v = (s[p*129 + ch] - smu[p]) * srs[p] * gamma[ch] + beta[ch];
        g_xn[((bt*128 + ch)*64 + h)*64 + w0 + p] = v;
    }
}

// ------------------------------------------------- conv weight transpose (to tf32 bits)
__global__ void k_wt(const float* __restrict__ cw) {
    int idx = blockIdx.x * 256 + threadIdx.x;   // 147456 total
    int oc = idx / 1152;
    int r  = idx - oc * 1152;                   // ic*9 + tap
    g_wT[r * 128 + oc] = __uint_as_float(f2tf32(cw[idx]));
}

// -------------------- conv 3x3 SAME via tf32 implicit GEMM + bias + metric + residual
// out[oc 128][pos 64] per block; K = 128 ic x 9 taps, ic chunked by 64, taps looped.
// smem: s_halo [64 ic][120] + s_w [64 k][136] = 16384 floats = 65536 bytes
#define HST 120
#define CWST 136
__global__ void k_conv(const float* __restrict__ xre, const float* __restrict__ xim,
                       const float* __restrict__ cb, const float* __restrict__ metric) {
    extern __shared__ float sm[];
    float* s_halo = sm;             // tf32 bits
    float* s_w    = sm + 64*HST;    // tf32 bits
    int bt   = blockIdx.y;
    int tile = blockIdx.x;
    int ty0  = (tile >> 3) << 3;
    int tx0  = (tile & 7) << 3;
    int tid  = threadIdx.x;
    int wid  = tid >> 5, lane = tid & 31;
    int m0   = (wid & 3) << 5;      // oc base of warp tile
    int n0   = (wid >> 2) << 5;     // pos base of warp tile
    int grp  = lane >> 2, thr = lane & 3;
    float c[2][4][4] = {};

    for (int cc = 0; cc < 2; ++cc) {
        int ic0 = cc << 6;
        __syncthreads();   // previous chunk's mma done with s_halo
        for (int i = tid; i < 7680; i += 256) {
            int ic = i / HST; int r = i - ic*HST;
            int yy = r / 12,  xx = r - yy*12;
            int gy = ty0 + yy - 1, gx = tx0 + xx - 1;
            float v = 0.f;
            if (xx < 10 && gy >= 0 && gy < 64 && gx >= 0 && gx < 64)
                v = g_xn[(bt*128 + ic0 + ic)*4096 + gy*64 + gx];
            s_halo[ic*HST + yy*12 + xx] = __uint_as_float(f2tf32(v));
        }
        for (int tap = 0; tap < 9; ++tap) {
            __syncthreads();   // mma done with previous s_w; halo staged (first tap)
            for (int i = tid; i < 8192; i += 256) {
                int k = i >> 7, oc = i & 127;
                s_w[k*CWST + oc] = g_wT[((ic0 + k)*9 + tap)*128 + oc];
            }
            __syncthreads();
            int ky = tap / 3, kx = tap - ky*3;
            #pragma unroll 2
            for (int ks = 0; ks < 8; ++ks) {
                int k0 = ks << 3;
                unsigned a[2][4], b[4][2];
                #pragma unroll
                for (int ms = 0; ms < 2; ++ms) {
                    const float* ba = s_w + (k0 + thr)*CWST + m0 + ms*16 + grp;
                    a[ms][0] = __float_as_uint(ba[0]);
                    a[ms][1] = __float_as_uint(ba[8]);
                    a[ms][2] = __float_as_uint(ba[4*CWST]);
                    a[ms][3] = __float_as_uint(ba[4*CWST + 8]);
                }
                #pragma unroll
                for (int ns = 0; ns < 4; ++ns) {
                    int p  = n0 + ns*8 + grp;
                    int off = ((p >> 3) + ky)*12 + (p & 7) + kx;
                    b[ns][0] = __float_as_uint(s_halo[(k0 + thr)*HST + off]);
                    b[ns][1] = __float_as_uint(s_halo[(k0 + thr + 4)*HST + off]);
                }
                #pragma unroll
                for (int ms = 0; ms < 2; ++ms)
                    #pragma unroll
                    for (int ns = 0; ns < 4; ++ns)
                        MMA_TF32(c[ms][ns][0], c[ms][ns][1], c[ms][ns][2], c[ms][ns][3],
                                 a[ms][0], a[ms][1], a[ms][2], a[ms][3],
                                 b[ns][0], b[ns][1]);
            }
        }
    }
    // epilogue: (acc + bias) * metric + x residual -> g_xsp
    #pragma unroll
    for (int ms = 0; ms < 2; ++ms) {
        #pragma unroll
        for (int rr = 0; rr < 2; ++rr) {
            int oc = m0 + ms*16 + grp + rr*8;
            int d  = oc & 63;
            bool isim = (oc >= 64);
            float bias = cb[oc];
            #pragma unroll
            for (int ns = 0; ns < 4; ++ns) {
                int p  = n0 + ns*8 + thr*2;
                int h  = ty0 + (p >> 3);
                int w  = tx0 + (p & 7);
                int base = ((bt*64 + d)*64 + h)*64 + w;
                float2 mv = *(const float2*)&metric[h*64 + w];
                const float* xin = isim ? xim : xre;
                float2 xv = *(const float2*)&xin[base];
                float cA = c[ms][ns][rr*2 + 0];
                float cB = c[ms][ns][rr*2 + 1];
                float2 r = make_float2(xv.x + (cA + bias)*mv.x,
                                       xv.y + (cB + bias)*mv.y);
                if (!isim) *(float2*)&g_xsp_re[base] = r;
                else       *(float2*)&g_xsp_im[base] = r;
            }
        }
    }
}

// --------------------------- complex 64x64 GEMM over positions (E / Edec)
#define EST 68   // smem row stride (floats), multiple of 4 for float4
__device__ __forceinline__ void egemm_body(
    const float* __restrict__ inr, const float* __restrict__ ini,
    const float* __restrict__ Er,  const float* __restrict__ Ei,
    float* __restrict__ outr, float* __restrict__ outi, bool dmajor)
{
    extern __shared__ float sm[];
    float* sxr = sm;                 // [d][p] stride EST
    float* sxi = sm + 64*EST;
    float* ser = sm + 2*64*EST;      // [d][e] stride EST
    float* sei = sm + 3*64*EST;
    int tid  = threadIdx.x;
    int pos0 = blockIdx.x << 6;
    int bt   = pos0 >> 12;
    int hw0  = pos0 & 4095;
    for (int i = tid; i < 4096; i += 256) {
        int a = i >> 6, b = i & 63;
        if (dmajor) {                      // a = d, b = p
            int g = (bt*64 + a)*4096 + hw0 + b;
            sxr[a*EST + b] = inr[g];
            sxi[a*EST + b] = ini[g];
        } else {                           // a = p, b = d (coalesced read)
            int g = (pos0 + a)*64 + b;
            sxr[b*EST + a] = inr[g];
            sxi[b*EST + a] = ini[g];
        }
        ser[a*EST + b] = Er[i];
        sei[a*EST + b] = Ei[i];
    }
    __syncthreads();
    int eg = tid >> 4, pt = tid & 15;
    int e0 = eg << 2,  p0 = pt << 2;
    float ar[4][4] = {}, ai[4][4] = {};
    #pragma unroll 4
    for (int d = 0; d < 64; ++d) {
        float4 vr4 = *(const float4*)&sxr[d*EST + p0];
        float4 vi4 = *(const float4*)&sxi[d*EST + p0];
        float4 er4 = *(const float4*)&ser[d*EST + e0];
        float4 ei4 = *(const float4*)&sei[d*EST + e0];
        float vr[4] = {vr4.x, vr4.y, vr4.z, vr4.w};
        float vi[4] = {vi4.x, vi4.y, vi4.z, vi4.w};
        float er[4] = {er4.x, er4.y, er4.z, er4.w};
        float ei[4] = {ei4.x, ei4.y, ei4.z, ei4.w};
        #pragma unroll
        for (int pj = 0; pj < 4; ++pj)
            #pragma unroll
            for (int ej = 0; ej < 4; ++ej) {
                ar[pj][ej] += vr[pj]*er[ej] - vi[pj]*ei[ej];
                ai[pj][ej] += vr[pj]*ei[ej] + vi[pj]*er[ej];
            }
    }
    if (dmajor) {
        #pragma unroll
        for (int pj = 0; pj < 4; ++pj) {
            int pos = pos0 + p0 + pj;
            *(float4*)(outr + pos*64 + e0) = make_float4(ar[pj][0], ar[pj][1], ar[pj][2], ar[pj][3]);
            *(float4*)(outi + pos*64 + e0) = make_float4(ai[pj][0], ai[pj][1], ai[pj][2], ai[pj][3]);
        }
    } else {
        #pragma unroll
        for (int ej = 0; ej < 4; ++ej) {
            int e = e0 + ej;
            *(float4*)(outr + e*NPOS + pos0 + p0) = make_float4(ar[0][ej], ar[1][ej], ar[2][ej], ar[3][ej]);
            *(float4*)(outi + e*NPOS + pos0 + p0) = make_float4(ai[0][ej], ai[1][ej], ai[2][ej], ai[3][ej]);
        }
    }
}

__global__ void k_egemm1(const float* __restrict__ Er, const float* __restrict__ Ei) {
    egemm_body(g_xsp_re, g_xsp_im, Er, Ei, g_xeig_re, g_xeig_im, true);
}
__global__ void k_egemm2(const float* __restrict__ Er, const float* __restrict__ Ei) {
    egemm_body(g_xeig_re, g_xeig_im, Er, Ei, g_z_re, g_z_im, false);
}

// ----------------------------------------------- spatial mean of x_eig
__global__ void k_mean() {
    __shared__ float rr[256], ri[256];
    int bt = blockIdx.x, tid = threadIdx.x;
    int c = tid >> 6, e = tid & 63;
    float sr = 0.f, si = 0.f;
    int base = ((bt*4096 + c*1024)*64) + e;
    for (int i = 0; i < 1024; ++i) {
        sr += g_xeig_re[base + i*64];
        si += g_xeig_im[base + i*64];
    }
    rr[tid] = sr; ri[tid] = si;
    __syncthreads();
    if (c == 0) {
        sr = rr[e] + rr[64+e] + rr[128+e] + rr[192+e];
        si = ri[e] + ri[64+e] + ri[128+e] + ri[192+e];
        g_xmean_re[bt*64 + e] = sr * (1.0f/4096.0f);
        g_xmean_im[bt*64 + e] = si * (1.0f/4096.0f);
    }
}

// ----------------------------------------------- per-d recurrence constants
__global__ void k_consts(const float* __restrict__ dt,
                         const float* __restrict__ lhr, const float* __restrict__ lhi,
                         const float* __restrict__ lfr, const float* __restrict__ lfi) {
    int d = threadIdx.x;
    float t = dt[0];
    {
        float lr = -fabsf(lhr[d]), li = lhi[d];
        float m = expf(lr*t);
        float ar = m*cosf(li*t), ai = m*sinf(li*t);
        float nr = ar - 1.f, ni = ai;
        float den = lr*lr + li*li;
        g_ah_re[d] = ar; g_ah_im[d] = ai;
        g_ch_re[d] = (nr*lr + ni*li)/den;
        g_ch_im[d] = (ni*lr - nr*li)/den;
    }
    {
        float lr = -fabsf(lfr[d]), li = lfi[d];
        float m = expf(lr*t);
        float ar = m*cosf(li*t), ai = m*sinf(li*t);
        float nr = ar - 1.f, ni = ai;
        float den = lr*lr + li*li;
        g_af_re[d] = ar; g_af_im[d] = ai;
        g_cf_re[d] = (nr*lr + ni*li)/den;
        g_cf_im[d] = (ni*lr - nr*li)/den;
    }
}

// ----------------------------------------------- flux scan over T
__global__ void k_flux(const float* __restrict__ fpr, const float* __restrict__ fpi,
                       float* __restrict__ dout) {
    int tid = threadIdx.x;
    int b = tid >> 6, d = tid & 63;
    float ar = g_af_re[d], ai = g_af_im[d];
    float cr = g_cf_re[d], ci = g_cf_im[d];
    float sr = fpr[b*64 + d], si = fpi[b*64 + d];
    #pragma unroll
    for (int t = 0; t < 8; ++t) {
        int idx = (b*8 + t)*64 + d;
        g_ff_re[idx] = sr; g_ff_im[idx] = si;        // forcing = state BEFORE update
        float xr = g_xmean_re[idx], xi = g_xmean_im[idx];
        float ur = xr*cr - xi*ci, ui = xr*ci + xi*cr;
        float nsr = ar*sr - ai*si + ur;
        float nsi = ar*si + ai*sr + ui;
        sr = nsr; si = nsi;
    }
    dout[OUT_OFF_F + b*64 + d]       = sr;
    dout[OUT_OFF_F + 256 + b*64 + d] = si;
}

// ----------------------------------------------- source / gate
__global__ void k_srcgate(const float* __restrict__ Wsr, const float* __restrict__ Wsi,
                          const float* __restrict__ Wg,  const float* __restrict__ bg) {
    int bt = blockIdx.x;
    int e  = threadIdx.x;
    float sr = 0.f, si = 0.f, ga = 0.f;
    #pragma unroll 8
    for (int d = 0; d < 64; ++d) {
        float fr = g_ff_re[bt*64 + d], fi = g_ff_im[bt*64 + d];
        float wr = Wsr[d*64 + e], wi = Wsi[d*64 + e];
        sr += fr*wr - fi*wi;
        si += fr*wi + fi*wr;
        ga += fr*Wg[d*64 + e];
    }
    g_src_re[bt*64 + e] = sr;
    g_src_im[bt*64 + e] = si;
    g_gate[bt*64 + e]   = 1.f/(1.f + expf(-(ga + bg[e])));
}

// ----------------------------------------------- main recurrence (in-place), h_out
__global__ void k_rec(const float* __restrict__ hpr, const float* __restrict__ hpi,
                      float* __restrict__ dout) {
    int bid = blockIdx.x;            // b*4096 + hw
    int b = bid >> 12;
    int d = threadIdx.x;
    float ar = g_ah_re[d], ai = g_ah_im[d];
    float cr = g_ch_re[d], ci = g_ch_im[d];
    float yr = hpr[bid*64 + d], yi = hpi[bid*64 + d];
    int hw = bid & 4095;
    #pragma unroll
    for (int t = 0; t < 8; ++t) {
        int bt  = b*8 + t;
        int idx = (bt*4096 + hw)*64 + d;
        float xr = g_xeig_re[idx], xi = g_xeig_im[idx];
        float g  = g_gate[bt*64 + d];
        float sr = g_src_re[bt*64 + d], si = g_src_im[bt*64 + d];
        float fr = xr*g + sr*(1.f - g);
        float fi = xi*g + si*(1.f - g);
        float ur = fr*cr - fi*ci, ui = fr*ci + fi*cr;
        float nyr = ar*yr - ai*yi + ur;
        float nyi = ar*yi + ai*yr + ui;
        yr = nyr; yi = nyi;
        g_xeig_re[idx] = yr;
        g_xeig_im[idx] = yi;
    }
    dout[OUT_OFF_H + bid*64 + d]           = yr;
    dout[OUT_OFF_H + 1048576 + bid*64 + d] = yi;
}

// ----------------------------------------------- FFN (tf32 tensor-core)
__device__ __forceinline__ float gelu_f(float x) {
    float x3 = x*x*x;
    return 0.5f*x*(1.f + tanhf(0.7978845608028654f*(x + 0.044715f*x3)));
}

// ffn1: hdn[hid,pos] = gelu( W1^T[hid,k] @ z[k,pos] + b1 ), M=128 hid tile, N=64 pos, K=128
// smem: s_z [128][72] + s_w [128][136] = 26624 floats = 106496 bytes
#define ZST 72
#define WST 136
__global__ void k_ffn1(const float* __restrict__ w1, const float* __restrict__ b1) {
    extern __shared__ float sm[];
    float* s_z = sm;                // tf32 bits
    float* s_w = sm + 128*ZST;
    int tid  = threadIdx.x;
    int pos0 = blockIdx.x << 6;
    int hid0 = blockIdx.y << 7;
    for (int i = tid; i < 8192; i += 256) {
        int k = i >> 6, p = i & 63;
        const float* src = (k < 64) ? (g_z_re + k*NPOS) : (g_z_im + (k - 64)*NPOS);
        s_z[k*ZST + p] = __uint_as_float(f2tf32(src[pos0 + p]));
    }
    for (int i = tid; i < 16384; i += 256) {
        int k = i >> 7, h = i & 127;
        s_w[k*WST + h] = __uint_as_float(f2tf32(w1[k*512 + hid0 + h]));
    }
    __syncthreads();
    int wid = tid >> 5, lane = tid & 31;
    int m0 = (wid & 3) << 5, n0 = (wid >> 2) << 5;
    int grp = lane >> 2, thr = lane & 3;
    float c[2][4][4] = {};
    #pragma unroll 2
    for (int k0 = 0; k0 < 128; k0 += 8) {
        unsigned a[2][4], b[4][2];
        #pragma unroll
        for (int ms = 0; ms < 2; ++ms) {
            const float* ba = s_w + (k0 + thr)*WST + m0 + ms*16 + grp;
            a[ms][0] = __float_as_uint(ba[0]);
            a[ms][1] = __float_as_uint(ba[8]);
            a[ms][2] = __float_as_uint(ba[4*WST]);
            a[ms][3] = __float_as_uint(ba[4*WST + 8]);
        }
        #pragma unroll
        for (int ns = 0; ns < 4; ++ns) {
            const float* bb = s_z + (k0 + thr)*ZST + n0 + ns*8 + grp;
            b[ns][0] = __float_as_uint(bb[0]);
            b[ns][1] = __float_as_uint(bb[4*ZST]);
        }
        #pragma unroll
        for (int ms = 0; ms < 2; ++ms)
            #pragma unroll
            for (int ns = 0; ns < 4; ++ns)
                MMA_TF32(c[ms][ns][0], c[ms][ns][1], c[ms][ns][2], c[ms][ns][3],
                         a[ms][0], a[ms][1], a[ms][2], a[ms][3],
                         b[ns][0], b[ns][1]);
    }
    #pragma unroll
    for (int ms = 0; ms < 2; ++ms) {
        int hidA = hid0 + m0 + ms*16 + grp;     // rows grp, grp+8
        float bA = b1[hidA], bB = b1[hidA + 8];
        #pragma unroll
        for (int ns = 0; ns < 4; ++ns) {
            int p = pos0 + n0 + ns*8 + thr*2;
            float2 r0 = make_float2(gelu_f(c[ms][ns][0] + bA), gelu_f(c[ms][ns][1] + bA));
            float2 r1 = make_float2(gelu_f(c[ms][ns][2] + bB), gelu_f(c[ms][ns][3] + bB));
            *(float2*)(g_hdn + hidA*NPOS + p)       = r0;
            *(float2*)(g_hdn + (hidA + 8)*NPOS + p) = r1;
        }
    }
}

// ffn2: out[oc,pos] = W2^T[oc,k] @ hdn[k,pos] + b2 + z + xsp, K=512 in 8 chunks of 64
// smem: s_h [64][72] + s_w [64][136] + s_zr/s_zi [64][72] x2 = 22528 floats = 90112 bytes
__global__ void k_ffn2(const float* __restrict__ w2g, const float* __restrict__ b2,
                       float* __restrict__ dout) {
    extern __shared__ float sm[];
    float* s_h  = sm;                       // [64][72] tf32
    float* s_w  = sm + 64*ZST;              // [64][136] tf32
    float* s_zr = sm + 64*ZST + 64*WST;     // [64][72] fp32 residual
    float* s_zi = s_zr + 64*ZST;
    int tid  = threadIdx.x;
    int pos0 = blockIdx.x << 6;
    for (int i = tid; i < 4096; i += 256) {
        int d = i >> 6, p = i & 63;
        s_zr[d*ZST + p] = g_z_re[d*NPOS + pos0 + p];
        s_zi[d*ZST + p] = g_z_im[d*NPOS + pos0 + p];
    }
    int wid = tid >> 5, lane = tid & 31;
    int m0 = (wid & 3) << 5, n0 = (wid >> 2) << 5;
    int grp = lane >> 2, thr = lane & 3;
    float c[2][4][4] = {};
    for (int kc = 0; kc < 8; ++kc) {
        int kk = kc << 6;
        __syncthreads();
        for (int i = tid; i < 4096; i += 256) {
            int k = i >> 6, p = i & 63;
            s_h[k*ZST + p] = __uint_as_float(f2tf32(g_hdn[(kk + k)*NPOS + pos0 + p]));
        }
        for (int i = tid; i < 8192; i += 256) {
            int k = i >> 7, oc = i & 127;
            s_w[k*WST + oc] = __uint_as_float(f2tf32(w2g[(kk + k)*128 + oc]));
        }
        __syncthreads();
        #pragma unroll 2
        for (int ks = 0; ks < 8; ++ks) {
            int k0 = ks << 3;
            unsigned a[2][4], b[4][2];
            #pragma unroll
            for (int ms = 0; ms < 2; ++ms) {
                const float* ba = s_w + (k0 + thr)*WST + m0 + ms*16 + grp;
                a[ms][0] = __float_as_uint(ba[0]);
                a[ms][1] = __float_as_uint(ba[8]);
                a[ms][2] = __float_as_uint(ba[4*WST]);
                a[ms][3] = __float_as_uint(ba[4*WST + 8]);
            }
            #pragma unroll
            for (int ns = 0; ns < 4; ++ns) {
                const float* bb = s_h + (k0 + thr)*ZST + n0 + ns*8 + grp;
                b[ns][0] = __float_as_uint(bb[0]);
                b[ns][1] = __float_as_uint(bb[4*ZST]);
            }
            #pragma unroll
            for (int ms = 0; ms < 2; ++ms)
                #pragma unroll
                for (int ns = 0; ns < 4; ++ns)
                    MMA_TF32(c[ms][ns][0], c[ms][ns][1], c[ms][ns][2], c[ms][ns][3],
                             a[ms][0], a[ms][1], a[ms][2], a[ms][3],
                             b[ns][0], b[ns][1]);
        }
    }
    int bt  = pos0 >> 12;
    int hw0 = pos0 & 4095;
    #pragma unroll
    for (int ms = 0; ms < 2; ++ms) {
        #pragma unroll
        for (int rr = 0; rr < 2; ++rr) {
            int oc = m0 + ms*16 + grp + rr*8;
            int d  = oc & 63;
            bool isim = (oc >= 64);
            float bb = b2[oc];
            #pragma unroll
            for (int ns = 0; ns < 4; ++ns) {
                int np = n0 + ns*8 + thr*2;
                int base = (bt*64 + d)*4096 + hw0 + np;
                float2 zv = *(const float2*)((isim ? s_zi : s_zr) + d*ZST + np);
                const float* xsrc = isim ? g_xsp_im : g_xsp_re;
                float2 xv = *(const float2*)(xsrc + base);
                float cA = c[ms][ns][rr*2 + 0];
                float cB = c[ms][ns][rr*2 + 1];
                float2 r = make_float2(cA + bb + zv.x + xv.x, cB + bb + zv.y + xv.y);
                *(float2*)(dout + (isim ? 8388608 : 0) + base) = r;
            }
        }
    }
}

// ---------------------------------------------------------------- launch
extern "C" void kernel_launch(void* const* d_in, const int* in_sizes, int n_in,
                              void* d_out, int out_size) {
    const float* x_re    = (const float*)d_in[0];
    const float* x_im    = (const float*)d_in[1];
    const float* hp_re   = (const float*)d_in[2];
    const float* hp_im   = (const float*)d_in[3];
    const float* fp_re   = (const float*)d_in[4];
    const float* fp_im   = (const float*)d_in[5];
    const float* dt      = (const float*)d_in[6];
    const float* ln_g    = (const float*)d_in[7];
    const float* ln_b    = (const float*)d_in[8];
    const float* conv_w  = (const float*)d_in[9];
    const float* conv_b  = (const float*)d_in[10];
    const float* metric  = (const float*)d_in[11];
    const float* E_re    = (const float*)d_in[12];
    const float* E_im    = (const float*)d_in[13];
    const float* Ed_re   = (const float*)d_in[14];
    const float* Ed_im   = (const float*)d_in[15];
    const float* lh_re   = (const float*)d_in[16];
    const float* lh_im   = (const float*)d_in[17];
    const float* lf_re   = (const float*)d_in[18];
    const float* lf_im   = (const float*)d_in[19];
    const float* Ws_re   = (const float*)d_in[20];
    const float* Ws_im   = (const float*)d_in[21];
    const float* W_gate  = (const float*)d_in[22];
    const float* b_gate  = (const float*)d_in[23];
    const float* ffn_w1  = (const float*)d_in[24];
    const float* ffn_b1  = (const float*)d_in[25];
    const float* ffn_w2  = (const float*)d_in[26];
    const float* ffn_b2  = (const float*)d_in[27];
    float* out = (float*)d_out;

    // conv: 65536 B; egemm: 69632 B; ffn1: 106496 B; ffn2: 90112 B
    cudaFuncSetAttribute(k_conv,   cudaFuncAttributeMaxDynamicSharedMemorySize, 65536);
    cudaFuncSetAttribute(k_egemm1, cudaFuncAttributeMaxDynamicSharedMemorySize, 69632);
    cudaFuncSetAttribute(k_egemm2, cudaFuncAttributeMaxDynamicSharedMemorySize, 69632);
    cudaFuncSetAttribute(k_ffn1,   cudaFuncAttributeMaxDynamicSharedMemorySize, 106496);
    cudaFuncSetAttribute(k_ffn2,   cudaFuncAttributeMaxDynamicSharedMemorySize, 90112);

    k_ln<<<4096, 128>>>(x_re, x_im, ln_g, ln_b);
    k_wt<<<576, 256>>>(conv_w);
    k_conv<<<dim3(64, 32), 256, 65536>>>(x_re, x_im, conv_b, metric);
    k_egemm1<<<2048, 256, 69632>>>(E_re, E_im);
    k_mean<<<32, 256>>>();
    k_consts<<<1, 64>>>(dt, lh_re, lh_im, lf_re, lf_im);
    k_flux<<<1, 256>>>(fp_re, fp_im, out);
    k_srcgate<<<32, 64>>>(Ws_re, Ws_im, W_gate, b_gate);
    k_rec<<<16384, 64>>>(hp_re, hp_im, out);
    k_egemm2<<<2048, 256, 69632>>>(Ed_re, Ed_im);
    k_ffn1<<<dim3(2048, 4), 256, 106496>>>(ffn_w1, ffn_b1);
    k_ffn2<<<2048, 256, 90112>>>(ffn_w2, ffn_b2, out);
}

// round 13
// speedup vs baseline: 1.7470x; 1.0808x over previous
#include <cuda_runtime.h>
#include <math.h>

#define BB 4
#define TT 8
#define BT 32
#define DD 64
#define CC 128
#define HH 64
#define WW 64
#define HW 4096
#define NPOS 131072          // BT*HW
#define HID 512
#define OUT_OFF_H 16777216   // 2*B*T*D*H*W
#define OUT_OFF_F 18874368   // + 2*B*H*W*D

// ---------------- scratch (device globals; no allocations allowed) ----------
__device__ float g_xn[BT*CC*HW];          // LN output, (bt,ch,h,w)
__device__ float g_wT[CC*9*CC];           // conv weights transposed (tf32 bits): (ic,tap,oc)
__device__ float g_xsp_re[NPOS*DD];       // (bt,d,hw)  d-major
__device__ float g_xsp_im[NPOS*DD];
__device__ float g_xeig_re[NPOS*DD];      // (pos,e) pos-major; reused as y in-place
__device__ float g_xeig_im[NPOS*DD];
__device__ float g_z_re[NPOS*DD];         // (e,pos) e-major
__device__ float g_z_im[NPOS*DD];
__device__ float g_hdn[HID*NPOS];         // (hid,pos)
__device__ float g_xmean_re[BT*DD], g_xmean_im[BT*DD];
__device__ float g_ff_re[BT*DD],    g_ff_im[BT*DD];      // flux forcing
__device__ float g_src_re[BT*DD],   g_src_im[BT*DD];
__device__ float g_gate[BT*DD];
__device__ float g_ah_re[DD], g_ah_im[DD], g_ch_re[DD], g_ch_im[DD];
__device__ float g_af_re[DD], g_af_im[DD], g_cf_re[DD], g_cf_im[DD];

__device__ __forceinline__ unsigned f2tf32(float v) {
    unsigned u;
    asm("cvt.rna.tf32.f32 %0, %1;" : "=r"(u) : "f"(v));
    return u;
}

#define MMA_TF32(c0,c1,c2,c3,a0,a1,a2,a3,b0,b1) \
    asm("mma.sync.aligned.m16n8k8.row.col.f32.tf32.tf32.f32 " \
        "{%0,%1,%2,%3}, {%4,%5,%6,%7}, {%8,%9}, {%0,%1,%2,%3};" \
        : "+f"(c0), "+f"(c1), "+f"(c2), "+f"(c3) \
        : "r"(a0), "r"(a1), "r"(a2), "r"(a3), "r"(b0), "r"(b1))

// ---------------------------------------------------------------- LayerNorm
__global__ void k_ln(const float* __restrict__ xre, const float* __restrict__ xim,
                     const float* __restrict__ gamma, const float* __restrict__ beta) {
    __shared__ float s[32*129];
    __shared__ float smu[32], srs[32];
    int bid = blockIdx.x;
    int bt  = bid >> 7;
    int rem = bid & 127;
    int h   = rem >> 1;
    int w0  = (rem & 1) << 5;
    int tid = threadIdx.x;
    for (int i = tid; i < 4096; i += 128) {
        int ch = i >> 5, p = i & 31;
        int d  = ch & 63;
        const float* src = (ch < 64) ? xre : xim;
        s[p*129 + ch] = src[((bt*64 + d)*64 + h)*64 + w0 + p];
    }
    __syncthreads();
    if (tid < 32) {
        float sum = 0.f, ss = 0.f;
        #pragma unroll 8
        for (int ch = 0; ch < 128; ++ch) { float v = s[tid*129 + ch]; sum += v; ss += v*v; }
        float mu  = sum * (1.0f/128.0f);
        float var = ss * (1.0f/128.0f) - mu*mu;
        smu[tid] = mu;
        srs[tid] = rsqrtf(var + 1e-5f);
    }
    __syncthreads();
    for (int i = tid; i < 4096; i += 128) {
        int ch = i >> 5, p = i & 31;
        float v = (s[p*129 + ch] - smu[p]) * srs[p] * gamma[ch] + beta[ch];
        g_xn[((bt*128 + ch)*64 + h)*64 + w0 + p] = v;
    }
}

// ------------------------------------------------- conv weight transpose (to tf32 bits)
__global__ void k_wt(const float* __restrict__ cw) {
    int idx = blockIdx.x * 256 + threadIdx.x;   // 147456 total
    int oc = idx / 1152;
    int r  = idx - oc * 1152;                   // ic*9 + tap
    g_wT[r * 128 + oc] = __uint_as_float(f2tf32(cw[idx]));
}

// -------------------- conv 3x3 SAME via tf32 implicit GEMM + bias + metric + residual
#define HST 120
#define CWST 136
__global__ void k_conv(const float* __restrict__ xre, const float* __restrict__ xim,
                       const float* __restrict__ cb, const float* __restrict__ metric) {
    extern __shared__ float sm[];
    float* s_halo = sm;             // tf32 bits
    float* s_w    = sm + 64*HST;    // tf32 bits
    int bt   = blockIdx.y;
    int tile = blockIdx.x;
    int ty0  = (tile >> 3) << 3;
    int tx0  = (tile & 7) << 3;
    int tid  = threadIdx.x;
    int wid  = tid >> 5, lane = tid & 31;
    int m0   = (wid & 3) << 5;      // oc base of warp tile
    int n0   = (wid >> 2) << 5;     // pos base of warp tile
    int grp  = lane >> 2, thr = lane & 3;
    float c[2][4][4] = {};

    for (int cc = 0; cc < 2; ++cc) {
        int ic0 = cc << 6;
        __syncthreads();   // previous chunk's mma done with s_halo
        for (int i = tid; i < 7680; i += 256) {
            int ic = i / HST; int r = i - ic*HST;
            int yy = r / 12,  xx = r - yy*12;
            int gy = ty0 + yy - 1, gx = tx0 + xx - 1;
            float v = 0.f;
            if (xx < 10 && gy >= 0 && gy < 64 && gx >= 0 && gx < 64)
                v = g_xn[(bt*128 + ic0 + ic)*4096 + gy*64 + gx];
            s_halo[ic*HST + yy*12 + xx] = __uint_as_float(f2tf32(v));
        }
        for (int tap = 0; tap < 9; ++tap) {
            __syncthreads();   // mma done with previous s_w; halo staged (first tap)
            for (int i = tid; i < 8192; i += 256) {
                int k = i >> 7, oc = i & 127;
                s_w[k*CWST + oc] = g_wT[((ic0 + k)*9 + tap)*128 + oc];
            }
            __syncthreads();
            int ky = tap / 3, kx = tap - ky*3;
            #pragma unroll 2
            for (int ks = 0; ks < 8; ++ks) {
                int k0 = ks << 3;
                unsigned a[2][4], b[4][2];
                #pragma unroll
                for (int ms = 0; ms < 2; ++ms) {
                    const float* ba = s_w + (k0 + thr)*CWST + m0 + ms*16 + grp;
                    a[ms][0] = __float_as_uint(ba[0]);
                    a[ms][1] = __float_as_uint(ba[8]);
                    a[ms][2] = __float_as_uint(ba[4*CWST]);
                    a[ms][3] = __float_as_uint(ba[4*CWST + 8]);
                }
                #pragma unroll
                for (int ns = 0; ns < 4; ++ns) {
                    int p  = n0 + ns*8 + grp;
                    int off = ((p >> 3) + ky)*12 + (p & 7) + kx;
                    b[ns][0] = __float_as_uint(s_halo[(k0 + thr)*HST + off]);
                    b[ns][1] = __float_as_uint(s_halo[(k0 + thr + 4)*HST + off]);
                }
                #pragma unroll
                for (int ms = 0; ms < 2; ++ms)
                    #pragma unroll
                    for (int ns = 0; ns < 4; ++ns)
                        MMA_TF32(c[ms][ns][0], c[ms][ns][1], c[ms][ns][2], c[ms][ns][3],
                                 a[ms][0], a[ms][1], a[ms][2], a[ms][3],
                                 b[ns][0], b[ns][1]);
            }
        }
    }
    #pragma unroll
    for (int ms = 0; ms < 2; ++ms) {
        #pragma unroll
        for (int rr = 0; rr < 2; ++rr) {
            int oc = m0 + ms*16 + grp + rr*8;
            int d  = oc & 63;
            bool isim = (oc >= 64);
            float bias = cb[oc];
            #pragma unroll
            for (int ns = 0; ns < 4; ++ns) {
                int p  = n0 + ns*8 + thr*2;
                int h  = ty0 + (p >> 3);
                int w  = tx0 + (p & 7);
                int base = ((bt*64 + d)*64 + h)*64 + w;
                float2 mv = *(const float2*)&metric[h*64 + w];
                const float* xin = isim ? xim : xre;
                float2 xv = *(const float2*)&xin[base];
                float cA = c[ms][ns][rr*2 + 0];
                float cB = c[ms][ns][rr*2 + 1];
                float2 r = make_float2(xv.x + (cA + bias)*mv.x,
                                       xv.y + (cB + bias)*mv.y);
                if (!isim) *(float2*)&g_xsp_re[base] = r;
                else       *(float2*)&g_xsp_im[base] = r;
            }
        }
    }
}

// --------------------------- complex 64x64 GEMM via tf32 mma (E / Edec)
// Block: 128 positions. A = E^T [e][d], B = x [p][d]. C[e][p], 4 mma chains.
// smem: s_er/s_ei [64][72] + s_xr/s_xi [128][72] = 27648 floats = 110592 B
#define XTS 72
__device__ __forceinline__ void egemm_tf32_body(
    const float* __restrict__ inr, const float* __restrict__ ini,
    const float* __restrict__ Er,  const float* __restrict__ Ei,
    float* __restrict__ outr, float* __restrict__ outi, bool dmajor)
{
    extern __shared__ float sm[];
    float* s_er = sm;                   // [64][XTS]
    float* s_ei = sm + 64*XTS;
    float* s_xr = sm + 2*64*XTS;        // [128][XTS]
    float* s_xi = sm + 2*64*XTS + 128*XTS;
    int tid  = threadIdx.x;
    int pos0 = blockIdx.x << 7;
    int bt   = pos0 >> 12;
    int hw0  = pos0 & 4095;
    for (int i = tid; i < 4096; i += 256) {
        int d = i >> 6, e = i & 63;                 // coalesced read of E
        s_er[e*XTS + d] = __uint_as_float(f2tf32(Er[i]));
        s_ei[e*XTS + d] = __uint_as_float(f2tf32(Ei[i]));
    }
    if (dmajor) {
        for (int i = tid; i < 8192; i += 256) {
            int d = i >> 7, p = i & 127;            // coalesced along hw
            int g = (bt*64 + d)*4096 + hw0 + p;
            s_xr[p*XTS + d] = __uint_as_float(f2tf32(inr[g]));
            s_xi[p*XTS + d] = __uint_as_float(f2tf32(ini[g]));
        }
    } else {
        for (int i = tid; i < 8192; i += 256) {
            int p = i >> 6, d = i & 63;             // coalesced along d
            int g = (pos0 + p)*64 + d;
            s_xr[p*XTS + d] = __uint_as_float(f2tf32(inr[g]));
            s_xi[p*XTS + d] = __uint_as_float(f2tf32(ini[g]));
        }
    }
    __syncthreads();
    int wid = tid >> 5, lane = tid & 31;
    int m0  = (wid & 1) << 5;       // e base (64 total -> 2 warp tiles)
    int n0  = (wid >> 1) << 5;      // pos base (128 total -> 4 warp tiles)
    int grp = lane >> 2, thr = lane & 3;
    float cre[2][4][4] = {}, cim[2][4][4] = {};
    #pragma unroll
    for (int k0 = 0; k0 < 64; k0 += 8) {
        unsigned aer[2][4], pei[2][4], nei[2][4], bxr[4][2], bxi[4][2];
        #pragma unroll
        for (int ms = 0; ms < 2; ++ms) {
            const float* be = s_er + (m0 + ms*16 + grp)*XTS + k0 + thr;
            aer[ms][0] = __float_as_uint(be[0]);
            aer[ms][1] = __float_as_uint(be[8*XTS]);
            aer[ms][2] = __float_as_uint(be[4]);
            aer[ms][3] = __float_as_uint(be[8*XTS + 4]);
            const float* bi = s_ei + (m0 + ms*16 + grp)*XTS + k0 + thr;
            pei[ms][0] = __float_as_uint(bi[0]);
            pei[ms][1] = __float_as_uint(bi[8*XTS]);
            pei[ms][2] = __float_as_uint(bi[4]);
            pei[ms][3] = __float_as_uint(bi[8*XTS + 4]);
            #pragma unroll
            for (int j = 0; j < 4; ++j) nei[ms][j] = pei[ms][j] ^ 0x80000000u;
        }
        #pragma unroll
        for (int ns = 0; ns < 4; ++ns) {
            const float* br = s_xr + (n0 + ns*8 + grp)*XTS + k0 + thr;
            bxr[ns][0] = __float_as_uint(br[0]);
            bxr[ns][1] = __float_as_uint(br[4]);
            const float* bim = s_xi + (n0 + ns*8 + grp)*XTS + k0 + thr;
            bxi[ns][0] = __float_as_uint(bim[0]);
            bxi[ns][1] = __float_as_uint(bim[4]);
        }
        #pragma unroll
        for (int ms = 0; ms < 2; ++ms)
            #pragma unroll
            for (int ns = 0; ns < 4; ++ns) {
                MMA_TF32(cre[ms][ns][0], cre[ms][ns][1], cre[ms][ns][2], cre[ms][ns][3],
                         aer[ms][0], aer[ms][1], aer[ms][2], aer[ms][3],
                         bxr[ns][0], bxr[ns][1]);
                MMA_TF32(cre[ms][ns][0], cre[ms][ns][1], cre[ms][ns][2], cre[ms][ns][3],
                         nei[ms][0], nei[ms][1], nei[ms][2], nei[ms][3],
                         bxi[ns][0], bxi[ns][1]);
                MMA_TF32(cim[ms][ns][0], cim[ms][ns][1], cim[ms][ns][2], cim[ms][ns][3],
                         aer[ms][0], aer[ms][1], aer[ms][2], aer[ms][3],
                         bxi[ns][0], bxi[ns][1]);
                MMA_TF32(cim[ms][ns][0], cim[ms][ns][1], cim[ms][ns][2], cim[ms][ns][3],
                         pei[ms][0], pei[ms][1], pei[ms][2], pei[ms][3],
                         bxr[ns][0], bxr[ns][1]);
            }
    }
    if (dmajor) {
        // (pos,e) output: transpose through smem (reuse s_xr region; [128][66])
        float* sbuf = s_xr;
        #pragma unroll
        for (int pass = 0; pass < 2; ++pass) {
            float (*cc)[4][4] = pass ? cim : cre;
            float* dst = pass ? outi : outr;
            __syncthreads();
            #pragma unroll
            for (int ms = 0; ms < 2; ++ms)
                #pragma unroll
                for (int ns = 0; ns < 4; ++ns) {
                    int e  = m0 + ms*16 + grp;
                    int np = n0 + ns*8 + thr*2;
                    sbuf[np*66 + e]           = cc[ms][ns][0];
                    sbuf[(np+1)*66 + e]       = cc[ms][ns][1];
                    sbuf[np*66 + e + 8]       = cc[ms][ns][2];
                    sbuf[(np+1)*66 + e + 8]   = cc[ms][ns][3];
                }
            __syncthreads();
            for (int i = tid; i < 8192; i += 256) {
                int p = i >> 6, e = i & 63;
                dst[(pos0 + p)*64 + e] = sbuf[p*66 + e];
            }
        }
    } else {
        // (e,pos) e-major output: direct float2 stores
        #pragma unroll
        for (int ms = 0; ms < 2; ++ms)
            #pragma unroll
            for (int ns = 0; ns < 4; ++ns) {
                int e  = m0 + ms*16 + grp;
                int np = n0 + ns*8 + thr*2;
                *(float2*)(outr + e*NPOS + pos0 + np)       = make_float2(cre[ms][ns][0], cre[ms][ns][1]);
                *(float2*)(outr + (e+8)*NPOS + pos0 + np)   = make_float2(cre[ms][ns][2], cre[ms][ns][3]);
                *(float2*)(outi + e*NPOS + pos0 + np)       = make_float2(cim[ms][ns][0], cim[ms][ns][1]);
                *(float2*)(outi + (e+8)*NPOS + pos0 + np)   = make_float2(cim[ms][ns][2], cim[ms][ns][3]);
            }
    }
}

__global__ void k_egemm1(const float* __restrict__ Er, const float* __restrict__ Ei) {
    egemm_tf32_body(g_xsp_re, g_xsp_im, Er, Ei, g_xeig_re, g_xeig_im, true);
}
__global__ void k_egemm2(const float* __restrict__ Er, const float* __restrict__ Ei) {
    egemm_tf32_body(g_xeig_re, g_xeig_im, Er, Ei, g_z_re, g_z_im, false);
}

// ----------------------------------------------- spatial mean of x_eig
__global__ void k_mean() {
    __shared__ float rr[256], ri[256];
    int bt = blockIdx.x, tid = threadIdx.x;
    int c = tid >> 6, e = tid & 63;
    float sr = 0.f, si = 0.f;
    int base = ((bt*4096 + c*1024)*64) + e;
    for (int i = 0; i < 1024; ++i) {
        sr += g_xeig_re[base + i*64];
        si += g_xeig_im[base + i*64];
    }
    rr[tid] = sr; ri[tid] = si;
    __syncthreads();
    if (c == 0) {
        sr = rr[e] + rr[64+e] + rr[128+e] + rr[192+e];
        si = ri[e] + ri[64+e] + ri[128+e] + ri[192+e];
        g_xmean_re[bt*64 + e] = sr * (1.0f/4096.0f);
        g_xmean_im[bt*64 + e] = si * (1.0f/4096.0f);
    }
}

// ----------------------------------------------- per-d recurrence constants
__global__ void k_consts(const float* __restrict__ dt,
                         const float* __restrict__ lhr, const float* __restrict__ lhi,
                         const float* __restrict__ lfr, const float* __restrict__ lfi) {
    int d = threadIdx.x;
    float t = dt[0];
    {
        float lr = -fabsf(lhr[d]), li = lhi[d];
        float m = expf(lr*t);
        float ar = m*cosf(li*t), ai = m*sinf(li*t);
        float nr = ar - 1.f, ni = ai;
        float den = lr*lr + li*li;
        g_ah_re[d] = ar; g_ah_im[d] = ai;
        g_ch_re[d] = (nr*lr + ni*li)/den;
        g_ch_im[d] = (ni*lr - nr*li)/den;
    }
    {
        float lr = -fabsf(lfr[d]), li = lfi[d];
        float m = expf(lr*t);
        float ar = m*cosf(li*t), ai = m*sinf(li*t);
        float nr = ar - 1.f, ni = ai;
        float den = lr*lr + li*li;
        g_af_re[d] = ar; g_af_im[d] = ai;
        g_cf_re[d] = (nr*lr + ni*li)/den;
        g_cf_im[d] = (ni*lr - nr*li)/den;
    }
}

// ----------------------------------------------- flux scan over T
__global__ void k_flux(const float* __restrict__ fpr, const float* __restrict__ fpi,
                       float* __restrict__ dout) {
    int tid = threadIdx.x;
    int b = tid >> 6, d = tid & 63;
    float ar = g_af_re[d], ai = g_af_im[d];
    float cr = g_cf_re[d], ci = g_cf_im[d];
    float sr = fpr[b*64 + d], si = fpi[b*64 + d];
    #pragma unroll
    for (int t = 0; t < 8; ++t) {
        int idx = (b*8 + t)*64 + d;
        g_ff_re[idx] = sr; g_ff_im[idx] = si;        // forcing = state BEFORE update
        float xr = g_xmean_re[idx], xi = g_xmean_im[idx];
        float ur = xr*cr - xi*ci, ui = xr*ci + xi*cr;
        float nsr = ar*sr - ai*si + ur;
        float nsi = ar*si + ai*sr + ui;
        sr = nsr; si = nsi;
    }
    dout[OUT_OFF_F + b*64 + d]       = sr;
    dout[OUT_OFF_F + 256 + b*64 + d] = si;
}

// ----------------------------------------------- source / gate
__global__ void k_srcgate(const float* __restrict__ Wsr, const float* __restrict__ Wsi,
                          const float* __restrict__ Wg,  const float* __restrict__ bg) {
    int bt = blockIdx.x;
    int e  = threadIdx.x;
    float sr = 0.f, si = 0.f, ga = 0.f;
    #pragma unroll 8
    for (int d = 0; d < 64; ++d) {
        float fr = g_ff_re[bt*64 + d], fi = g_ff_im[bt*64 + d];
        float wr = Wsr[d*64 + e], wi = Wsi[d*64 + e];
        sr += fr*wr - fi*wi;
        si += fr*wi + fi*wr;
        ga += fr*Wg[d*64 + e];
    }
    g_src_re[bt*64 + e] = sr;
    g_src_im[bt*64 + e] = si;
    g_gate[bt*64 + e]   = 1.f/(1.f + expf(-(ga + bg[e])));
}

// ----------------------------------------------- main recurrence (in-place), h_out
__global__ void k_rec(const float* __restrict__ hpr, const float* __restrict__ hpi,
                      float* __restrict__ dout) {
    int bid = blockIdx.x;            // b*4096 + hw
    int b = bid >> 12;
    int d = threadIdx.x;
    float ar = g_ah_re[d], ai = g_ah_im[d];
    float cr = g_ch_re[d], ci = g_ch_im[d];
    float yr = hpr[bid*64 + d], yi = hpi[bid*64 + d];
    int hw = bid & 4095;
    #pragma unroll
    for (int t = 0; t < 8; ++t) {
        int bt  = b*8 + t;
        int idx = (bt*4096 + hw)*64 + d;
        float xr = g_xeig_re[idx], xi = g_xeig_im[idx];
        float g  = g_gate[bt*64 + d];
        float sr = g_src_re[bt*64 + d], si = g_src_im[bt*64 + d];
        float fr = xr*g + sr*(1.f - g);
        float fi = xi*g + si*(1.f - g);
        float ur = fr*cr - fi*ci, ui = fr*ci + fi*cr;
        float nyr = ar*yr - ai*yi + ur;
        float nyi = ar*yi + ai*yr + ui;
        yr = nyr; yi = nyi;
        g_xeig_re[idx] = yr;
        g_xeig_im[idx] = yi;
    }
    dout[OUT_OFF_H + bid*64 + d]           = yr;
    dout[OUT_OFF_H + 1048576 + bid*64 + d] = yi;
}

// ----------------------------------------------- FFN (tf32 tensor-core)
__device__ __forceinline__ float gelu_f(float x) {
    float x3 = x*x*x;
    return 0.5f*x*(1.f + tanhf(0.7978845608028654f*(x + 0.044715f*x3)));
}

#define ZST 72
#define WST 136
__global__ void k_ffn1(const float* __restrict__ w1, const float* __restrict__ b1) {
    extern __shared__ float sm[];
    float* s_z = sm;                // tf32 bits
    float* s_w = sm + 128*ZST;
    int tid  = threadIdx.x;
    int pos0 = blockIdx.x << 6;
    int hid0 = blockIdx.y << 7;
    for (int i = tid; i < 8192; i += 256) {
        int k = i >> 6, p = i & 63;
        const float* src = (k < 64) ? (g_z_re + k*NPOS) : (g_z_im + (k - 64)*NPOS);
        s_z[k*ZST + p] = __uint_as_float(f2tf32(src[pos0 + p]));
    }
    for (int i = tid; i < 16384; i += 256) {
        int k = i >> 7, h = i & 127;
        s_w[k*WST + h] = __uint_as_float(f2tf32(w1[k*512 + hid0 + h]));
    }
    __syncthreads();
    int wid = tid >> 5, lane = tid & 31;
    int m0 = (wid & 3) << 5, n0 = (wid >> 2) << 5;
    int grp = lane >> 2, thr = lane & 3;
    float c[2][4][4] = {};
    #pragma unroll 2
    for (int k0 = 0; k0 < 128; k0 += 8) {
        unsigned a[2][4], b[4][2];
        #pragma unroll
        for (int ms = 0; ms < 2; ++ms) {
            const float* ba = s_w + (k0 + thr)*WST + m0 + ms*16 + grp;
            a[ms][0] = __float_as_uint(ba[0]);
            a[ms][1] = __float_as_uint(ba[8]);
            a[ms][2] = __float_as_uint(ba[4*WST]);
            a[ms][3] = __float_as_uint(ba[4*WST + 8]);
        }
        #pragma unroll
        for (int ns = 0; ns < 4; ++ns) {
            const float* bb = s_z + (k0 + thr)*ZST + n0 + ns*8 + grp;
            b[ns][0] = __float_as_uint(bb[0]);
            b[ns][1] = __float_as_uint(bb[4*ZST]);
        }
        #pragma unroll
        for (int ms = 0; ms < 2; ++ms)
            #pragma unroll
            for (int ns = 0; ns < 4; ++ns)
                MMA_TF32(c[ms][ns][0], c[ms][ns][1], c[ms][ns][2], c[ms][ns][3],
                         a[ms][0], a[ms][1], a[ms][2], a[ms][3],
                         b[ns][0], b[ns][1]);
    }
    #pragma unroll
    for (int ms = 0; ms < 2; ++ms) {
        int hidA = hid0 + m0 + ms*16 + grp;     // rows grp, grp+8
        float bA = b1[hidA], bB = b1[hidA + 8];
        #pragma unroll
        for (int ns = 0; ns < 4; ++ns) {
            int p = pos0 + n0 + ns*8 + thr*2;
            float2 r0 = make_float2(gelu_f(c[ms][ns][0] + bA), gelu_f(c[ms][ns][1] + bA));
            float2 r1 = make_float2(gelu_f(c[ms][ns][2] + bB), gelu_f(c[ms][ns][3] + bB));
            *(float2*)(g_hdn + hidA*NPOS + p)       = r0;
            *(float2*)(g_hdn + (hidA + 8)*NPOS + p) = r1;
        }
    }
}

__global__ void k_ffn2(const float* __restrict__ w2g, const float* __restrict__ b2,
                       float* __restrict__ dout) {
    extern __shared__ float sm[];
    float* s_h  = sm;                       // [64][72] tf32
    float* s_w  = sm + 64*ZST;              // [64][136] tf32
    float* s_zr = sm + 64*ZST + 64*WST;     // [64][72] fp32 residual
    float* s_zi = s_zr + 64*ZST;
    int tid  = threadIdx.x;
    int pos0 = blockIdx.x << 6;
    for (int i = tid; i < 4096; i += 256) {
        int d = i >> 6, p = i & 63;
        s_zr[d*ZST + p] = g_z_re[d*NPOS + pos0 + p];
        s_zi[d*ZST + p] = g_z_im[d*NPOS + pos0 + p];
    }
    int wid = tid >> 5, lane = tid & 31;
    int m0 = (wid & 3) << 5, n0 = (wid >> 2) << 5;
    int grp = lane >> 2, thr = lane & 3;
    float c[2][4][4] = {};
    for (int kc = 0; kc < 8; ++kc) {
        int kk = kc << 6;
        __syncthreads();
        for (int i = tid; i < 4096; i += 256) {
            int k = i >> 6, p = i & 63;
            s_h[k*ZST + p] = __uint_as_float(f2tf32(g_hdn[(kk + k)*NPOS + pos0 + p]));
        }
        for (int i = tid; i < 8192; i += 256) {
            int k = i >> 7, oc = i & 127;
            s_w[k*WST + oc] = __uint_as_float(f2tf32(w2g[(kk + k)*128 + oc]));
        }
        __syncthreads();
        #pragma unroll 2
        for (int ks = 0; ks < 8; ++ks) {
            int k0 = ks << 3;
            unsigned a[2][4], b[4][2];
            #pragma unroll
            for (int ms = 0; ms < 2; ++ms) {
                const float* ba = s_w + (k0 + thr)*WST + m0 + ms*16 + grp;
                a[ms][0] = __float_as_uint(ba[0]);
                a[ms][1] = __float_as_uint(ba[8]);
                a[ms][2] = __float_as_uint(ba[4*WST]);
                a[ms][3] = __float_as_uint(ba[4*WST + 8]);
            }
            #pragma unroll
            for (int ns = 0; ns < 4; ++ns) {
                const float* bb = s_h + (k0 + thr)*ZST + n0 + ns*8 + grp;
                b[ns][0] = __float_as_uint(bb[0]);
                b[ns][1] = __float_as_uint(bb[4*ZST]);
            }
            #pragma unroll
            for (int ms = 0; ms < 2; ++ms)
                #pragma unroll
                for (int ns = 0; ns < 4; ++ns)
                    MMA_TF32(c[ms][ns][0], c[ms][ns][1], c[ms][ns][2], c[ms][ns][3],
                             a[ms][0], a[ms][1], a[ms][2], a[ms][3],
                             b[ns][0], b[ns][1]);
        }
    }
    int bt  = pos0 >> 12;
    int hw0 = pos0 & 4095;
    #pragma unroll
    for (int ms = 0; ms < 2; ++ms) {
        #pragma unroll
        for (int rr = 0; rr < 2; ++rr) {
            int oc = m0 + ms*16 + grp + rr*8;
            int d  = oc & 63;
            bool isim = (oc >= 64);
            float bb = b2[oc];
            #pragma unroll
            for (int ns = 0; ns < 4; ++ns) {
                int np = n0 + ns*8 + thr*2;
                int base = (bt*64 + d)*4096 + hw0 + np;
                float2 zv = *(const float2*)((isim ? s_zi : s_zr) + d*ZST + np);
                const float* xsrc = isim ? g_xsp_im : g_xsp_re;
                float2 xv = *(const float2*)(xsrc + base);
                float cA = c[ms][ns][rr*2 + 0];
                float cB = c[ms][ns][rr*2 + 1];
                float2 r = make_float2(cA + bb + zv.x + xv.x, cB + bb + zv.y + xv.y);
                *(float2*)(dout + (isim ? 8388608 : 0) + base) = r;
            }
        }
    }
}

// ---------------------------------------------------------------- launch
extern "C" void kernel_launch(void* const* d_in, const int* in_sizes, int n_in,
                              void* d_out, int out_size) {
    const float* x_re    = (const float*)d_in[0];
    const float* x_im    = (const float*)d_in[1];
    const float* hp_re   = (const float*)d_in[2];
    const float* hp_im   = (const float*)d_in[3];
    const float* fp_re   = (const float*)d_in[4];
    const float* fp_im   = (const float*)d_in[5];
    const float* dt      = (const float*)d_in[6];
    const float* ln_g    = (const float*)d_in[7];
    const float* ln_b    = (const float*)d_in[8];
    const float* conv_w  = (const float*)d_in[9];
    const float* conv_b  = (const float*)d_in[10];
    const float* metric  = (const float*)d_in[11];
    const float* E_re    = (const float*)d_in[12];
    const float* E_im    = (const float*)d_in[13];
    const float* Ed_re   = (const float*)d_in[14];
    const float* Ed_im   = (const float*)d_in[15];
    const float* lh_re   = (const float*)d_in[16];
    const float* lh_im   = (const float*)d_in[17];
    const float* lf_re   = (const float*)d_in[18];
    const float* lf_im   = (const float*)d_in[19];
    const float* Ws_re   = (const float*)d_in[20];
    const float* Ws_im   = (const float*)d_in[21];
    const float* W_gate  = (const float*)d_in[22];
    const float* b_gate  = (const float*)d_in[23];
    const float* ffn_w1  = (const float*)d_in[24];
    const float* ffn_b1  = (const float*)d_in[25];
    const float* ffn_w2  = (const float*)d_in[26];
    const float* ffn_b2  = (const float*)d_in[27];
    float* out = (float*)d_out;

    // conv: 65536 B; egemm: 110592 B; ffn1: 106496 B; ffn2: 90112 B
    cudaFuncSetAttribute(k_conv,   cudaFuncAttributeMaxDynamicSharedMemorySize, 65536);
    cudaFuncSetAttribute(k_egemm1, cudaFuncAttributeMaxDynamicSharedMemorySize, 110592);
    cudaFuncSetAttribute(k_egemm2, cudaFuncAttributeMaxDynamicSharedMemorySize, 110592);
    cudaFuncSetAttribute(k_ffn1,   cudaFuncAttributeMaxDynamicSharedMemorySize, 106496);
    cudaFuncSetAttribute(k_ffn2,   cudaFuncAttributeMaxDynamicSharedMemorySize, 90112);

    k_ln<<<4096, 128>>>(x_re, x_im, ln_g, ln_b);
    k_wt<<<576, 256>>>(conv_w);
    k_conv<<<dim3(64, 32), 256, 65536>>>(x_re, x_im, conv_b, metric);
    k_egemm1<<<1024, 256, 110592>>>(E_re, E_im);
    k_mean<<<32, 256>>>();
    k_consts<<<1, 64>>>(dt, lh_re, lh_im, lf_re, lf_im);
    k_flux<<<1, 256>>>(fp_re, fp_im, out);
    k_srcgate<<<32, 64>>>(Ws_re, Ws_im, W_gate, b_gate);
    k_rec<<<16384, 64>>>(hp_re, hp_im, out);
    k_egemm2<<<1024, 256, 110592>>>(Ed_re, Ed_im);
    k_ffn1<<<dim3(2048, 4), 256, 106496>>>(ffn_w1, ffn_b1);
    k_ffn2<<<2048, 256, 90112>>>(ffn_w2, ffn_b2, out);
}

// round 14
// speedup vs baseline: 1.8303x; 1.0477x over previous
#include <cuda_runtime.h>
#include <math.h>

#define BB 4
#define TT 8
#define BT 32
#define DD 64
#define CC 128
#define HH 64
#define WW 64
#define HW 4096
#define NPOS 131072          // BT*HW
#define HID 512
#define OUT_OFF_H 16777216   // 2*B*T*D*H*W
#define OUT_OFF_F 18874368   // + 2*B*H*W*D

// ---------------- scratch (device globals; no allocations allowed) ----------
__device__ float g_xn[BT*CC*HW];          // LN output, (bt,ch,h,w)
__device__ float g_wT[CC*9*CC];           // conv weights transposed (tf32 bits): (ic,tap,oc)
__device__ float g_xsp_re[NPOS*DD];       // (bt,d,hw)  d-major
__device__ float g_xsp_im[NPOS*DD];
__device__ float g_xeig_re[NPOS*DD];      // (pos,e) pos-major; reused as y in-place
__device__ float g_xeig_im[NPOS*DD];
__device__ float g_z_re[NPOS*DD];         // (e,pos) e-major
__device__ float g_z_im[NPOS*DD];
__device__ float g_xmean_re[BT*DD], g_xmean_im[BT*DD];
__device__ float g_ff_re[BT*DD],    g_ff_im[BT*DD];      // flux forcing
__device__ float g_src_re[BT*DD],   g_src_im[BT*DD];
__device__ float g_gate[BT*DD];
__device__ float g_ah_re[DD], g_ah_im[DD], g_ch_re[DD], g_ch_im[DD];
__device__ float g_af_re[DD], g_af_im[DD], g_cf_re[DD], g_cf_im[DD];

__device__ __forceinline__ unsigned f2tf32(float v) {
    unsigned u;
    asm("cvt.rna.tf32.f32 %0, %1;" : "=r"(u) : "f"(v));
    return u;
}

#define MMA_TF32(c0,c1,c2,c3,a0,a1,a2,a3,b0,b1) \
    asm("mma.sync.aligned.m16n8k8.row.col.f32.tf32.tf32.f32 " \
        "{%0,%1,%2,%3}, {%4,%5,%6,%7}, {%8,%9}, {%0,%1,%2,%3};" \
        : "+f"(c0), "+f"(c1), "+f"(c2), "+f"(c3) \
        : "r"(a0), "r"(a1), "r"(a2), "r"(a3), "r"(b0), "r"(b1))

// ---------------------------------------------------------------- LayerNorm
__global__ void k_ln(const float* __restrict__ xre, const float* __restrict__ xim,
                     const float* __restrict__ gamma, const float* __restrict__ beta) {
    __shared__ float s[32*129];
    __shared__ float smu[32], srs[32];
    int bid = blockIdx.x;
    int bt  = bid >> 7;
    int rem = bid & 127;
    int h   = rem >> 1;
    int w0  = (rem & 1) << 5;
    int tid = threadIdx.x;
    for (int i = tid; i < 4096; i += 128) {
        int ch = i >> 5, p = i & 31;
        int d  = ch & 63;
        const float* src = (ch < 64) ? xre : xim;
        s[p*129 + ch] = src[((bt*64 + d)*64 + h)*64 + w0 + p];
    }
    __syncthreads();
    if (tid < 32) {
        float sum = 0.f, ss = 0.f;
        #pragma unroll 8
        for (int ch = 0; ch < 128; ++ch) { float v = s[tid*129 + ch]; sum += v; ss += v*v; }
        float mu  = sum * (1.0f/128.0f);
        float var = ss * (1.0f/128.0f) - mu*mu;
        smu[tid] = mu;
        srs[tid] = rsqrtf(var + 1e-5f);
    }
    __syncthreads();
    for (int i = tid; i < 4096; i += 128) {
        int ch = i >> 5, p = i & 31;
        float v = (s[p*129 + ch] - smu[p]) * srs[p] * gamma[ch] + beta[ch];
        g_xn[((bt*128 + ch)*64 + h)*64 + w0 + p] = v;
    }
}

// ------------------------------------------------- conv weight transpose (to tf32 bits)
__global__ void k_wt(const float* __restrict__ cw) {
    int idx = blockIdx.x * 256 + threadIdx.x;   // 147456 total
    int oc = idx / 1152;
    int r  = idx - oc * 1152;                   // ic*9 + tap
    g_wT[r * 128 + oc] = __uint_as_float(f2tf32(cw[idx]));
}

// -------------------- conv 3x3 SAME via tf32 implicit GEMM + bias + metric + residual
#define HST 120
#define CWST 136
__global__ void k_conv(const float* __restrict__ xre, const float* __restrict__ xim,
                       const float* __restrict__ cb, const float* __restrict__ metric) {
    extern __shared__ float sm[];
    float* s_halo = sm;             // tf32 bits
    float* s_w    = sm + 64*HST;    // tf32 bits
    int bt   = blockIdx.y;
    int tile = blockIdx.x;
    int ty0  = (tile >> 3) << 3;
    int tx0  = (tile & 7) << 3;
    int tid  = threadIdx.x;
    int wid  = tid >> 5, lane = tid & 31;
    int m0   = (wid & 3) << 5;      // oc base of warp tile
    int n0   = (wid >> 2) << 5;     // pos base of warp tile
    int grp  = lane >> 2, thr = lane & 3;
    float c[2][4][4] = {};

    for (int cc = 0; cc < 2; ++cc) {
        int ic0 = cc << 6;
        __syncthreads();
        for (int i = tid; i < 7680; i += 256) {
            int ic = i / HST; int r = i - ic*HST;
            int yy = r / 12,  xx = r - yy*12;
            int gy = ty0 + yy - 1, gx = tx0 + xx - 1;
            float v = 0.f;
            if (xx < 10 && gy >= 0 && gy < 64 && gx >= 0 && gx < 64)
                v = g_xn[(bt*128 + ic0 + ic)*4096 + gy*64 + gx];
            s_halo[ic*HST + yy*12 + xx] = __uint_as_float(f2tf32(v));
        }
        for (int tap = 0; tap < 9; ++tap) {
            __syncthreads();
            for (int i = tid; i < 8192; i += 256) {
                int k = i >> 7, oc = i & 127;
                s_w[k*CWST + oc] = g_wT[((ic0 + k)*9 + tap)*128 + oc];
            }
            __syncthreads();
            int ky = tap / 3, kx = tap - ky*3;
            #pragma unroll 2
            for (int ks = 0; ks < 8; ++ks) {
                int k0 = ks << 3;
                unsigned a[2][4], b[4][2];
                #pragma unroll
                for (int ms = 0; ms < 2; ++ms) {
                    const float* ba = s_w + (k0 + thr)*CWST + m0 + ms*16 + grp;
                    a[ms][0] = __float_as_uint(ba[0]);
                    a[ms][1] = __float_as_uint(ba[8]);
                    a[ms][2] = __float_as_uint(ba[4*CWST]);
                    a[ms][3] = __float_as_uint(ba[4*CWST + 8]);
                }
                #pragma unroll
                for (int ns = 0; ns < 4; ++ns) {
                    int p  = n0 + ns*8 + grp;
                    int off = ((p >> 3) + ky)*12 + (p & 7) + kx;
                    b[ns][0] = __float_as_uint(s_halo[(k0 + thr)*HST + off]);
                    b[ns][1] = __float_as_uint(s_halo[(k0 + thr + 4)*HST + off]);
                }
                #pragma unroll
                for (int ms = 0; ms < 2; ++ms)
                    #pragma unroll
                    for (int ns = 0; ns < 4; ++ns)
                        MMA_TF32(c[ms][ns][0], c[ms][ns][1], c[ms][ns][2], c[ms][ns][3],
                                 a[ms][0], a[ms][1], a[ms][2], a[ms][3],
                                 b[ns][0], b[ns][1]);
            }
        }
    }
    #pragma unroll
    for (int ms = 0; ms < 2; ++ms) {
        #pragma unroll
        for (int rr = 0; rr < 2; ++rr) {
            int oc = m0 + ms*16 + grp + rr*8;
            int d  = oc & 63;
            bool isim = (oc >= 64);
            float bias = cb[oc];
            #pragma unroll
            for (int ns = 0; ns < 4; ++ns) {
                int p  = n0 + ns*8 + thr*2;
                int h  = ty0 + (p >> 3);
                int w  = tx0 + (p & 7);
                int base = ((bt*64 + d)*64 + h)*64 + w;
                float2 mv = *(const float2*)&metric[h*64 + w];
                const float* xin = isim ? xim : xre;
                float2 xv = *(const float2*)&xin[base];
                float cA = c[ms][ns][rr*2 + 0];
                float cB = c[ms][ns][rr*2 + 1];
                float2 r = make_float2(xv.x + (cA + bias)*mv.x,
                                       xv.y + (cB + bias)*mv.y);
                if (!isim) *(float2*)&g_xsp_re[base] = r;
                else       *(float2*)&g_xsp_im[base] = r;
            }
        }
    }
}

// --------------------------- complex 64x64 GEMM via tf32 mma (E / Edec)
#define XTS 72
__device__ __forceinline__ void egemm_tf32_body(
    const float* __restrict__ inr, const float* __restrict__ ini,
    const float* __restrict__ Er,  const float* __restrict__ Ei,
    float* __restrict__ outr, float* __restrict__ outi, bool dmajor)
{
    extern __shared__ float sm[];
    float* s_er = sm;                   // [64][XTS]
    float* s_ei = sm + 64*XTS;
    float* s_xr = sm + 2*64*XTS;        // [128][XTS]
    float* s_xi = sm + 2*64*XTS + 128*XTS;
    int tid  = threadIdx.x;
    int pos0 = blockIdx.x << 7;
    int bt   = pos0 >> 12;
    int hw0  = pos0 & 4095;
    for (int i = tid; i < 4096; i += 256) {
        int d = i >> 6, e = i & 63;
        s_er[e*XTS + d] = __uint_as_float(f2tf32(Er[i]));
        s_ei[e*XTS + d] = __uint_as_float(f2tf32(Ei[i]));
    }
    if (dmajor) {
        for (int i = tid; i < 8192; i += 256) {
            int d = i >> 7, p = i & 127;
            int g = (bt*64 + d)*4096 + hw0 + p;
            s_xr[p*XTS + d] = __uint_as_float(f2tf32(inr[g]));
            s_xi[p*XTS + d] = __uint_as_float(f2tf32(ini[g]));
        }
    } else {
        for (int i = tid; i < 8192; i += 256) {
            int p = i >> 6, d = i & 63;
            int g = (pos0 + p)*64 + d;
            s_xr[p*XTS + d] = __uint_as_float(f2tf32(inr[g]));
            s_xi[p*XTS + d] = __uint_as_float(f2tf32(ini[g]));
        }
    }
    __syncthreads();
    int wid = tid >> 5, lane = tid & 31;
    int m0  = (wid & 1) << 5;
    int n0  = (wid >> 1) << 5;
    int grp = lane >> 2, thr = lane & 3;
    float cre[2][4][4] = {}, cim[2][4][4] = {};
    #pragma unroll
    for (int k0 = 0; k0 < 64; k0 += 8) {
        unsigned aer[2][4], pei[2][4], nei[2][4], bxr[4][2], bxi[4][2];
        #pragma unroll
        for (int ms = 0; ms < 2; ++ms) {
            const float* be = s_er + (m0 + ms*16 + grp)*XTS + k0 + thr;
            aer[ms][0] = __float_as_uint(be[0]);
            aer[ms][1] = __float_as_uint(be[8*XTS]);
            aer[ms][2] = __float_as_uint(be[4]);
            aer[ms][3] = __float_as_uint(be[8*XTS + 4]);
            const float* bi = s_ei + (m0 + ms*16 + grp)*XTS + k0 + thr;
            pei[ms][0] = __float_as_uint(bi[0]);
            pei[ms][1] = __float_as_uint(bi[8*XTS]);
            pei[ms][2] = __float_as_uint(bi[4]);
            pei[ms][3] = __float_as_uint(bi[8*XTS + 4]);
            #pragma unroll
            for (int j = 0; j < 4; ++j) nei[ms][j] = pei[ms][j] ^ 0x80000000u;
        }
        #pragma unroll
        for (int ns = 0; ns < 4; ++ns) {
            const float* br = s_xr + (n0 + ns*8 + grp)*XTS + k0 + thr;
            bxr[ns][0] = __float_as_uint(br[0]);
            bxr[ns][1] = __float_as_uint(br[4]);
            const float* bim = s_xi + (n0 + ns*8 + grp)*XTS + k0 + thr;
            bxi[ns][0] = __float_as_uint(bim[0]);
            bxi[ns][1] = __float_as_uint(bim[4]);
        }
        #pragma unroll
        for (int ms = 0; ms < 2; ++ms)
            #pragma unroll
            for (int ns = 0; ns < 4; ++ns) {
                MMA_TF32(cre[ms][ns][0], cre[ms][ns][1], cre[ms][ns][2], cre[ms][ns][3],
                         aer[ms][0], aer[ms][1], aer[ms][2], aer[ms][3],
                         bxr[ns][0], bxr[ns][1]);
                MMA_TF32(cre[ms][ns][0], cre[ms][ns][1], cre[ms][ns][2], cre[ms][ns][3],
                         nei[ms][0], nei[ms][1], nei[ms][2], nei[ms][3],
                         bxi[ns][0], bxi[ns][1]);
                MMA_TF32(cim[ms][ns][0], cim[ms][ns][1], cim[ms][ns][2], cim[ms][ns][3],
                         aer[ms][0], aer[ms][1], aer[ms][2], aer[ms][3],
                         bxi[ns][0], bxi[ns][1]);
                MMA_TF32(cim[ms][ns][0], cim[ms][ns][1], cim[ms][ns][2], cim[ms][ns][3],
                         pei[ms][0], pei[ms][1], pei[ms][2], pei[ms][3],
                         bxr[ns][0], bxr[ns][1]);
            }
    }
    if (dmajor) {
        float* sbuf = s_xr;
        #pragma unroll
        for (int pass = 0; pass < 2; ++pass) {
            float (*cc)[4][4] = pass ? cim : cre;
            float* dst = pass ? outi : outr;
            __syncthreads();
            #pragma unroll
            for (int ms = 0; ms < 2; ++ms)
                #pragma unroll
                for (int ns = 0; ns < 4; ++ns) {
                    int e  = m0 + ms*16 + grp;
                    int np = n0 + ns*8 + thr*2;
                    sbuf[np*66 + e]           = cc[ms][ns][0];
                    sbuf[(np+1)*66 + e]       = cc[ms][ns][1];
                    sbuf[np*66 + e + 8]       = cc[ms][ns][2];
                    sbuf[(np+1)*66 + e + 8]   = cc[ms][ns][3];
                }
            __syncthreads();
            for (int i = tid; i < 8192; i += 256) {
                int p = i >> 6, e = i & 63;
                dst[(pos0 + p)*64 + e] = sbuf[p*66 + e];
            }
        }
    } else {
        #pragma unroll
        for (int ms = 0; ms < 2; ++ms)
            #pragma unroll
            for (int ns = 0; ns < 4; ++ns) {
                int e  = m0 + ms*16 + grp;
                int np = n0 + ns*8 + thr*2;
                *(float2*)(outr + e*NPOS + pos0 + np)       = make_float2(cre[ms][ns][0], cre[ms][ns][1]);
                *(float2*)(outr + (e+8)*NPOS + pos0 + np)   = make_float2(cre[ms][ns][2], cre[ms][ns][3]);
                *(float2*)(outi + e*NPOS + pos0 + np)       = make_float2(cim[ms][ns][0], cim[ms][ns][1]);
                *(float2*)(outi + (e+8)*NPOS + pos0 + np)   = make_float2(cim[ms][ns][2], cim[ms][ns][3]);
            }
    }
}

__global__ void k_egemm1(const float* __restrict__ Er, const float* __restrict__ Ei) {
    egemm_tf32_body(g_xsp_re, g_xsp_im, Er, Ei, g_xeig_re, g_xeig_im, true);
}
__global__ void k_egemm2(const float* __restrict__ Er, const float* __restrict__ Ei) {
    egemm_tf32_body(g_xeig_re, g_xeig_im, Er, Ei, g_z_re, g_z_im, false);
}

// ----------------------------------------------- spatial mean of x_eig
__global__ void k_mean() {
    __shared__ float rr[256], ri[256];
    int bt = blockIdx.x, tid = threadIdx.x;
    int c = tid >> 6, e = tid & 63;
    float sr = 0.f, si = 0.f;
    int base = ((bt*4096 + c*1024)*64) + e;
    for (int i = 0; i < 1024; ++i) {
        sr += g_xeig_re[base + i*64];
        si += g_xeig_im[base + i*64];
    }
    rr[tid] = sr; ri[tid] = si;
    __syncthreads();
    if (c == 0) {
        sr = rr[e] + rr[64+e] + rr[128+e] + rr[192+e];
        si = ri[e] + ri[64+e] + ri[128+e] + ri[192+e];
        g_xmean_re[bt*64 + e] = sr * (1.0f/4096.0f);
        g_xmean_im[bt*64 + e] = si * (1.0f/4096.0f);
    }
}

// ----------------------------------------------- per-d recurrence constants
__global__ void k_consts(const float* __restrict__ dt,
                         const float* __restrict__ lhr, const float* __restrict__ lhi,
                         const float* __restrict__ lfr, const float* __restrict__ lfi) {
    int d = threadIdx.x;
    float t = dt[0];
    {
        float lr = -fabsf(lhr[d]), li = lhi[d];
        float m = expf(lr*t);
        float ar = m*cosf(li*t), ai = m*sinf(li*t);
        float nr = ar - 1.f, ni = ai;
        float den = lr*lr + li*li;
        g_ah_re[d] = ar; g_ah_im[d] = ai;
        g_ch_re[d] = (nr*lr + ni*li)/den;
        g_ch_im[d] = (ni*lr - nr*li)/den;
    }
    {
        float lr = -fabsf(lfr[d]), li = lfi[d];
        float m = expf(lr*t);
        float ar = m*cosf(li*t), ai = m*sinf(li*t);
        float nr = ar - 1.f, ni = ai;
        float den = lr*lr + li*li;
        g_af_re[d] = ar; g_af_im[d] = ai;
        g_cf_re[d] = (nr*lr + ni*li)/den;
        g_cf_im[d] = (ni*lr - nr*li)/den;
    }
}

// ----------------------------------------------- flux scan over T
__global__ void k_flux(const float* __restrict__ fpr, const float* __restrict__ fpi,
                       float* __restrict__ dout) {
    int tid = threadIdx.x;
    int b = tid >> 6, d = tid & 63;
    float ar = g_af_re[d], ai = g_af_im[d];
    float cr = g_cf_re[d], ci = g_cf_im[d];
    float sr = fpr[b*64 + d], si = fpi[b*64 + d];
    #pragma unroll
    for (int t = 0; t < 8; ++t) {
        int idx = (b*8 + t)*64 + d;
        g_ff_re[idx] = sr; g_ff_im[idx] = si;
        float xr = g_xmean_re[idx], xi = g_xmean_im[idx];
        float ur = xr*cr - xi*ci, ui = xr*ci + xi*cr;
        float nsr = ar*sr - ai*si + ur;
        float nsi = ar*si + ai*sr + ui;
        sr = nsr; si = nsi;
    }
    dout[OUT_OFF_F + b*64 + d]       = sr;
    dout[OUT_OFF_F + 256 + b*64 + d] = si;
}

// ----------------------------------------------- source / gate
__global__ void k_srcgate(const float* __restrict__ Wsr, const float* __restrict__ Wsi,
                          const float* __restrict__ Wg,  const float* __restrict__ bg) {
    int bt = blockIdx.x;
    int e  = threadIdx.x;
    float sr = 0.f, si = 0.f, ga = 0.f;
    #pragma unroll 8
    for (int d = 0; d < 64; ++d) {
        float fr = g_ff_re[bt*64 + d], fi = g_ff_im[bt*64 + d];
        float wr = Wsr[d*64 + e], wi = Wsi[d*64 + e];
        sr += fr*wr - fi*wi;
        si += fr*wi + fi*wr;
        ga += fr*Wg[d*64 + e];
    }
    g_src_re[bt*64 + e] = sr;
    g_src_im[bt*64 + e] = si;
    g_gate[bt*64 + e]   = 1.f/(1.f + expf(-(ga + bg[e])));
}

// ----------------------------------------------- main recurrence (in-place), h_out
__global__ void k_rec(const float* __restrict__ hpr, const float* __restrict__ hpi,
                      float* __restrict__ dout) {
    int bid = blockIdx.x;
    int b = bid >> 12;
    int d = threadIdx.x;
    float ar = g_ah_re[d], ai = g_ah_im[d];
    float cr = g_ch_re[d], ci = g_ch_im[d];
    float yr = hpr[bid*64 + d], yi = hpi[bid*64 + d];
    int hw = bid & 4095;
    #pragma unroll
    for (int t = 0; t < 8; ++t) {
        int bt  = b*8 + t;
        int idx = (bt*4096 + hw)*64 + d;
        float xr = g_xeig_re[idx], xi = g_xeig_im[idx];
        float g  = g_gate[bt*64 + d];
        float sr = g_src_re[bt*64 + d], si = g_src_im[bt*64 + d];
        float fr = xr*g + sr*(1.f - g);
        float fi = xi*g + si*(1.f - g);
        float ur = fr*cr - fi*ci, ui = fr*ci + fi*cr;
        float nyr = ar*yr - ai*yi + ur;
        float nyi = ar*yi + ai*yr + ui;
        yr = nyr; yi = nyi;
        g_xeig_re[idx] = yr;
        g_xeig_im[idx] = yi;
    }
    dout[OUT_OFF_H + bid*64 + d]           = yr;
    dout[OUT_OFF_H + 1048576 + bid*64 + d] = yi;
}

// ----------------------------------------------- fused FFN (tf32 tensor-core)
__device__ __forceinline__ float gelu_f(float x) {
    float x3 = x*x*x;
    return 0.5f*x*(1.f + tanhf(0.7978845608028654f*(x + 0.044715f*x3)));
}

// One block = 64 positions, full K=128 -> HID=512 -> 128 FFN chain in smem.
// smem floats: s_z[128][72]=9216, s_h[128][72]=9216, s_zr/s_zi[64][72]=4608 x2,
//              s_w[128][136]=17408  -> total 45056 floats = 180224 bytes
#define ZST 72
#define WST 136
__global__ void k_ffn(const float* __restrict__ w1, const float* __restrict__ b1,
                      const float* __restrict__ w2g, const float* __restrict__ b2,
                      float* __restrict__ dout) {
    extern __shared__ float sm[];
    float* s_z  = sm;                   // [128 k][72] tf32
    float* s_h  = sm + 9216;            // [128 hid][72] tf32
    float* s_zr = sm + 18432;           // [64 d][72] fp32 residual
    float* s_zi = sm + 23040;
    float* s_w  = sm + 27648;           // [128 k][136] tf32 (W1 chunk / W2 chunk)
    int tid  = threadIdx.x;
    int pos0 = blockIdx.x << 6;
    // stage z: tf32 for gemm + fp32 for residual
    for (int i = tid; i < 8192; i += 256) {
        int k = i >> 6, p = i & 63;
        if (k < 64) {
            float v = g_z_re[k*NPOS + pos0 + p];
            s_zr[k*ZST + p] = v;
            s_z[k*ZST + p] = __uint_as_float(f2tf32(v));
        } else {
            float v = g_z_im[(k - 64)*NPOS + pos0 + p];
            s_zi[(k - 64)*ZST + p] = v;
            s_z[k*ZST + p] = __uint_as_float(f2tf32(v));
        }
    }
    int wid = tid >> 5, lane = tid & 31;
    int m0 = (wid & 3) << 5, n0 = (wid >> 2) << 5;
    int grp = lane >> 2, thr = lane & 3;
    float co[2][4][4] = {};

    for (int hc = 0; hc < 4; ++hc) {
        __syncthreads();                 // prev gemm2 done with s_w/s_h; z staged (hc=0)
        // stage W1 chunk: [k 128][hid 128]
        for (int i = tid; i < 16384; i += 256) {
            int k = i >> 7, h = i & 127;
            s_w[k*WST + h] = __uint_as_float(f2tf32(w1[k*512 + hc*128 + h]));
        }
        __syncthreads();
        // gemm1: ch = W1c^T @ z, M=128 hid, N=64 pos, K=128
        float ch[2][4][4] = {};
        #pragma unroll 2
        for (int k0 = 0; k0 < 128; k0 += 8) {
            unsigned a[2][4], b[4][2];
            #pragma unroll
            for (int ms = 0; ms < 2; ++ms) {
                const float* ba = s_w + (k0 + thr)*WST + m0 + ms*16 + grp;
                a[ms][0] = __float_as_uint(ba[0]);
                a[ms][1] = __float_as_uint(ba[8]);
                a[ms][2] = __float_as_uint(ba[4*WST]);
                a[ms][3] = __float_as_uint(ba[4*WST + 8]);
            }
            #pragma unroll
            for (int ns = 0; ns < 4; ++ns) {
                const float* bb = s_z + (k0 + thr)*ZST + n0 + ns*8 + grp;
                b[ns][0] = __float_as_uint(bb[0]);
                b[ns][1] = __float_as_uint(bb[4*ZST]);
            }
            #pragma unroll
            for (int ms = 0; ms < 2; ++ms)
                #pragma unroll
                for (int ns = 0; ns < 4; ++ns)
                    MMA_TF32(ch[ms][ns][0], ch[ms][ns][1], ch[ms][ns][2], ch[ms][ns][3],
                             a[ms][0], a[ms][1], a[ms][2], a[ms][3],
                             b[ns][0], b[ns][1]);
        }
        // gelu + bias -> s_h (tf32)
        #pragma unroll
        for (int ms = 0; ms < 2; ++ms) {
            #pragma unroll
            for (int rr = 0; rr < 2; ++rr) {
                int hh = m0 + ms*16 + grp + rr*8;
                float bb = b1[hc*128 + hh];
                #pragma unroll
                for (int ns = 0; ns < 4; ++ns) {
                    int p = n0 + ns*8 + thr*2;
                    s_h[hh*ZST + p]     = __uint_as_float(f2tf32(gelu_f(ch[ms][ns][rr*2 + 0] + bb)));
                    s_h[hh*ZST + p + 1] = __uint_as_float(f2tf32(gelu_f(ch[ms][ns][rr*2 + 1] + bb)));
                }
            }
        }
        __syncthreads();                 // s_h complete; gemm1 done with s_w
        // stage W2 chunk: [k 128 (hid)][oc 128]
        for (int i = tid; i < 16384; i += 256) {
            int k = i >> 7, oc = i & 127;
            s_w[k*WST + oc] = __uint_as_float(f2tf32(w2g[(hc*128 + k)*128 + oc]));
        }
        __syncthreads();
        // gemm2: co += W2c^T @ s_h, K=128
        #pragma unroll 2
        for (int k0 = 0; k0 < 128; k0 += 8) {
            unsigned a[2][4], b[4][2];
            #pragma unroll
            for (int ms = 0; ms < 2; ++ms) {
                const float* ba = s_w + (k0 + thr)*WST + m0 + ms*16 + grp;
                a[ms][0] = __float_as_uint(ba[0]);
                a[ms][1] = __float_as_uint(ba[8]);
                a[ms][2] = __float_as_uint(ba[4*WST]);
                a[ms][3] = __float_as_uint(ba[4*WST + 8]);
            }
            #pragma unroll
            for (int ns = 0; ns < 4; ++ns) {
                const float* bb = s_h + (k0 + thr)*ZST + n0 + ns*8 + grp;
                b[ns][0] = __float_as_uint(bb[0]);
                b[ns][1] = __float_as_uint(bb[4*ZST]);
            }
            #pragma unroll
            for (int ms = 0; ms < 2; ++ms)
                #pragma unroll
                for (int ns = 0; ns < 4; ++ns)
                    MMA_TF32(co[ms][ns][0], co[ms][ns][1], co[ms][ns][2], co[ms][ns][3],
                             a[ms][0], a[ms][1], a[ms][2], a[ms][3],
                             b[ns][0], b[ns][1]);
        }
    }
    // epilogue: + b2 + z residual + xsp residual -> dout
    int bt  = pos0 >> 12;
    int hw0 = pos0 & 4095;
    #pragma unroll
    for (int ms = 0; ms < 2; ++ms) {
        #pragma unroll
        for (int rr = 0; rr < 2; ++rr) {
            int oc = m0 + ms*16 + grp + rr*8;
            int d  = oc & 63;
            bool isim = (oc >= 64);
            float bb = b2[oc];
            #pragma unroll
            for (int ns = 0; ns < 4; ++ns) {
                int np = n0 + ns*8 + thr*2;
                int base = (bt*64 + d)*4096 + hw0 + np;
                float2 zv = *(const float2*)((isim ? s_zi : s_zr) + d*ZST + np);
                const float* xsrc = isim ? g_xsp_im : g_xsp_re;
                float2 xv = *(const float2*)(xsrc + base);
                float cA = co[ms][ns][rr*2 + 0];
                float cB = co[ms][ns][rr*2 + 1];
                float2 r = make_float2(cA + bb + zv.x + xv.x, cB + bb + zv.y + xv.y);
                *(float2*)(dout + (isim ? 8388608 : 0) + base) = r;
            }
        }
    }
}

// ---------------------------------------------------------------- launch
extern "C" void kernel_launch(void* const* d_in, const int* in_sizes, int n_in,
                              void* d_out, int out_size) {
    const float* x_re    = (const float*)d_in[0];
    const float* x_im    = (const float*)d_in[1];
    const float* hp_re   = (const float*)d_in[2];
    const float* hp_im   = (const float*)d_in[3];
    const float* fp_re   = (const float*)d_in[4];
    const float* fp_im   = (const float*)d_in[5];
    const float* dt      = (const float*)d_in[6];
    const float* ln_g    = (const float*)d_in[7];
    const float* ln_b    = (const float*)d_in[8];
    const float* conv_w  = (const float*)d_in[9];
    const float* conv_b  = (const float*)d_in[10];
    const float* metric  = (const float*)d_in[11];
    const float* E_re    = (const float*)d_in[12];
    const float* E_im    = (const float*)d_in[13];
    const float* Ed_re   = (const float*)d_in[14];
    const float* Ed_im   = (const float*)d_in[15];
    const float* lh_re   = (const float*)d_in[16];
    const float* lh_im   = (const float*)d_in[17];
    const float* lf_re   = (const float*)d_in[18];
    const float* lf_im   = (const float*)d_in[19];
    const float* Ws_re   = (const float*)d_in[20];
    const float* Ws_im   = (const float*)d_in[21];
    const float* W_gate  = (const float*)d_in[22];
    const float* b_gate  = (const float*)d_in[23];
    const float* ffn_w1  = (const float*)d_in[24];
    const float* ffn_b1  = (const float*)d_in[25];
    const float* ffn_w2  = (const float*)d_in[26];
    const float* ffn_b2  = (const float*)d_in[27];
    float* out = (float*)d_out;

    // conv: 65536 B; egemm: 110592 B; ffn fused: 180224 B
    cudaFuncSetAttribute(k_conv,   cudaFuncAttributeMaxDynamicSharedMemorySize, 65536);
    cudaFuncSetAttribute(k_egemm1, cudaFuncAttributeMaxDynamicSharedMemorySize, 110592);
    cudaFuncSetAttribute(k_egemm2, cudaFuncAttributeMaxDynamicSharedMemorySize, 110592);
    cudaFuncSetAttribute(k_ffn,    cudaFuncAttributeMaxDynamicSharedMemorySize, 180224);

    k_ln<<<4096, 128>>>(x_re, x_im, ln_g, ln_b);
    k_wt<<<576, 256>>>(conv_w);
    k_conv<<<dim3(64, 32), 256, 65536>>>(x_re, x_im, conv_b, metric);
    k_egemm1<<<1024, 256, 110592>>>(E_re, E_im);
    k_mean<<<32, 256>>>();
    k_consts<<<1, 64>>>(dt, lh_re, lh_im, lf_re, lf_im);
    k_flux<<<1, 256>>>(fp_re, fp_im, out);
    k_srcgate<<<32, 64>>>(Ws_re, Ws_im, W_gate, b_gate);
    k_rec<<<16384, 64>>>(hp_re, hp_im, out);
    k_egemm2<<<1024, 256, 110592>>>(Ed_re, Ed_im);
    k_ffn<<<2048, 256, 180224>>>(ffn_w1, ffn_b1, ffn_w2, ffn_b2, out);
}

// round 16
// speedup vs baseline: 1.8489x; 1.0101x over previous
#include <cuda_runtime.h>
#include <math.h>

#define BB 4
#define TT 8
#define BT 32
#define DD 64
#define CC 128
#define HH 64
#define WW 64
#define HW 4096
#define NPOS 131072          // BT*HW
#define HID 512
#define OUT_OFF_H 16777216   // 2*B*T*D*H*W
#define OUT_OFF_F 18874368   // + 2*B*H*W*D

// ---------------- scratch (device globals; no allocations allowed) ----------
__device__ float g_xn[BT*CC*HW];          // LN output, (bt,ch,h,w)
__device__ float g_wT[CC*9*CC];           // conv weights transposed (tf32 bits): (ic,tap,oc)
__device__ float g_xsp_re[NPOS*DD];       // (bt,d,hw)  d-major
__device__ float g_xsp_im[NPOS*DD];
__device__ float g_xeig_re[NPOS*DD];      // (pos,e) pos-major (pre-recurrence)
__device__ float g_xeig_im[NPOS*DD];
__device__ float g_z_re[NPOS*DD];         // (e,pos) e-major
__device__ float g_z_im[NPOS*DD];
__device__ float g_xmean_re[BT*DD], g_xmean_im[BT*DD];
__device__ float g_ff_re[BT*DD],    g_ff_im[BT*DD];      // flux forcing
__device__ float g_src_re[BT*DD],   g_src_im[BT*DD];
__device__ float g_gate[BT*DD];
__device__ float g_ah_re[DD], g_ah_im[DD], g_ch_re[DD], g_ch_im[DD];
__device__ float g_af_re[DD], g_af_im[DD], g_cf_re[DD], g_cf_im[DD];

__device__ __forceinline__ unsigned f2tf32(float v) {
    unsigned u;
    asm("cvt.rna.tf32.f32 %0, %1;" : "=r"(u) : "f"(v));
    return u;
}

#define MMA_TF32(c0,c1,c2,c3,a0,a1,a2,a3,b0,b1) \
    asm("mma.sync.aligned.m16n8k8.row.col.f32.tf32.tf32.f32 " \
        "{%0,%1,%2,%3}, {%4,%5,%6,%7}, {%8,%9}, {%0,%1,%2,%3};" \
        : "+f"(c0), "+f"(c1), "+f"(c2), "+f"(c3) \
        : "r"(a0), "r"(a1), "r"(a2), "r"(a3), "r"(b0), "r"(b1))

// ---------------------------------------------------------------- LayerNorm
__global__ void k_ln(const float* __restrict__ xre, const float* __restrict__ xim,
                     const float* __restrict__ gamma, const float* __restrict__ beta) {
    __shared__ float s[32*129];
    __shared__ float smu[32], srs[32];
    int bid = blockIdx.x;
    int bt  = bid >> 7;
    int rem = bid & 127;
    int h   = rem >> 1;
    int w0  = (rem & 1) << 5;
    int tid = threadIdx.x;
    for (int i = tid; i < 4096; i += 128) {
        int ch = i >> 5, p = i & 31;
        int d  = ch & 63;
        const float* src = (ch < 64) ? xre : xim;
        s[p*129 + ch] = src[((bt*64 + d)*64 + h)*64 + w0 + p];
    }
    __syncthreads();
    if (tid < 32) {
        float sum = 0.f, ss = 0.f;
        #pragma unroll 8
        for (int ch = 0; ch < 128; ++ch) { float v = s[tid*129 + ch]; sum += v; ss += v*v; }
        float mu  = sum * (1.0f/128.0f);
        float var = ss * (1.0f/128.0f) - mu*mu;
        smu[tid] = mu;
        srs[tid] = rsqrtf(var + 1e-5f);
    }
    __syncthreads();
    for (int i = tid; i < 4096; i += 128) {
        int ch = i >> 5, p = i & 31;
        float v = (s[p*129 + ch] - smu[p]) * srs[p] * gamma[ch] + beta[ch];
        g_xn[((bt*128 + ch)*64 + h)*64 + w0 + p] = v;
    }
}

// ------------------------------------------------- conv weight transpose (to tf32 bits)
__global__ void k_wt(const float* __restrict__ cw) {
    int idx = blockIdx.x * 256 + threadIdx.x;   // 147456 total
    int oc = idx / 1152;
    int r  = idx - oc * 1152;                   // ic*9 + tap
    g_wT[r * 128 + oc] = __uint_as_float(f2tf32(cw[idx]));
}

// -------------------- conv 3x3 SAME via tf32 implicit GEMM + bias + metric + residual
#define HST 120
#define CWST 136
__global__ void k_conv(const float* __restrict__ xre, const float* __restrict__ xim,
                       const float* __restrict__ cb, const float* __restrict__ metric) {
    extern __shared__ float sm[];
    float* s_halo = sm;             // tf32 bits
    float* s_w    = sm + 64*HST;    // tf32 bits
    int bt   = blockIdx.y;
    int tile = blockIdx.x;
    int ty0  = (tile >> 3) << 3;
    int tx0  = (tile & 7) << 3;
    int tid  = threadIdx.x;
    int wid  = tid >> 5, lane = tid & 31;
    int m0   = (wid & 3) << 5;
    int n0   = (wid >> 2) << 5;
    int grp  = lane >> 2, thr = lane & 3;
    float c[2][4][4] = {};

    for (int cc = 0; cc < 2; ++cc) {
        int ic0 = cc << 6;
        __syncthreads();
        for (int i = tid; i < 7680; i += 256) {
            int ic = i / HST; int r = i - ic*HST;
            int yy = r / 12,  xx = r - yy*12;
            int gy = ty0 + yy - 1, gx = tx0 + xx - 1;
            float v = 0.f;
            if (xx < 10 && gy >= 0 && gy < 64 && gx >= 0 && gx < 64)
                v = g_xn[(bt*128 + ic0 + ic)*4096 + gy*64 + gx];
            s_halo[ic*HST + yy*12 + xx] = __uint_as_float(f2tf32(v));
        }
        for (int tap = 0; tap < 9; ++tap) {
            __syncthreads();
            for (int i = tid; i < 8192; i += 256) {
                int k = i >> 7, oc = i & 127;
                s_w[k*CWST + oc] = g_wT[((ic0 + k)*9 + tap)*128 + oc];
            }
            __syncthreads();
            int ky = tap / 3, kx = tap - ky*3;
            #pragma unroll 2
            for (int ks = 0; ks < 8; ++ks) {
                int k0 = ks << 3;
                unsigned a[2][4], b[4][2];
                #pragma unroll
                for (int ms = 0; ms < 2; ++ms) {
                    const float* ba = s_w + (k0 + thr)*CWST + m0 + ms*16 + grp;
                    a[ms][0] = __float_as_uint(ba[0]);
                    a[ms][1] = __float_as_uint(ba[8]);
                    a[ms][2] = __float_as_uint(ba[4*CWST]);
                    a[ms][3] = __float_as_uint(ba[4*CWST + 8]);
                }
                #pragma unroll
                for (int ns = 0; ns < 4; ++ns) {
                    int p  = n0 + ns*8 + grp;
                    int off = ((p >> 3) + ky)*12 + (p & 7) + kx;
                    b[ns][0] = __float_as_uint(s_halo[(k0 + thr)*HST + off]);
                    b[ns][1] = __float_as_uint(s_halo[(k0 + thr + 4)*HST + off]);
                }
                #pragma unroll
                for (int ms = 0; ms < 2; ++ms)
                    #pragma unroll
                    for (int ns = 0; ns < 4; ++ns)
                        MMA_TF32(c[ms][ns][0], c[ms][ns][1], c[ms][ns][2], c[ms][ns][3],
                                 a[ms][0], a[ms][1], a[ms][2], a[ms][3],
                                 b[ns][0], b[ns][1]);
            }
        }
    }
    #pragma unroll
    for (int ms = 0; ms < 2; ++ms) {
        #pragma unroll
        for (int rr = 0; rr < 2; ++rr) {
            int oc = m0 + ms*16 + grp + rr*8;
            int d  = oc & 63;
            bool isim = (oc >= 64);
            float bias = cb[oc];
            #pragma unroll
            for (int ns = 0; ns < 4; ++ns) {
                int p  = n0 + ns*8 + thr*2;
                int h  = ty0 + (p >> 3);
                int w  = tx0 + (p & 7);
                int base = ((bt*64 + d)*64 + h)*64 + w;
                float2 mv = *(const float2*)&metric[h*64 + w];
                const float* xin = isim ? xim : xre;
                float2 xv = *(const float2*)&xin[base];
                float cA = c[ms][ns][rr*2 + 0];
                float cB = c[ms][ns][rr*2 + 1];
                float2 r = make_float2(xv.x + (cA + bias)*mv.x,
                                       xv.y + (cB + bias)*mv.y);
                if (!isim) *(float2*)&g_xsp_re[base] = r;
                else       *(float2*)&g_xsp_im[base] = r;
            }
        }
    }
}

// --------------------------- egemm1: complex 64x64 GEMM via tf32 mma (E)
#define XTS 72
__global__ void k_egemm1(const float* __restrict__ Er, const float* __restrict__ Ei) {
    extern __shared__ float sm[];
    float* s_er = sm;                   // [64][XTS]
    float* s_ei = sm + 64*XTS;
    float* s_xr = sm + 2*64*XTS;        // [128][XTS]
    float* s_xi = sm + 2*64*XTS + 128*XTS;
    int tid  = threadIdx.x;
    int pos0 = blockIdx.x << 7;
    int bt   = pos0 >> 12;
    int hw0  = pos0 & 4095;
    for (int i = tid; i < 4096; i += 256) {
        int d = i >> 6, e = i & 63;
        s_er[e*XTS + d] = __uint_as_float(f2tf32(Er[i]));
        s_ei[e*XTS + d] = __uint_as_float(f2tf32(Ei[i]));
    }
    for (int i = tid; i < 8192; i += 256) {
        int d = i >> 7, p = i & 127;
        int g = (bt*64 + d)*4096 + hw0 + p;
        s_xr[p*XTS + d] = __uint_as_float(f2tf32(g_xsp_re[g]));
        s_xi[p*XTS + d] = __uint_as_float(f2tf32(g_xsp_im[g]));
    }
    __syncthreads();
    int wid = tid >> 5, lane = tid & 31;
    int m0  = (wid & 1) << 5;
    int n0  = (wid >> 1) << 5;
    int grp = lane >> 2, thr = lane & 3;
    float cre[2][4][4] = {}, cim[2][4][4] = {};
    #pragma unroll
    for (int k0 = 0; k0 < 64; k0 += 8) {
        unsigned aer[2][4], pei[2][4], nei[2][4], bxr[4][2], bxi[4][2];
        #pragma unroll
        for (int ms = 0; ms < 2; ++ms) {
            const float* be = s_er + (m0 + ms*16 + grp)*XTS + k0 + thr;
            aer[ms][0] = __float_as_uint(be[0]);
            aer[ms][1] = __float_as_uint(be[8*XTS]);
            aer[ms][2] = __float_as_uint(be[4]);
            aer[ms][3] = __float_as_uint(be[8*XTS + 4]);
            const float* bi = s_ei + (m0 + ms*16 + grp)*XTS + k0 + thr;
            pei[ms][0] = __float_as_uint(bi[0]);
            pei[ms][1] = __float_as_uint(bi[8*XTS]);
            pei[ms][2] = __float_as_uint(bi[4]);
            pei[ms][3] = __float_as_uint(bi[8*XTS + 4]);
            #pragma unroll
            for (int j = 0; j < 4; ++j) nei[ms][j] = pei[ms][j] ^ 0x80000000u;
        }
        #pragma unroll
        for (int ns = 0; ns < 4; ++ns) {
            const float* br = s_xr + (n0 + ns*8 + grp)*XTS + k0 + thr;
            bxr[ns][0] = __float_as_uint(br[0]);
            bxr[ns][1] = __float_as_uint(br[4]);
            const float* bim = s_xi + (n0 + ns*8 + grp)*XTS + k0 + thr;
            bxi[ns][0] = __float_as_uint(bim[0]);
            bxi[ns][1] = __float_as_uint(bim[4]);
        }
        #pragma unroll
        for (int ms = 0; ms < 2; ++ms)
            #pragma unroll
            for (int ns = 0; ns < 4; ++ns) {
                MMA_TF32(cre[ms][ns][0], cre[ms][ns][1], cre[ms][ns][2], cre[ms][ns][3],
                         aer[ms][0], aer[ms][1], aer[ms][2], aer[ms][3],
                         bxr[ns][0], bxr[ns][1]);
                MMA_TF32(cre[ms][ns][0], cre[ms][ns][1], cre[ms][ns][2], cre[ms][ns][3],
                         nei[ms][0], nei[ms][1], nei[ms][2], nei[ms][3],
                         bxi[ns][0], bxi[ns][1]);
                MMA_TF32(cim[ms][ns][0], cim[ms][ns][1], cim[ms][ns][2], cim[ms][ns][3],
                         aer[ms][0], aer[ms][1], aer[ms][2], aer[ms][3],
                         bxi[ns][0], bxi[ns][1]);
                MMA_TF32(cim[ms][ns][0], cim[ms][ns][1], cim[ms][ns][2], cim[ms][ns][3],
                         pei[ms][0], pei[ms][1], pei[ms][2], pei[ms][3],
                         bxr[ns][0], bxr[ns][1]);
            }
    }
    // (pos,e) output: transpose through smem (reuse s_xr region; [128][66])
    float* sbuf = s_xr;
    #pragma unroll
    for (int pass = 0; pass < 2; ++pass) {
        float (*cc)[4][4] = pass ? cim : cre;
        float* dst = pass ? g_xeig_im : g_xeig_re;
        __syncthreads();
        #pragma unroll
        for (int ms = 0; ms < 2; ++ms)
            #pragma unroll
            for (int ns = 0; ns < 4; ++ns) {
                int e  = m0 + ms*16 + grp;
                int np = n0 + ns*8 + thr*2;
                sbuf[np*66 + e]           = cc[ms][ns][0];
                sbuf[(np+1)*66 + e]       = cc[ms][ns][1];
                sbuf[np*66 + e + 8]       = cc[ms][ns][2];
                sbuf[(np+1)*66 + e + 8]   = cc[ms][ns][3];
            }
        __syncthreads();
        for (int i = tid; i < 8192; i += 256) {
            int p = i >> 6, e = i & 63;
            dst[(pos0 + p)*64 + e] = sbuf[p*66 + e];
        }
    }
}

// --------------- fused recurrence + decode GEMM (Edec), h_out write
// Block = 16 hw x 8 t of one batch b (128 "positions"); p = t*16 + hwl.
__global__ void k_recdec(const float* __restrict__ Er, const float* __restrict__ Ei,
                         const float* __restrict__ hpr, const float* __restrict__ hpi,
                         float* __restrict__ dout) {
    extern __shared__ float sm[];
    float* s_er = sm;                   // [64][XTS]
    float* s_ei = sm + 64*XTS;
    float* s_xr = sm + 2*64*XTS;        // [128][XTS]  (y, tf32)
    float* s_xi = sm + 2*64*XTS + 128*XTS;
    int tid = threadIdx.x;
    int blk = blockIdx.x;               // 1024 = 4 b * 256 hw-tiles
    int b   = blk >> 8;
    int hw0 = (blk & 255) << 4;
    for (int i = tid; i < 4096; i += 256) {
        int d = i >> 6, e = i & 63;
        s_er[e*XTS + d] = __uint_as_float(f2tf32(Er[i]));
        s_ei[e*XTS + d] = __uint_as_float(f2tf32(Ei[i]));
    }
    // recurrence staging: 1024 (hwl,d) pairs, serial over t
    for (int i = tid; i < 1024; i += 256) {
        int hwl = i >> 6, d = i & 63;
        int hw  = hw0 + hwl;
        float ar = g_ah_re[d], ai = g_ah_im[d];
        float cr = g_ch_re[d], ci = g_ch_im[d];
        int hbase = (b*4096 + hw)*64 + d;
        float yr = hpr[hbase], yi = hpi[hbase];
        #pragma unroll
        for (int t = 0; t < 8; ++t) {
            int bt  = b*8 + t;
            int idx = (bt*4096 + hw)*64 + d;
            float xr = g_xeig_re[idx], xi = g_xeig_im[idx];
            float g  = g_gate[bt*64 + d];
            float sr = g_src_re[bt*64 + d], si = g_src_im[bt*64 + d];
            float fr = xr*g + sr*(1.f - g);
            float fi = xi*g + si*(1.f - g);
            float ur = fr*cr - fi*ci, ui = fr*ci + fi*cr;
            float nyr = ar*yr - ai*yi + ur;
            float nyi = ar*yi + ai*yr + ui;
            yr = nyr; yi = nyi;
            int p = t*16 + hwl;
            s_xr[p*XTS + d] = __uint_as_float(f2tf32(yr));
            s_xi[p*XTS + d] = __uint_as_float(f2tf32(yi));
        }
        dout[OUT_OFF_H + hbase]           = yr;
        dout[OUT_OFF_H + 1048576 + hbase] = yi;
    }
    __syncthreads();
    int wid = tid >> 5, lane = tid & 31;
    int m0  = (wid & 1) << 5;
    int n0  = (wid >> 1) << 5;
    int grp = lane >> 2, thr = lane & 3;
    float cre[2][4][4] = {}, cim[2][4][4] = {};
    #pragma unroll
    for (int k0 = 0; k0 < 64; k0 += 8) {
        unsigned aer[2][4], pei[2][4], nei[2][4], bxr[4][2], bxi[4][2];
        #pragma unroll
        for (int ms = 0; ms < 2; ++ms) {
            const float* be = s_er + (m0 + ms*16 + grp)*XTS + k0 + thr;
            aer[ms][0] = __float_as_uint(be[0]);
            aer[ms][1] = __float_as_uint(be[8*XTS]);
            aer[ms][2] = __float_as_uint(be[4]);
            aer[ms][3] = __float_as_uint(be[8*XTS + 4]);
            const float* bi = s_ei + (m0 + ms*16 + grp)*XTS + k0 + thr;
            pei[ms][0] = __float_as_uint(bi[0]);
            pei[ms][1] = __float_as_uint(bi[8*XTS]);
            pei[ms][2] = __float_as_uint(bi[4]);
            pei[ms][3] = __float_as_uint(bi[8*XTS + 4]);
            #pragma unroll
            for (int j = 0; j < 4; ++j) nei[ms][j] = pei[ms][j] ^ 0x80000000u;
        }
        #pragma unroll
        for (int ns = 0; ns < 4; ++ns) {
            const float* br = s_xr + (n0 + ns*8 + grp)*XTS + k0 + thr;
            bxr[ns][0] = __float_as_uint(br[0]);
            bxr[ns][1] = __float_as_uint(br[4]);
            const float* bim = s_xi + (n0 + ns*8 + grp)*XTS + k0 + thr;
            bxi[ns][0] = __float_as_uint(bim[0]);
            bxi[ns][1] = __float_as_uint(bim[4]);
        }
        #pragma unroll
        for (int ms = 0; ms < 2; ++ms)
            #pragma unroll
            for (int ns = 0; ns < 4; ++ns) {
                MMA_TF32(cre[ms][ns][0], cre[ms][ns][1], cre[ms][ns][2], cre[ms][ns][3],
                         aer[ms][0], aer[ms][1], aer[ms][2], aer[ms][3],
                         bxr[ns][0], bxr[ns][1]);
                MMA_TF32(cre[ms][ns][0], cre[ms][ns][1], cre[ms][ns][2], cre[ms][ns][3],
                         nei[ms][0], nei[ms][1], nei[ms][2], nei[ms][3],
                         bxi[ns][0], bxi[ns][1]);
                MMA_TF32(cim[ms][ns][0], cim[ms][ns][1], cim[ms][ns][2], cim[ms][ns][3],
                         aer[ms][0], aer[ms][1], aer[ms][2], aer[ms][3],
                         bxi[ns][0], bxi[ns][1]);
                MMA_TF32(cim[ms][ns][0], cim[ms][ns][1], cim[ms][ns][2], cim[ms][ns][3],
                         pei[ms][0], pei[ms][1], pei[ms][2], pei[ms][3],
                         bxr[ns][0], bxr[ns][1]);
            }
    }
    // (e,pos) e-major stores; pos = (b*8 + t)*4096 + hw0 + hwl, p = t*16 + hwl
    #pragma unroll
    for (int ms = 0; ms < 2; ++ms)
        #pragma unroll
        for (int ns = 0; ns < 4; ++ns) {
            int e  = m0 + ms*16 + grp;
            int np = n0 + ns*8 + thr*2;
            int t  = np >> 4, hwl = np & 15;
            int gp = (b*8 + t)*4096 + hw0 + hwl;
            *(float2*)(g_z_re + e*NPOS + gp)       = make_float2(cre[ms][ns][0], cre[ms][ns][1]);
            *(float2*)(g_z_re + (e+8)*NPOS + gp)   = make_float2(cre[ms][ns][2], cre[ms][ns][3]);
            *(float2*)(g_z_im + e*NPOS + gp)       = make_float2(cim[ms][ns][0], cim[ms][ns][1]);
            *(float2*)(g_z_im + (e+8)*NPOS + gp)   = make_float2(cim[ms][ns][2], cim[ms][ns][3]);
        }
}

// ----------------------------------------------- spatial mean of x_eig
__global__ void k_mean() {
    __shared__ float rr[256], ri[256];
    int bt = blockIdx.x, tid = threadIdx.x;
    int c = tid >> 6, e = tid & 63;
    float sr = 0.f, si = 0.f;
    int base = ((bt*4096 + c*1024)*64) + e;
    for (int i = 0; i < 1024; ++i) {
        sr += g_xeig_re[base + i*64];
        si += g_xeig_im[base + i*64];
    }
    rr[tid] = sr; ri[tid] = si;
    __syncthreads();
    if (c == 0) {
        sr = rr[e] + rr[64+e] + rr[128+e] + rr[192+e];
        si = ri[e] + ri[64+e] + ri[128+e] + ri[192+e];
        g_xmean_re[bt*64 + e] = sr * (1.0f/4096.0f);
        g_xmean_im[bt*64 + e] = si * (1.0f/4096.0f);
    }
}

// ----------------------------------------------- per-d recurrence constants
__global__ void k_consts(const float* __restrict__ dt,
                         const float* __restrict__ lhr, const float* __restrict__ lhi,
                         const float* __restrict__ lfr, const float* __restrict__ lfi) {
    int d = threadIdx.x;
    float t = dt[0];
    {
        float lr = -fabsf(lhr[d]), li = lhi[d];
        float m = expf(lr*t);
        float ar = m*cosf(li*t), ai = m*sinf(li*t);
        float nr = ar - 1.f, ni = ai;
        float den = lr*lr + li*li;
        g_ah_re[d] = ar; g_ah_im[d] = ai;
        g_ch_re[d] = (nr*lr + ni*li)/den;
        g_ch_im[d] = (ni*lr - nr*li)/den;
    }
    {
        float lr = -fabsf(lfr[d]), li = lfi[d];
        float m = expf(lr*t);
        float ar = m*cosf(li*t), ai = m*sinf(li*t);
        float nr = ar - 1.f, ni = ai;
        float den = lr*lr + li*li;
        g_af_re[d] = ar; g_af_im[d] = ai;
        g_cf_re[d] = (nr*lr + ni*li)/den;
        g_cf_im[d] = (ni*lr - nr*li)/den;
    }
}

// ----------------------------------------------- flux scan over T
__global__ void k_flux(const float* __restrict__ fpr, const float* __restrict__ fpi,
                       float* __restrict__ dout) {
    int tid = threadIdx.x;
    int b = tid >> 6, d = tid & 63;
    float ar = g_af_re[d], ai = g_af_im[d];
    float cr = g_cf_re[d], ci = g_cf_im[d];
    float sr = fpr[b*64 + d], si = fpi[b*64 + d];
    #pragma unroll
    for (int t = 0; t < 8; ++t) {
        int idx = (b*8 + t)*64 + d;
        g_ff_re[idx] = sr; g_ff_im[idx] = si;
        float xr = g_xmean_re[idx], xi = g_xmean_im[idx];
        float ur = xr*cr - xi*ci, ui = xr*ci + xi*cr;
        float nsr = ar*sr - ai*si + ur;
        float nsi = ar*si + ai*sr + ui;
        sr = nsr; si = nsi;
    }
    dout[OUT_OFF_F + b*64 + d]       = sr;
    dout[OUT_OFF_F + 256 + b*64 + d] = si;
}

// ----------------------------------------------- source / gate
__global__ void k_srcgate(const float* __restrict__ Wsr, const float* __restrict__ Wsi,
                          const float* __restrict__ Wg,  const float* __restrict__ bg) {
    int bt = blockIdx.x;
    int e  = threadIdx.x;
    float sr = 0.f, si = 0.f, ga = 0.f;
    #pragma unroll 8
    for (int d = 0; d < 64; ++d) {
        float fr = g_ff_re[bt*64 + d], fi = g_ff_im[bt*64 + d];
        float wr = Wsr[d*64 + e], wi = Wsi[d*64 + e];
        sr += fr*wr - fi*wi;
        si += fr*wi + fi*wr;
        ga += fr*Wg[d*64 + e];
    }
    g_src_re[bt*64 + e] = sr;
    g_src_im[bt*64 + e] = si;
    g_gate[bt*64 + e]   = 1.f/(1.f + expf(-(ga + bg[e])));
}

// ----------------------------------------------- fused FFN (tf32 tensor-core)
__device__ __forceinline__ float gelu_f(float x) {
    float x3 = x*x*x;
    return 0.5f*x*(1.f + tanhf(0.7978845608028654f*(x + 0.044715f*x3)));
}

#define ZST 72
#define WST 136
__global__ void k_ffn(const float* __restrict__ w1, const float* __restrict__ b1,
                      const float* __restrict__ w2g, const float* __restrict__ b2,
                      float* __restrict__ dout) {
    extern __shared__ float sm[];
    float* s_z  = sm;                   // [128 k][72] tf32
    float* s_h  = sm + 9216;            // [128 hid][72] tf32
    float* s_zr = sm + 18432;           // [64 d][72] fp32 residual
    float* s_zi = sm + 23040;
    float* s_w  = sm + 27648;           // [128 k][136] tf32
    int tid  = threadIdx.x;
    int pos0 = blockIdx.x << 6;
    for (int i = tid; i < 8192; i += 256) {
        int k = i >> 6, p = i & 63;
        if (k < 64) {
            float v = g_z_re[k*NPOS + pos0 + p];
            s_zr[k*ZST + p] = v;
            s_z[k*ZST + p] = __uint_as_float(f2tf32(v));
        } else {
            float v = g_z_im[(k - 64)*NPOS + pos0 + p];
            s_zi[(k - 64)*ZST + p] = v;
            s_z[k*ZST + p] = __uint_as_float(f2tf32(v));
        }
    }
    int wid = tid >> 5, lane = tid & 31;
    int m0 = (wid & 3) << 5, n0 = (wid >> 2) << 5;
    int grp = lane >> 2, thr = lane & 3;
    float co[2][4][4] = {};

    for (int hc = 0; hc < 4; ++hc) {
        __syncthreads();
        for (int i = tid; i < 16384; i += 256) {
            int k = i >> 7, h = i & 127;
            s_w[k*WST + h] = __uint_as_float(f2tf32(w1[k*512 + hc*128 + h]));
        }
        __syncthreads();
        float ch[2][4][4] = {};
        #pragma unroll 2
        for (int k0 = 0; k0 < 128; k0 += 8) {
            unsigned a[2][4], b[4][2];
            #pragma unroll
            for (int ms = 0; ms < 2; ++ms) {
                const float* ba = s_w + (k0 + thr)*WST + m0 + ms*16 + grp;
                a[ms][0] = __float_as_uint(ba[0]);
                a[ms][1] = __float_as_uint(ba[8]);
                a[ms][2] = __float_as_uint(ba[4*WST]);
                a[ms][3] = __float_as_uint(ba[4*WST + 8]);
            }
            #pragma unroll
            for (int ns = 0; ns < 4; ++ns) {
                const float* bb = s_z + (k0 + thr)*ZST + n0 + ns*8 + grp;
                b[ns][0] = __float_as_uint(bb[0]);
                b[ns][1] = __float_as_uint(bb[4*ZST]);
            }
            #pragma unroll
            for (int ms = 0; ms < 2; ++ms)
                #pragma unroll
                for (int ns = 0; ns < 4; ++ns)
                    MMA_TF32(ch[ms][ns][0], ch[ms][ns][1], ch[ms][ns][2], ch[ms][ns][3],
                             a[ms][0], a[ms][1], a[ms][2], a[ms][3],
                             b[ns][0], b[ns][1]);
        }
        #pragma unroll
        for (int ms = 0; ms < 2; ++ms) {
            #pragma unroll
            for (int rr = 0; rr < 2; ++rr) {
                int hh = m0 + ms*16 + grp + rr*8;
                float bb = b1[hc*128 + hh];
                #pragma unroll
                for (int ns = 0; ns < 4; ++ns) {
                    int p = n0 + ns*8 + thr*2;
                    s_h[hh*ZST + p]     = __uint_as_float(f2tf32(gelu_f(ch[ms][ns][rr*2 + 0] + bb)));
                    s_h[hh*ZST + p + 1] = __uint_as_float(f2tf32(gelu_f(ch[ms][ns][rr*2 + 1] + bb)));
                }
            }
        }
        __syncthreads();
        for (int i = tid; i < 16384; i += 256) {
            int k = i >> 7, oc = i & 127;
            s_w[k*WST + oc] = __uint_as_float(f2tf32(w2g[(hc*128 + k)*128 + oc]));
        }
        __syncthreads();
        #pragma unroll 2
        for (int k0 = 0; k0 < 128; k0 += 8) {
            unsigned a[2][4], b[4][2];
            #pragma unroll
            for (int ms = 0; ms < 2; ++ms) {
                const float* ba = s_w + (k0 + thr)*WST + m0 + ms*16 + grp;
                a[ms][0] = __float_as_uint(ba[0]);
                a[ms][1] = __float_as_uint(ba[8]);
                a[ms][2] = __float_as_uint(ba[4*WST]);
                a[ms][3] = __float_as_uint(ba[4*WST + 8]);
            }
            #pragma unroll
            for (int ns = 0; ns < 4; ++ns) {
                const float* bb = s_h + (k0 + thr)*ZST + n0 + ns*8 + grp;
                b[ns][0] = __float_as_uint(bb[0]);
                b[ns][1] = __float_as_uint(bb[4*ZST]);
            }
            #pragma unroll
            for (int ms = 0; ms < 2; ++ms)
                #pragma unroll
                for (int ns = 0; ns < 4; ++ns)
                    MMA_TF32(co[ms][ns][0], co[ms][ns][1], co[ms][ns][2], co[ms][ns][3],
                             a[ms][0], a[ms][1], a[ms][2], a[ms][3],
                             b[ns][0], b[ns][1]);
        }
    }
    int bt  = pos0 >> 12;
    int hw0 = pos0 & 4095;
    #pragma unroll
    for (int ms = 0; ms < 2; ++ms) {
        #pragma unroll
        for (int rr = 0; rr < 2; ++rr) {
            int oc = m0 + ms*16 + grp + rr*8;
            int d  = oc & 63;
            bool isim = (oc >= 64);
            float bb = b2[oc];
            #pragma unroll
            for (int ns = 0; ns < 4; ++ns) {
                int np = n0 + ns*8 + thr*2;
                int base = (bt*64 + d)*4096 + hw0 + np;
                float2 zv = *(const float2*)((isim ? s_zi : s_zr) + d*ZST + np);
                const float* xsrc = isim ? g_xsp_im : g_xsp_re;
                float2 xv = *(const float2*)(xsrc + base);
                float cA = co[ms][ns][rr*2 + 0];
                float cB = co[ms][ns][rr*2 + 1];
                float2 r = make_float2(cA + bb + zv.x + xv.x, cB + bb + zv.y + xv.y);
                *(float2*)(dout + (isim ? 8388608 : 0) + base) = r;
            }
        }
    }
}

// ---------------------------------------------------------------- launch
extern "C" void kernel_launch(void* const* d_in, const int* in_sizes, int n_in,
                              void* d_out, int out_size) {
    const float* x_re    = (const float*)d_in[0];
    const float* x_im    = (const float*)d_in[1];
    const float* hp_re   = (const float*)d_in[2];
    const float* hp_im   = (const float*)d_in[3];
    const float* fp_re   = (const float*)d_in[4];
    const float* fp_im   = (const float*)d_in[5];
    const float* dt      = (const float*)d_in[6];
    const float* ln_g    = (const float*)d_in[7];
    const float* ln_b    = (const float*)d_in[8];
    const float* conv_w  = (const float*)d_in[9];
    const float* conv_b  = (const float*)d_in[10];
    const float* metric  = (const float*)d_in[11];
    const float* E_re    = (const float*)d_in[12];
    const float* E_im    = (const float*)d_in[13];
    const float* Ed_re   = (const float*)d_in[14];
    const float* Ed_im   = (const float*)d_in[15];
    const float* lh_re   = (const float*)d_in[16];
    const float* lh_im   = (const float*)d_in[17];
    const float* lf_re   = (const float*)d_in[18];
    const float* lf_im   = (const float*)d_in[19];
    const float* Ws_re   = (const float*)d_in[20];
    const float* Ws_im   = (const float*)d_in[21];
    const float* W_gate  = (const float*)d_in[22];
    const float* b_gate  = (const float*)d_in[23];
    const float* ffn_w1  = (const float*)d_in[24];
    const float* ffn_b1  = (const float*)d_in[25];
    const float* ffn_w2  = (const float*)d_in[26];
    const float* ffn_b2  = (const float*)d_in[27];
    float* out = (float*)d_out;

    // conv: 65536 B; egemm1/recdec: 110592 B; ffn fused: 180224 B
    cudaFuncSetAttribute(k_conv,   cudaFuncAttributeMaxDynamicSharedMemorySize, 65536);
    cudaFuncSetAttribute(k_egemm1, cudaFuncAttributeMaxDynamicSharedMemorySize, 110592);
    cudaFuncSetAttribute(k_recdec, cudaFuncAttributeMaxDynamicSharedMemorySize, 110592);
    cudaFuncSetAttribute(k_ffn,    cudaFuncAttributeMaxDynamicSharedMemorySize, 180224);

    k_ln<<<4096, 128>>>(x_re, x_im, ln_g, ln_b);
    k_wt<<<576, 256>>>(conv_w);
    k_conv<<<dim3(64, 32), 256, 65536>>>(x_re, x_im, conv_b, metric);
    k_egemm1<<<1024, 256, 110592>>>(E_re, E_im);
    k_mean<<<32, 256>>>();
    k_consts<<<1, 64>>>(dt, lh_re, lh_im, lf_re, lf_im);
    k_flux<<<1, 256>>>(fp_re, fp_im, out);
    k_srcgate<<<32, 64>>>(Ws_re, Ws_im, W_gate, b_gate);
    k_recdec<<<1024, 256, 110592>>>(Ed_re, Ed_im, hp_re, hp_im, out);
    k_ffn<<<2048, 256, 180224>>>(ffn_w1, ffn_b1, ffn_w2, ffn_b2, out);
}

// round 17
// speedup vs baseline: 2.5387x; 1.3731x over previous
#include <cuda_runtime.h>
#include <math.h>

#define BB 4
#define TT 8
#define BT 32
#define DD 64
#define CC 128
#define HH 64
#define WW 64
#define HW 4096
#define NPOS 131072          // BT*HW
#define HID 512
#define OUT_OFF_H 16777216   // 2*B*T*D*H*W
#define OUT_OFF_F 18874368   // + 2*B*H*W*D

// ---------------- scratch (device globals; no allocations allowed) ----------
__device__ float g_xn[BT*CC*HW];          // LN output, (bt,ch,h,w)
__device__ float g_wT[CC*9*CC];           // conv weights transposed (tf32 bits): (ic,tap,oc)
__device__ float g_xsp_re[NPOS*DD];       // (bt,d,hw)  d-major
__device__ float g_xsp_im[NPOS*DD];
__device__ float g_xeig_re[NPOS*DD];      // (e,pos) e-major (pre-recurrence)
__device__ float g_xeig_im[NPOS*DD];
__device__ float g_z_re[NPOS*DD];         // (e,pos) e-major
__device__ float g_z_im[NPOS*DD];
__device__ float g_xmean_re[BT*DD], g_xmean_im[BT*DD];
__device__ float g_ff_re[BT*DD],    g_ff_im[BT*DD];      // flux forcing
__device__ float g_src_re[BT*DD],   g_src_im[BT*DD];
__device__ float g_gate[BT*DD];
__device__ float g_ah_re[DD], g_ah_im[DD], g_ch_re[DD], g_ch_im[DD];
__device__ float g_af_re[DD], g_af_im[DD], g_cf_re[DD], g_cf_im[DD];

__device__ __forceinline__ unsigned f2tf32(float v) {
    unsigned u;
    asm("cvt.rna.tf32.f32 %0, %1;" : "=r"(u) : "f"(v));
    return u;
}
__device__ __forceinline__ float4 cvt4(float4 v) {
    v.x = __uint_as_float(f2tf32(v.x));
    v.y = __uint_as_float(f2tf32(v.y));
    v.z = __uint_as_float(f2tf32(v.z));
    v.w = __uint_as_float(f2tf32(v.w));
    return v;
}

#define MMA_TF32(c0,c1,c2,c3,a0,a1,a2,a3,b0,b1) \
    asm("mma.sync.aligned.m16n8k8.row.col.f32.tf32.tf32.f32 " \
        "{%0,%1,%2,%3}, {%4,%5,%6,%7}, {%8,%9}, {%0,%1,%2,%3};" \
        : "+f"(c0), "+f"(c1), "+f"(c2), "+f"(c3) \
        : "r"(a0), "r"(a1), "r"(a2), "r"(a3), "r"(b0), "r"(b1))

// ---------------------------------------------------------------- LayerNorm
__global__ void k_ln(const float* __restrict__ xre, const float* __restrict__ xim,
                     const float* __restrict__ gamma, const float* __restrict__ beta) {
    __shared__ float s[32*129];
    __shared__ float smu[32], srs[32];
    int bid = blockIdx.x;
    int bt  = bid >> 7;
    int rem = bid & 127;
    int h   = rem >> 1;
    int w0  = (rem & 1) << 5;
    int tid = threadIdx.x;
    for (int i = tid; i < 4096; i += 128) {
        int ch = i >> 5, p = i & 31;
        int d  = ch & 63;
        const float* src = (ch < 64) ? xre : xim;
        s[p*129 + ch] = src[((bt*64 + d)*64 + h)*64 + w0 + p];
    }
    __syncthreads();
    if (tid < 32) {
        float sum = 0.f, ss = 0.f;
        #pragma unroll 8
        for (int ch = 0; ch < 128; ++ch) { float v = s[tid*129 + ch]; sum += v; ss += v*v; }
        float mu  = sum * (1.0f/128.0f);
        float var = ss * (1.0f/128.0f) - mu*mu;
        smu[tid] = mu;
        srs[tid] = rsqrtf(var + 1e-5f);
    }
    __syncthreads();
    for (int i = tid; i < 4096; i += 128) {
        int ch = i >> 5, p = i & 31;
        float v = (s[p*129 + ch] - smu[p]) * srs[p] * gamma[ch] + beta[ch];
        g_xn[((bt*128 + ch)*64 + h)*64 + w0 + p] = v;
    }
}

// ------------------------------------------------- conv weight transpose (to tf32 bits)
__global__ void k_wt(const float* __restrict__ cw) {
    int idx = blockIdx.x * 256 + threadIdx.x;   // 147456 total
    int oc = idx / 1152;
    int r  = idx - oc * 1152;                   // ic*9 + tap
    g_wT[r * 128 + oc] = __uint_as_float(f2tf32(cw[idx]));
}

// -------------------- conv 3x3 SAME via tf32 implicit GEMM + bias + metric + residual
#define HST 120
#define CWST 136
__global__ void k_conv(const float* __restrict__ xre, const float* __restrict__ xim,
                       const float* __restrict__ cb, const float* __restrict__ metric) {
    extern __shared__ float sm[];
    float* s_halo = sm;             // tf32 bits
    float* s_w    = sm + 64*HST;    // tf32 bits
    int bt   = blockIdx.y;
    int tile = blockIdx.x;
    int ty0  = (tile >> 3) << 3;
    int tx0  = (tile & 7) << 3;
    int tid  = threadIdx.x;
    int wid  = tid >> 5, lane = tid & 31;
    int m0   = (wid & 3) << 5;
    int n0   = (wid >> 2) << 5;
    int grp  = lane >> 2, thr = lane & 3;
    float c[2][4][4] = {};

    for (int cc = 0; cc < 2; ++cc) {
        int ic0 = cc << 6;
        __syncthreads();
        for (int i = tid; i < 7680; i += 256) {
            int ic = i / HST; int r = i - ic*HST;
            int yy = r / 12,  xx = r - yy*12;
            int gy = ty0 + yy - 1, gx = tx0 + xx - 1;
            float v = 0.f;
            if (xx < 10 && gy >= 0 && gy < 64 && gx >= 0 && gx < 64)
                v = g_xn[(bt*128 + ic0 + ic)*4096 + gy*64 + gx];
            s_halo[ic*HST + yy*12 + xx] = __uint_as_float(f2tf32(v));
        }
        for (int tap = 0; tap < 9; ++tap) {
            __syncthreads();
            for (int i = tid; i < 2048; i += 256) {
                int k = i >> 5, oc4 = (i & 31) << 2;
                *(float4*)(s_w + k*CWST + oc4) =
                    *(const float4*)(g_wT + ((ic0 + k)*9 + tap)*128 + oc4);
            }
            __syncthreads();
            int ky = tap / 3, kx = tap - ky*3;
            #pragma unroll 2
            for (int ks = 0; ks < 8; ++ks) {
                int k0 = ks << 3;
                unsigned a[2][4], b[4][2];
                #pragma unroll
                for (int ms = 0; ms < 2; ++ms) {
                    const float* ba = s_w + (k0 + thr)*CWST + m0 + ms*16 + grp;
                    a[ms][0] = __float_as_uint(ba[0]);
                    a[ms][1] = __float_as_uint(ba[8]);
                    a[ms][2] = __float_as_uint(ba[4*CWST]);
                    a[ms][3] = __float_as_uint(ba[4*CWST + 8]);
                }
                #pragma unroll
                for (int ns = 0; ns < 4; ++ns) {
                    int p  = n0 + ns*8 + grp;
                    int off = ((p >> 3) + ky)*12 + (p & 7) + kx;
                    b[ns][0] = __float_as_uint(s_halo[(k0 + thr)*HST + off]);
                    b[ns][1] = __float_as_uint(s_halo[(k0 + thr + 4)*HST + off]);
                }
                #pragma unroll
                for (int ms = 0; ms < 2; ++ms)
                    #pragma unroll
                    for (int ns = 0; ns < 4; ++ns)
                        MMA_TF32(c[ms][ns][0], c[ms][ns][1], c[ms][ns][2], c[ms][ns][3],
                                 a[ms][0], a[ms][1], a[ms][2], a[ms][3],
                                 b[ns][0], b[ns][1]);
            }
        }
    }
    #pragma unroll
    for (int ms = 0; ms < 2; ++ms) {
        #pragma unroll
        for (int rr = 0; rr < 2; ++rr) {
            int oc = m0 + ms*16 + grp + rr*8;
            int d  = oc & 63;
            bool isim = (oc >= 64);
            float bias = cb[oc];
            #pragma unroll
            for (int ns = 0; ns < 4; ++ns) {
                int p  = n0 + ns*8 + thr*2;
                int h  = ty0 + (p >> 3);
                int w  = tx0 + (p & 7);
                int base = ((bt*64 + d)*64 + h)*64 + w;
                float2 mv = *(const float2*)&metric[h*64 + w];
                const float* xin = isim ? xim : xre;
                float2 xv = *(const float2*)&xin[base];
                float cA = c[ms][ns][rr*2 + 0];
                float cB = c[ms][ns][rr*2 + 1];
                float2 r = make_float2(xv.x + (cA + bias)*mv.x,
                                       xv.y + (cB + bias)*mv.y);
                if (!isim) *(float2*)&g_xsp_re[base] = r;
                else       *(float2*)&g_xsp_im[base] = r;
            }
        }
    }
}

// --------------------------- egemm1: complex 64x64 GEMM via tf32 mma (E)
// Tiles: A (E) as [k=d][m=e] stride 72; B (x) as [k=d][n=p] stride 136.
#define AST 72
#define BST 136
__global__ void k_egemm1(const float* __restrict__ Er, const float* __restrict__ Ei) {
    extern __shared__ float sm[];
    float* s_er = sm;                   // [64 d][72 e]
    float* s_ei = sm + 64*AST;
    float* s_xr = sm + 2*64*AST;        // [64 d][136 p]
    float* s_xi = sm + 2*64*AST + 64*BST;
    int tid  = threadIdx.x;
    int pos0 = blockIdx.x << 7;
    int bt   = pos0 >> 12;
    int hw0  = pos0 & 4095;
    for (int i = tid; i < 1024; i += 256) {
        int d = i >> 4, e4 = (i & 15) << 2;
        *(float4*)(s_er + d*AST + e4) = cvt4(*(const float4*)(Er + d*64 + e4));
        *(float4*)(s_ei + d*AST + e4) = cvt4(*(const float4*)(Ei + d*64 + e4));
    }
    for (int i = tid; i < 2048; i += 256) {
        int d = i >> 5, p4 = (i & 31) << 2;
        int g = (bt*64 + d)*4096 + hw0 + p4;
        *(float4*)(s_xr + d*BST + p4) = cvt4(*(const float4*)(g_xsp_re + g));
        *(float4*)(s_xi + d*BST + p4) = cvt4(*(const float4*)(g_xsp_im + g));
    }
    __syncthreads();
    int wid = tid >> 5, lane = tid & 31;
    int m0  = (wid & 1) << 5;
    int n0  = (wid >> 1) << 5;
    int grp = lane >> 2, thr = lane & 3;
    float cre[2][4][4] = {}, cim[2][4][4] = {};
    #pragma unroll
    for (int k0 = 0; k0 < 64; k0 += 8) {
        unsigned aer[2][4], pei[2][4], nei[2][4], bxr[4][2], bxi[4][2];
        #pragma unroll
        for (int ms = 0; ms < 2; ++ms) {
            const float* ba = s_er + (k0 + thr)*AST + m0 + ms*16 + grp;
            aer[ms][0] = __float_as_uint(ba[0]);
            aer[ms][1] = __float_as_uint(ba[8]);
            aer[ms][2] = __float_as_uint(ba[4*AST]);
            aer[ms][3] = __float_as_uint(ba[4*AST + 8]);
            const float* bi = s_ei + (k0 + thr)*AST + m0 + ms*16 + grp;
            pei[ms][0] = __float_as_uint(bi[0]);
            pei[ms][1] = __float_as_uint(bi[8]);
            pei[ms][2] = __float_as_uint(bi[4*AST]);
            pei[ms][3] = __float_as_uint(bi[4*AST + 8]);
            #pragma unroll
            for (int j = 0; j < 4; ++j) nei[ms][j] = pei[ms][j] ^ 0x80000000u;
        }
        #pragma unroll
        for (int ns = 0; ns < 4; ++ns) {
            const float* br = s_xr + (k0 + thr)*BST + n0 + ns*8 + grp;
            bxr[ns][0] = __float_as_uint(br[0]);
            bxr[ns][1] = __float_as_uint(br[4*BST]);
            const float* bim = s_xi + (k0 + thr)*BST + n0 + ns*8 + grp;
            bxi[ns][0] = __float_as_uint(bim[0]);
            bxi[ns][1] = __float_as_uint(bim[4*BST]);
        }
        #pragma unroll
        for (int ms = 0; ms < 2; ++ms)
            #pragma unroll
            for (int ns = 0; ns < 4; ++ns) {
                MMA_TF32(cre[ms][ns][0], cre[ms][ns][1], cre[ms][ns][2], cre[ms][ns][3],
                         aer[ms][0], aer[ms][1], aer[ms][2], aer[ms][3],
                         bxr[ns][0], bxr[ns][1]);
                MMA_TF32(cre[ms][ns][0], cre[ms][ns][1], cre[ms][ns][2], cre[ms][ns][3],
                         nei[ms][0], nei[ms][1], nei[ms][2], nei[ms][3],
                         bxi[ns][0], bxi[ns][1]);
                MMA_TF32(cim[ms][ns][0], cim[ms][ns][1], cim[ms][ns][2], cim[ms][ns][3],
                         aer[ms][0], aer[ms][1], aer[ms][2], aer[ms][3],
                         bxi[ns][0], bxi[ns][1]);
                MMA_TF32(cim[ms][ns][0], cim[ms][ns][1], cim[ms][ns][2], cim[ms][ns][3],
                         pei[ms][0], pei[ms][1], pei[ms][2], pei[ms][3],
                         bxr[ns][0], bxr[ns][1]);
            }
    }
    // e-major direct stores
    #pragma unroll
    for (int ms = 0; ms < 2; ++ms)
        #pragma unroll
        for (int ns = 0; ns < 4; ++ns) {
            int e  = m0 + ms*16 + grp;
            int np = n0 + ns*8 + thr*2;
            *(float2*)(g_xeig_re + e*NPOS + pos0 + np)     = make_float2(cre[ms][ns][0], cre[ms][ns][1]);
            *(float2*)(g_xeig_re + (e+8)*NPOS + pos0 + np) = make_float2(cre[ms][ns][2], cre[ms][ns][3]);
            *(float2*)(g_xeig_im + e*NPOS + pos0 + np)     = make_float2(cim[ms][ns][0], cim[ms][ns][1]);
            *(float2*)(g_xeig_im + (e+8)*NPOS + pos0 + np) = make_float2(cim[ms][ns][2], cim[ms][ns][3]);
        }
}

// --------------- fused recurrence + decode GEMM (Edec), h_out write
// Block = 16 hw x 8 t of one batch b (p = t*16 + hwl).
__global__ void k_recdec(const float* __restrict__ Er, const float* __restrict__ Ei,
                         const float* __restrict__ hpr, const float* __restrict__ hpi,
                         float* __restrict__ dout) {
    extern __shared__ float sm[];
    float* s_er = sm;                   // [64 d][72 e]
    float* s_ei = sm + 64*AST;
    float* s_xr = sm + 2*64*AST;        // [64 d][136 p] (y, tf32)
    float* s_xi = sm + 2*64*AST + 64*BST;
    int tid = threadIdx.x;
    int blk = blockIdx.x;               // 1024 = 4 b * 256 hw-tiles
    int b   = blk >> 8;
    int hw0 = (blk & 255) << 4;
    for (int i = tid; i < 1024; i += 256) {
        int d = i >> 4, e4 = (i & 15) << 2;
        *(float4*)(s_er + d*AST + e4) = cvt4(*(const float4*)(Er + d*64 + e4));
        *(float4*)(s_ei + d*AST + e4) = cvt4(*(const float4*)(Ei + d*64 + e4));
    }
    // recurrence: thread = (d, hw-quad); x_eig e-major float4 reads
    {
        int hq = tid & 3, d = tid >> 2;
        int hwb = hw0 + (hq << 2);
        float ar = g_ah_re[d], ai = g_ah_im[d];
        float cr = g_ch_re[d], ci = g_ch_im[d];
        float yr[4], yi[4];
        int hb0 = (b*4096 + hwb)*64 + d;
        #pragma unroll
        for (int j = 0; j < 4; ++j) { yr[j] = hpr[hb0 + j*64]; yi[j] = hpi[hb0 + j*64]; }
        #pragma unroll
        for (int t = 0; t < 8; ++t) {
            int bt = b*8 + t;
            int gp = d*NPOS + bt*4096 + hwb;
            float4 xr4 = *(const float4*)(g_xeig_re + gp);
            float4 xi4 = *(const float4*)(g_xeig_im + gp);
            float g  = g_gate[bt*64 + d];
            float sr = g_src_re[bt*64 + d], si = g_src_im[bt*64 + d];
            float xrA[4] = {xr4.x, xr4.y, xr4.z, xr4.w};
            float xiA[4] = {xi4.x, xi4.y, xi4.z, xi4.w};
            float4 or4, oi4;
            float* orp = &or4.x; float* oip = &oi4.x;
            #pragma unroll
            for (int j = 0; j < 4; ++j) {
                float fr = xrA[j]*g + sr*(1.f - g);
                float fi = xiA[j]*g + si*(1.f - g);
                float ur = fr*cr - fi*ci, ui = fr*ci + fi*cr;
                float nyr = ar*yr[j] - ai*yi[j] + ur;
                float nyi = ar*yi[j] + ai*yr[j] + ui;
                yr[j] = nyr; yi[j] = nyi;
                orp[j] = __uint_as_float(f2tf32(nyr));
                oip[j] = __uint_as_float(f2tf32(nyi));
            }
            int p = t*16 + (hq << 2);
            *(float4*)(s_xr + d*BST + p) = or4;
            *(float4*)(s_xi + d*BST + p) = oi4;
        }
        #pragma unroll
        for (int j = 0; j < 4; ++j) {
            dout[OUT_OFF_H + hb0 + j*64]           = yr[j];
            dout[OUT_OFF_H + 1048576 + hb0 + j*64] = yi[j];
        }
    }
    __syncthreads();
    int wid = tid >> 5, lane = tid & 31;
    int m0  = (wid & 1) << 5;
    int n0  = (wid >> 1) << 5;
    int grp = lane >> 2, thr = lane & 3;
    float cre[2][4][4] = {}, cim[2][4][4] = {};
    #pragma unroll
    for (int k0 = 0; k0 < 64; k0 += 8) {
        unsigned aer[2][4], pei[2][4], nei[2][4], bxr[4][2], bxi[4][2];
        #pragma unroll
        for (int ms = 0; ms < 2; ++ms) {
            const float* ba = s_er + (k0 + thr)*AST + m0 + ms*16 + grp;
            aer[ms][0] = __float_as_uint(ba[0]);
            aer[ms][1] = __float_as_uint(ba[8]);
            aer[ms][2] = __float_as_uint(ba[4*AST]);
            aer[ms][3] = __float_as_uint(ba[4*AST + 8]);
            const float* bi = s_ei + (k0 + thr)*AST + m0 + ms*16 + grp;
            pei[ms][0] = __float_as_uint(bi[0]);
            pei[ms][1] = __float_as_uint(bi[8]);
            pei[ms][2] = __float_as_uint(bi[4*AST]);
            pei[ms][3] = __float_as_uint(bi[4*AST + 8]);
            #pragma unroll
            for (int j = 0; j < 4; ++j) nei[ms][j] = pei[ms][j] ^ 0x80000000u;
        }
        #pragma unroll
        for (int ns = 0; ns < 4; ++ns) {
            const float* br = s_xr + (k0 + thr)*BST + n0 + ns*8 + grp;
            bxr[ns][0] = __float_as_uint(br[0]);
            bxr[ns][1] = __float_as_uint(br[4*BST]);
            const float* bim = s_xi + (k0 + thr)*BST + n0 + ns*8 + grp;
            bxi[ns][0] = __float_as_uint(bim[0]);
            bxi[ns][1] = __float_as_uint(bim[4*BST]);
        }
        #pragma unroll
        for (int ms = 0; ms < 2; ++ms)
            #pragma unroll
            for (int ns = 0; ns < 4; ++ns) {
                MMA_TF32(cre[ms][ns][0], cre[ms][ns][1], cre[ms][ns][2], cre[ms][ns][3],
                         aer[ms][0], aer[ms][1], aer[ms][2], aer[ms][3],
                         bxr[ns][0], bxr[ns][1]);
                MMA_TF32(cre[ms][ns][0], cre[ms][ns][1], cre[ms][ns][2], cre[ms][ns][3],
                         nei[ms][0], nei[ms][1], nei[ms][2], nei[ms][3],
                         bxi[ns][0], bxi[ns][1]);
                MMA_TF32(cim[ms][ns][0], cim[ms][ns][1], cim[ms][ns][2], cim[ms][ns][3],
                         aer[ms][0], aer[ms][1], aer[ms][2], aer[ms][3],
                         bxi[ns][0], bxi[ns][1]);
                MMA_TF32(cim[ms][ns][0], cim[ms][ns][1], cim[ms][ns][2], cim[ms][ns][3],
                         pei[ms][0], pei[ms][1], pei[ms][2], pei[ms][3],
                         bxr[ns][0], bxr[ns][1]);
            }
    }
    // (e,pos) e-major stores; p = t*16 + hwl -> pos = (b*8+t)*4096 + hw0 + hwl
    #pragma unroll
    for (int ms = 0; ms < 2; ++ms)
        #pragma unroll
        for (int ns = 0; ns < 4; ++ns) {
            int e  = m0 + ms*16 + grp;
            int np = n0 + ns*8 + thr*2;
            int t  = np >> 4, hwl = np & 15;
            int gp = (b*8 + t)*4096 + hw0 + hwl;
            *(float2*)(g_z_re + e*NPOS + gp)       = make_float2(cre[ms][ns][0], cre[ms][ns][1]);
            *(float2*)(g_z_re + (e+8)*NPOS + gp)   = make_float2(cre[ms][ns][2], cre[ms][ns][3]);
            *(float2*)(g_z_im + e*NPOS + gp)       = make_float2(cim[ms][ns][0], cim[ms][ns][1]);
            *(float2*)(g_z_im + (e+8)*NPOS + gp)   = make_float2(cim[ms][ns][2], cim[ms][ns][3]);
        }
}

// ----------------------------------------------- spatial mean of x_eig (e-major)
__global__ void k_mean() {
    __shared__ float rr[256], ri[256];
    int bt = blockIdx.x, tid = threadIdx.x;
    int c = tid >> 6, e = tid & 63;
    float sr = 0.f, si = 0.f;
    int base = e*NPOS + bt*4096 + c*1024;
    for (int j = 0; j < 256; ++j) {
        float4 vr = *(const float4*)(g_xeig_re + base + j*4);
        float4 vi = *(const float4*)(g_xeig_im + base + j*4);
        sr += (vr.x + vr.y) + (vr.z + vr.w);
        si += (vi.x + vi.y) + (vi.z + vi.w);
    }
    rr[tid] = sr; ri[tid] = si;
    __syncthreads();
    if (c == 0) {
        sr = rr[e] + rr[64+e] + rr[128+e] + rr[192+e];
        si = ri[e] + ri[64+e] + ri[128+e] + ri[192+e];
        g_xmean_re[bt*64 + e] = sr * (1.0f/4096.0f);
        g_xmean_im[bt*64 + e] = si * (1.0f/4096.0f);
    }
}

// ----------------------------------------------- per-d recurrence constants
__global__ void k_consts(const float* __restrict__ dt,
                         const float* __restrict__ lhr, const float* __restrict__ lhi,
                         const float* __restrict__ lfr, const float* __restrict__ lfi) {
    int d = threadIdx.x;
    float t = dt[0];
    {
        float lr = -fabsf(lhr[d]), li = lhi[d];
        float m = expf(lr*t);
        float ar = m*cosf(li*t), ai = m*sinf(li*t);
        float nr = ar - 1.f, ni = ai;
        float den = lr*lr + li*li;
        g_ah_re[d] = ar; g_ah_im[d] = ai;
        g_ch_re[d] = (nr*lr + ni*li)/den;
        g_ch_im[d] = (ni*lr - nr*li)/den;
    }
    {
        float lr = -fabsf(lfr[d]), li = lfi[d];
        float m = expf(lr*t);
        float ar = m*cosf(li*t), ai = m*sinf(li*t);
        float nr = ar - 1.f, ni = ai;
        float den = lr*lr + li*li;
        g_af_re[d] = ar; g_af_im[d] = ai;
        g_cf_re[d] = (nr*lr + ni*li)/den;
        g_cf_im[d] = (ni*lr - nr*li)/den;
    }
}

// ----------------------------------------------- flux scan over T
__global__ void k_flux(const float* __restrict__ fpr, const float* __restrict__ fpi,
                       float* __restrict__ dout) {
    int tid = threadIdx.x;
    int b = tid >> 6, d = tid & 63;
    float ar = g_af_re[d], ai = g_af_im[d];
    float cr = g_cf_re[d], ci = g_cf_im[d];
    float sr = fpr[b*64 + d], si = fpi[b*64 + d];
    #pragma unroll
    for (int t = 0; t < 8; ++t) {
        int idx = (b*8 + t)*64 + d;
        g_ff_re[idx] = sr; g_ff_im[idx] = si;
        float xr = g_xmean_re[idx], xi = g_xmean_im[idx];
        float ur = xr*cr - xi*ci, ui = xr*ci + xi*cr;
        float nsr = ar*sr - ai*si + ur;
        float nsi = ar*si + ai*sr + ui;
        sr = nsr; si = nsi;
    }
    dout[OUT_OFF_F + b*64 + d]       = sr;
    dout[OUT_OFF_F + 256 + b*64 + d] = si;
}

// ----------------------------------------------- source / gate
__global__ void k_srcgate(const float* __restrict__ Wsr, const float* __restrict__ Wsi,
                          const float* __restrict__ Wg,  const float* __restrict__ bg) {
    int bt = blockIdx.x;
    int e  = threadIdx.x;
    float sr = 0.f, si = 0.f, ga = 0.f;
    #pragma unroll 8
    for (int d = 0; d < 64; ++d) {
        float fr = g_ff_re[bt*64 + d], fi = g_ff_im[bt*64 + d];
        float wr = Wsr[d*64 + e], wi = Wsi[d*64 + e];
        sr += fr*wr - fi*wi;
        si += fr*wi + fi*wr;
        ga += fr*Wg[d*64 + e];
    }
    g_src_re[bt*64 + e] = sr;
    g_src_im[bt*64 + e] = si;
    g_gate[bt*64 + e]   = 1.f/(1.f + expf(-(ga + bg[e])));
}

// ----------------------------------------------- fused FFN (tf32 tensor-core)
__device__ __forceinline__ float gelu_f(float x) {
    float x3 = x*x*x;
    return 0.5f*x*(1.f + tanhf(0.7978845608028654f*(x + 0.044715f*x3)));
}

#define ZST 72
#define WST 136
__global__ void k_ffn(const float* __restrict__ w1, const float* __restrict__ b1,
                      const float* __restrict__ w2g, const float* __restrict__ b2,
                      float* __restrict__ dout) {
    extern __shared__ float sm[];
    float* s_z  = sm;                   // [128 k][72] tf32
    float* s_h  = sm + 9216;            // [128 hid][72] tf32
    float* s_zr = sm + 18432;           // [64 d][72] fp32 residual
    float* s_zi = sm + 23040;
    float* s_w  = sm + 27648;           // [128 k][136] tf32
    int tid  = threadIdx.x;
    int pos0 = blockIdx.x << 6;
    for (int i = tid; i < 2048; i += 256) {
        int k = i >> 4, p4 = (i & 15) << 2;
        if (k < 64) {
            float4 v = *(const float4*)(g_z_re + k*NPOS + pos0 + p4);
            *(float4*)(s_zr + k*ZST + p4) = v;
            *(float4*)(s_z + k*ZST + p4) = cvt4(v);
        } else {
            float4 v = *(const float4*)(g_z_im + (k - 64)*NPOS + pos0 + p4);
            *(float4*)(s_zi + (k - 64)*ZST + p4) = v;
            *(float4*)(s_z + k*ZST + p4) = cvt4(v);
        }
    }
    int wid = tid >> 5, lane = tid & 31;
    int m0 = (wid & 3) << 5, n0 = (wid >> 2) << 5;
    int grp = lane >> 2, thr = lane & 3;
    float co[2][4][4] = {};

    for (int hc = 0; hc < 4; ++hc) {
        __syncthreads();
        for (int i = tid; i < 4096; i += 256) {
            int k = i >> 5, h4 = (i & 31) << 2;
            *(float4*)(s_w + k*WST + h4) =
                cvt4(*(const float4*)(w1 + k*512 + hc*128 + h4));
        }
        __syncthreads();
        float ch[2][4][4] = {};
        #pragma unroll 2
        for (int k0 = 0; k0 < 128; k0 += 8) {
            unsigned a[2][4], b[4][2];
            #pragma unroll
            for (int ms = 0; ms < 2; ++ms) {
                const float* ba = s_w + (k0 + thr)*WST + m0 + ms*16 + grp;
                a[ms][0] = __float_as_uint(ba[0]);
                a[ms][1] = __float_as_uint(ba[8]);
                a[ms][2] = __float_as_uint(ba[4*WST]);
                a[ms][3] = __float_as_uint(ba[4*WST + 8]);
            }
            #pragma unroll
            for (int ns = 0; ns < 4; ++ns) {
                const float* bb = s_z + (k0 + thr)*ZST + n0 + ns*8 + grp;
                b[ns][0] = __float_as_uint(bb[0]);
                b[ns][1] = __float_as_uint(bb[4*ZST]);
            }
            #pragma unroll
            for (int ms = 0; ms < 2; ++ms)
                #pragma unroll
                for (int ns = 0; ns < 4; ++ns)
                    MMA_TF32(ch[ms][ns][0], ch[ms][ns][1], ch[ms][ns][2], ch[ms][ns][3],
                             a[ms][0], a[ms][1], a[ms][2], a[ms][3],
                             b[ns][0], b[ns][1]);
        }
        #pragma unroll
        for (int ms = 0; ms < 2; ++ms) {
            #pragma unroll
            for (int rr = 0; rr < 2; ++rr) {
                int hh = m0 + ms*16 + grp + rr*8;
                float bb = b1[hc*128 + hh];
                #pragma unroll
                for (int ns = 0; ns < 4; ++ns) {
                    int p = n0 + ns*8 + thr*2;
                    s_h[hh*ZST + p]     = __uint_as_float(f2tf32(gelu_f(ch[ms][ns][rr*2 + 0] + bb)));
                    s_h[hh*ZST + p + 1] = __uint_as_float(f2tf32(gelu_f(ch[ms][ns][rr*2 + 1] + bb)));
                }
            }
        }
        __syncthreads();
        for (int i = tid; i < 4096; i += 256) {
            int k = i >> 5, oc4 = (i & 31) << 2;
            *(float4*)(s_w + k*WST + oc4) =
                cvt4(*(const float4*)(w2g + (hc*128 + k)*128 + oc4));
        }
        __syncthreads();
        #pragma unroll 2
        for (int k0 = 0; k0 < 128; k0 += 8) {
            unsigned a[2][4], b[4][2];
            #pragma unroll
            for (int ms = 0; ms < 2; ++ms) {
                const float* ba = s_w + (k0 + thr)*WST + m0 + ms*16 + grp;
                a[ms][0] = __float_as_uint(ba[0]);
                a[ms][1] = __float_as_uint(ba[8]);
                a[ms][2] = __float_as_uint(ba[4*WST]);
                a[ms][3] = __float_as_uint(ba[4*WST + 8]);
            }
            #pragma unroll
            for (int ns = 0; ns < 4; ++ns) {
                const float* bb = s_h + (k0 + thr)*ZST + n0 + ns*8 + grp;
                b[ns][0] = __float_as_uint(bb[0]);
                b[ns][1] = __float_as_uint(bb[4*ZST]);
            }
            #pragma unroll
            for (int ms = 0; ms < 2; ++ms)
                #pragma unroll
                for (int ns = 0; ns < 4; ++ns)
                    MMA_TF32(co[ms][ns][0], co[ms][ns][1], co[ms][ns][2], co[ms][ns][3],
                             a[ms][0], a[ms][1], a[ms][2], a[ms][3],
                             b[ns][0], b[ns][1]);
        }
    }
    int bt  = pos0 >> 12;
    int hw0 = pos0 & 4095;
    #pragma unroll
    for (int ms = 0; ms < 2; ++ms) {
        #pragma unroll
        for (int rr = 0; rr < 2; ++rr) {
            int oc = m0 + ms*16 + grp + rr*8;
            int d  = oc & 63;
            bool isim = (oc >= 64);
            float bb = b2[oc];
            #pragma unroll
            for (int ns = 0; ns < 4; ++ns) {
                int np = n0 + ns*8 + thr*2;
                int base = (bt*64 + d)*4096 + hw0 + np;
                float2 zv = *(const float2*)((isim ? s_zi : s_zr) + d*ZST + np);
                const float* xsrc = isim ? g_xsp_im : g_xsp_re;
                float2 xv = *(const float2*)(xsrc + base);
                float cA = co[ms][ns][rr*2 + 0];
                float cB = co[ms][ns][rr*2 + 1];
                float2 r = make_float2(cA + bb + zv.x + xv.x, cB + bb + zv.y + xv.y);
                *(float2*)(dout + (isim ? 8388608 : 0) + base) = r;
            }
        }
    }
}

// ---------------------------------------------------------------- launch
extern "C" void kernel_launch(void* const* d_in, const int* in_sizes, int n_in,
                              void* d_out, int out_size) {
    const float* x_re    = (const float*)d_in[0];
    const float* x_im    = (const float*)d_in[1];
    const float* hp_re   = (const float*)d_in[2];
    const float* hp_im   = (const float*)d_in[3];
    const float* fp_re   = (const float*)d_in[4];
    const float* fp_im   = (const float*)d_in[5];
    const float* dt      = (const float*)d_in[6];
    const float* ln_g    = (const float*)d_in[7];
    const float* ln_b    = (const float*)d_in[8];
    const float* conv_w  = (const float*)d_in[9];
    const float* conv_b  = (const float*)d_in[10];
    const float* metric  = (const float*)d_in[11];
    const float* E_re    = (const float*)d_in[12];
    const float* E_im    = (const float*)d_in[13];
    const float* Ed_re   = (const float*)d_in[14];
    const float* Ed_im   = (const float*)d_in[15];
    const float* lh_re   = (const float*)d_in[16];
    const float* lh_im   = (const float*)d_in[17];
    const float* lf_re   = (const float*)d_in[18];
    const float* lf_im   = (const float*)d_in[19];
    const float* Ws_re   = (const float*)d_in[20];
    const float* Ws_im   = (const float*)d_in[21];
    const float* W_gate  = (const float*)d_in[22];
    const float* b_gate  = (const float*)d_in[23];
    const float* ffn_w1  = (const float*)d_in[24];
    const float* ffn_b1  = (const float*)d_in[25];
    const float* ffn_w2  = (const float*)d_in[26];
    const float* ffn_b2  = (const float*)d_in[27];
    float* out = (float*)d_out;

    // conv: 65536 B; egemm1/recdec: (2*64*72 + 2*64*136)*4 = 106496 B; ffn: 180224 B
    cudaFuncSetAttribute(k_conv,   cudaFuncAttributeMaxDynamicSharedMemorySize, 65536);
    cudaFuncSetAttribute(k_egemm1, cudaFuncAttributeMaxDynamicSharedMemorySize, 106496);
    cudaFuncSetAttribute(k_recdec, cudaFuncAttributeMaxDynamicSharedMemorySize, 106496);
    cudaFuncSetAttribute(k_ffn,    cudaFuncAttributeMaxDynamicSharedMemorySize, 180224);

    k_ln<<<4096, 128>>>(x_re, x_im, ln_g, ln_b);
    k_wt<<<576, 256>>>(conv_w);
    k_conv<<<dim3(64, 32), 256, 65536>>>(x_re, x_im, conv_b, metric);
    k_egemm1<<<1024, 256, 106496>>>(E_re, E_im);
    k_mean<<<32, 256>>>();
    k_consts<<<1, 64>>>(dt, lh_re, lh_im, lf_re, lf_im);
    k_flux<<<1, 256>>>(fp_re, fp_im, out);
    k_srcgate<<<32, 64>>>(Ws_re, Ws_im, W_gate, b_gate);
    k_recdec<<<1024, 256, 106496>>>(Ed_re, Ed_im, hp_re, hp_im, out);
    k_ffn<<<2048, 256, 180224>>>(ffn_w1, ffn_b1, ffn_w2, ffn_b2, out);
}